// round 1
// baseline (speedup 1.0000x reference)
#include <cuda_runtime.h>
#include <math.h>

#define NROI   2000
#define C_IN   256
#define KDIM   12544      // 256*7*7
#define FDIM   1024
#define NCLS   81
#define NBOX   324        // 81*4
#define NOUT   405        // NCLS + NBOX

// ---------------- scratch (static device globals; no allocations) ----------------
__device__ float g_pooled[(size_t)NROI * KDIM];   // ~100 MB
__device__ float g_x1[NROI * FDIM];
__device__ float g_x2[NROI * FDIM];
__device__ float g_mu1[2 * FDIM];
__device__ float g_rstd1[2 * FDIM];
__device__ float g_mu2[2 * FDIM];
__device__ float g_rstd2[2 * FDIM];

// ---------------- kernel 1: pyramid ROI align ----------------
// One block per ROI; thread = channel (256 threads = 256 channels).
__global__ __launch_bounds__(256) void roi_align_kernel(
    const float* __restrict__ rois,
    const float* __restrict__ p2, const float* __restrict__ p3,
    const float* __restrict__ p4, const float* __restrict__ p5)
{
    int roi = blockIdx.x;             // 0..1999  (b*1000+n)
    int b   = roi / 1000;
    int c   = threadIdx.x;

    const float* r = rois + (size_t)roi * 4;
    float y1 = r[0], x1 = r[1], y2 = r[2], x2 = r[3];
    float hh = y2 - y1, ww = x2 - x1;

    // level select: 4 + round(log2(sqrt(max(h*w,1e-12))/ (224/1024))), clip [2,5]
    float s   = sqrtf(fmaxf(hh * ww, 1e-12f));
    float lvl = log2f(s / 0.21875f);
    int level = 4 + (int)rintf(lvl);       // rintf = round-half-even, matches jnp.round
    level = level < 2 ? 2 : (level > 5 ? 5 : level);

    const float* feat; int H;
    if      (level == 2) { feat = p2; H = 256; }
    else if (level == 3) { feat = p3; H = 128; }
    else if (level == 4) { feat = p4; H = 64;  }
    else                 { feat = p5; H = 32;  }
    int HW = H * H;
    float Hm1 = (float)(H - 1);

    const float* plane = feat + (size_t)(b * C_IN + c) * HW;
    float* outp = g_pooled + (size_t)roi * KDIM + (size_t)c * 49;

    float wxv[7]; int xi0v[7], xi1v[7];
#pragma unroll
    for (int px = 0; px < 7; px++) {
        float t  = (float)px * (1.0f / 6.0f);
        float xs = (x1 + ww * t) * Hm1;
        float x0 = floorf(xs);
        wxv[px]  = xs - x0;
        int xi = (int)x0;
        xi0v[px] = min(max(xi, 0), H - 1);
        xi1v[px] = min(max(xi + 1, 0), H - 1);
    }
#pragma unroll
    for (int py = 0; py < 7; py++) {
        float t  = (float)py * (1.0f / 6.0f);
        float ys = (y1 + hh * t) * Hm1;
        float y0 = floorf(ys);
        float wy = ys - y0;
        int yi = (int)y0;
        int yi0 = min(max(yi, 0), H - 1);
        int yi1 = min(max(yi + 1, 0), H - 1);
        const float* row0 = plane + yi0 * H;
        const float* row1 = plane + yi1 * H;
#pragma unroll
        for (int px = 0; px < 7; px++) {
            float wx  = wxv[px];
            float v00 = row0[xi0v[px]], v01 = row0[xi1v[px]];
            float v10 = row1[xi0v[px]], v11 = row1[xi1v[px]];
            float val = v00 * (1.f - wy) * (1.f - wx)
                      + v01 * (1.f - wy) * wx
                      + v10 * wy * (1.f - wx)
                      + v11 * wy * wx;
            outp[py * 7 + px] = val;
        }
    }
}

// ---------------- GEMM: C[M,1024] = A[M,K] * Bw[1024,K]^T + bias ----------------
// 128x128 tile, BK=8, 256 threads, 8x8 per thread (quadrant layout, conflict-free LDS128).
// phase 0: A = g_pooled (K=12544) -> g_x1
// phase 1: A = bn1_relu(g_x1)     (K=1024)  -> g_x2
__global__ __launch_bounds__(256) void gemm_kernel(
    int phase,
    const float* __restrict__ Bw, const float* __restrict__ bias,
    const float* __restrict__ gam, const float* __restrict__ bet,
    int K)
{
    const float* A  = (phase == 0) ? g_pooled : g_x1;
    float*       Co = (phase == 0) ? g_x1     : g_x2;

    __shared__ float As[8][128];
    __shared__ float Bs[8][128];

    int tid = threadIdx.x;
    int tx  = tid & 15;
    int ty  = tid >> 4;
    int bm  = blockIdx.y * 128;
    int bn  = blockIdx.x * 128;

    int lm = tid >> 1;          // 0..127
    int lk = (tid & 1) * 4;     // 0 or 4
    int arow = bm + lm;
    bool a_ok = arow < NROI;
    const float* Ap = A  + (size_t)(a_ok ? arow : 0) * K + lk;
    const float* Bp = Bw + (size_t)(bn + lm) * K + lk;
    int ab = (arow < 1000) ? 0 : 1;

    float acc[8][8];
#pragma unroll
    for (int i = 0; i < 8; i++)
#pragma unroll
        for (int j = 0; j < 8; j++) acc[i][j] = 0.f;

    for (int k0 = 0; k0 < K; k0 += 8) {
        float4 av = make_float4(0.f, 0.f, 0.f, 0.f);
        if (a_ok) {
            av = *(const float4*)(Ap + k0);
            if (phase == 1) {
                int kg = k0 + lk;
                float4 g4  = *(const float4*)(gam + kg);
                float4 b4  = *(const float4*)(bet + kg);
                float4 mu4 = *(const float4*)(g_mu1   + ab * FDIM + kg);
                float4 rs4 = *(const float4*)(g_rstd1 + ab * FDIM + kg);
                av.x = fmaxf(g4.x * (av.x - mu4.x) * rs4.x + b4.x, 0.f);
                av.y = fmaxf(g4.y * (av.y - mu4.y) * rs4.y + b4.y, 0.f);
                av.z = fmaxf(g4.z * (av.z - mu4.z) * rs4.z + b4.z, 0.f);
                av.w = fmaxf(g4.w * (av.w - mu4.w) * rs4.w + b4.w, 0.f);
            }
        }
        float4 bv = *(const float4*)(Bp + k0);

        As[lk + 0][lm] = av.x; As[lk + 1][lm] = av.y;
        As[lk + 2][lm] = av.z; As[lk + 3][lm] = av.w;
        Bs[lk + 0][lm] = bv.x; Bs[lk + 1][lm] = bv.y;
        Bs[lk + 2][lm] = bv.z; Bs[lk + 3][lm] = bv.w;
        __syncthreads();

#pragma unroll
        for (int kk = 0; kk < 8; kk++) {
            float4 a0 = *(const float4*)&As[kk][ty * 4];
            float4 a1 = *(const float4*)&As[kk][64 + ty * 4];
            float4 b0 = *(const float4*)&Bs[kk][tx * 4];
            float4 b1 = *(const float4*)&Bs[kk][64 + tx * 4];
            float af[8] = {a0.x, a0.y, a0.z, a0.w, a1.x, a1.y, a1.z, a1.w};
            float bf[8] = {b0.x, b0.y, b0.z, b0.w, b1.x, b1.y, b1.z, b1.w};
#pragma unroll
            for (int i = 0; i < 8; i++)
#pragma unroll
                for (int j = 0; j < 8; j++)
                    acc[i][j] += af[i] * bf[j];
        }
        __syncthreads();
    }

#pragma unroll
    for (int i = 0; i < 8; i++) {
        int row = bm + ((i < 4) ? (ty * 4 + i) : (64 + ty * 4 + (i - 4)));
        if (row < NROI) {
#pragma unroll
            for (int j = 0; j < 8; j++) {
                int col = bn + ((j < 4) ? (tx * 4 + j) : (64 + tx * 4 + (j - 4)));
                Co[(size_t)row * FDIM + col] = acc[i][j] + bias[col];
            }
        }
    }
}

// ---------------- BN stats over axis=N (per batch, per feature) ----------------
// grid (2, 4), 256 threads; thread owns one feature column, loops 1000 rows (coalesced).
__global__ __launch_bounds__(256) void bn_stats_kernel(int phase)
{
    const float* X  = (phase == 0) ? g_x1   : g_x2;
    float* mu       = (phase == 0) ? g_mu1  : g_mu2;
    float* rstd     = (phase == 0) ? g_rstd1: g_rstd2;

    int b = blockIdx.x;
    int f = blockIdx.y * 256 + threadIdx.x;
    const float* p = X + (size_t)b * 1000 * FDIM + f;

    float s = 0.f, q = 0.f;
#pragma unroll 4
    for (int n = 0; n < 1000; n++) {
        float v = p[(size_t)n * FDIM];
        s += v;
        q += v * v;
    }
    float m   = s * (1.0f / 1000.0f);
    float var = q * (1.0f / 1000.0f) - m * m;
    mu[b * FDIM + f]   = m;
    rstd[b * FDIM + f] = rsqrtf(var + 1e-5f);
}

// ---------------- head: bn2_relu -> logits/bbox GEMV + softmax ----------------
// 8 rows per block for weight reuse. 250 blocks x 256 threads.
#define RPB 8
__global__ __launch_bounds__(256) void head_kernel(
    const float* __restrict__ g2, const float* __restrict__ b2,
    const float* __restrict__ Wl, const float* __restrict__ bl,
    const float* __restrict__ Wb, const float* __restrict__ bb,
    float* __restrict__ out)
{
    __shared__ float sh[RPB][FDIM];
    __shared__ float lg[RPB][NCLS];

    int m0  = blockIdx.x * RPB;
    int tid = threadIdx.x;

    for (int r = 0; r < RPB; r++) {
        int m = m0 + r;
        int b = m / 1000;
        for (int k = tid; k < FDIM; k += 256) {
            float v = g_x2[(size_t)m * FDIM + k];
            v = g2[k] * (v - g_mu2[b * FDIM + k]) * g_rstd2[b * FDIM + k] + b2[k];
            sh[r][k] = fmaxf(v, 0.f);
        }
    }
    __syncthreads();

    for (int o = tid; o < NOUT; o += 256) {
        const float* W; float bias;
        if (o < NCLS) { W = Wl + (size_t)o * FDIM;          bias = bl[o]; }
        else          { W = Wb + (size_t)(o - NCLS) * FDIM; bias = bb[o - NCLS]; }

        float acc[RPB];
#pragma unroll
        for (int r = 0; r < RPB; r++) acc[r] = 0.f;

        for (int k = 0; k < FDIM; k += 4) {
            float4 wv = *(const float4*)(W + k);
#pragma unroll
            for (int r = 0; r < RPB; r++) {
                float4 sv = *(const float4*)&sh[r][k];
                acc[r] += sv.x * wv.x + sv.y * wv.y + sv.z * wv.z + sv.w * wv.w;
            }
        }
#pragma unroll
        for (int r = 0; r < RPB; r++) {
            int m = m0 + r;
            float v = acc[r] + bias;
            if (o < NCLS) {
                lg[r][o] = v;
                out[(size_t)m * NCLS + o] = v;                       // logits
            } else {
                out[324000 + (size_t)m * NBOX + (o - NCLS)] = v;     // bbox
            }
        }
    }
    __syncthreads();

    // softmax: warp w -> row w
    int wid = tid >> 5, lane = tid & 31;
    if (wid < RPB) {
        int m = m0 + wid;
        float mx = -1e30f;
        for (int i = lane; i < NCLS; i += 32) mx = fmaxf(mx, lg[wid][i]);
#pragma unroll
        for (int off = 16; off; off >>= 1) mx = fmaxf(mx, __shfl_xor_sync(0xffffffffu, mx, off));
        float sum = 0.f;
        for (int i = lane; i < NCLS; i += 32) sum += expf(lg[wid][i] - mx);
#pragma unroll
        for (int off = 16; off; off >>= 1) sum += __shfl_xor_sync(0xffffffffu, sum, off);
        float inv = 1.0f / sum;
        for (int i = lane; i < NCLS; i += 32)
            out[162000 + (size_t)m * NCLS + i] = expf(lg[wid][i] - mx) * inv;   // probs
    }
}

// ---------------- launch ----------------
extern "C" void kernel_launch(void* const* d_in, const int* in_sizes, int n_in,
                              void* d_out, int out_size)
{
    const float* rois    = (const float*)d_in[0];
    const float* p2      = (const float*)d_in[1];
    const float* p3      = (const float*)d_in[2];
    const float* p4      = (const float*)d_in[3];
    const float* p5      = (const float*)d_in[4];
    const float* conv1_w = (const float*)d_in[5];
    const float* conv1_b = (const float*)d_in[6];
    const float* bn1_g   = (const float*)d_in[7];
    const float* bn1_b   = (const float*)d_in[8];
    const float* conv2_w = (const float*)d_in[9];
    const float* conv2_b = (const float*)d_in[10];
    const float* bn2_g   = (const float*)d_in[11];
    const float* bn2_b   = (const float*)d_in[12];
    const float* logitsW = (const float*)d_in[13];
    const float* logitsB = (const float*)d_in[14];
    const float* bboxW   = (const float*)d_in[15];
    const float* bboxB   = (const float*)d_in[16];
    float* out = (float*)d_out;

    // 1) ROI align -> g_pooled
    roi_align_kernel<<<NROI, 256>>>(rois, p2, p3, p4, p5);

    // 2) GEMM1: g_pooled (2000x12544) * conv1_w^T -> g_x1
    gemm_kernel<<<dim3(FDIM / 128, (NROI + 127) / 128), 256>>>(
        0, conv1_w, conv1_b, nullptr, nullptr, KDIM);

    // 3) BN1 stats
    bn_stats_kernel<<<dim3(2, FDIM / 256), 256>>>(0);

    // 4) GEMM2: bn1_relu(g_x1) (2000x1024) * conv2_w^T -> g_x2
    gemm_kernel<<<dim3(FDIM / 128, (NROI + 127) / 128), 256>>>(
        1, conv2_w, conv2_b, bn1_g, bn1_b, FDIM);

    // 5) BN2 stats
    bn_stats_kernel<<<dim3(2, FDIM / 256), 256>>>(1);

    // 6) head: bn2_relu + logits/bbox + softmax -> out
    head_kernel<<<NROI / RPB, 256>>>(bn2_g, bn2_b, logitsW, logitsB, bboxW, bboxB, out);
}

// round 3
// speedup vs baseline: 1.7431x; 1.7431x over previous
#include <cuda_runtime.h>
#include <cuda_bf16.h>
#include <cstdint>
#include <math.h>

#define NROI   2000
#define MPAD   2048
#define C_IN   256
#define KDIM   12544      // 256*7*7
#define FDIM   1024
#define NCLS   81
#define NBOX   324
#define NOUT   405

// ---------------- scratch (static device globals; zero-init at load) --------
__device__ __nv_bfloat16 g_A1hi[(size_t)MPAD * KDIM];
__device__ __nv_bfloat16 g_A1lo[(size_t)MPAD * KDIM];
__device__ __nv_bfloat16 g_B1hi[(size_t)FDIM * KDIM];
__device__ __nv_bfloat16 g_B1lo[(size_t)FDIM * KDIM];
__device__ __nv_bfloat16 g_A2hi[(size_t)MPAD * FDIM];
__device__ __nv_bfloat16 g_A2lo[(size_t)MPAD * FDIM];
__device__ __nv_bfloat16 g_B2hi[(size_t)FDIM * FDIM];
__device__ __nv_bfloat16 g_B2lo[(size_t)FDIM * FDIM];
__device__ float g_x1[NROI * FDIM];
__device__ float g_x2[NROI * FDIM];
__device__ float g_mu1[2 * FDIM];
__device__ float g_rstd1[2 * FDIM];
__device__ float g_mu2[2 * FDIM];
__device__ float g_rstd2[2 * FDIM];

// ---------------- helpers ----------------
__device__ __forceinline__ uint32_t smem_u32(const void* p) {
    uint32_t a;
    asm("{ .reg .u64 t; cvta.to.shared.u64 t, %1; cvt.u32.u64 %0, t; }" : "=r"(a) : "l"(p));
    return a;
}
#define CPA(dst, src) \
    asm volatile("cp.async.cg.shared.global [%0], [%1], 16;" :: "r"(dst), "l"(src))
#define CPA_COMMIT() asm volatile("cp.async.commit_group;" ::: "memory")
#define CPA_WAIT1()  asm volatile("cp.async.wait_group 1;" ::: "memory")
#define CPA_WAIT0()  asm volatile("cp.async.wait_group 0;" ::: "memory")

__device__ __forceinline__ void ldm4(uint32_t* r, uint32_t addr) {
    asm volatile("ldmatrix.sync.aligned.m8n8.x4.shared.b16 {%0,%1,%2,%3}, [%4];"
        : "=r"(r[0]), "=r"(r[1]), "=r"(r[2]), "=r"(r[3]) : "r"(addr));
}
__device__ __forceinline__ void mma16816(float* d, const uint32_t* a, const uint32_t* b) {
    asm volatile("mma.sync.aligned.m16n8k16.row.col.f32.bf16.bf16.f32 "
        "{%0,%1,%2,%3},{%4,%5,%6,%7},{%8,%9},{%0,%1,%2,%3};"
        : "+f"(d[0]), "+f"(d[1]), "+f"(d[2]), "+f"(d[3])
        : "r"(a[0]), "r"(a[1]), "r"(a[2]), "r"(a[3]), "r"(b[0]), "r"(b[1]));
}

// ---------------- kernel 1: pyramid ROI align -> bf16 hi/lo ----------------
__global__ __launch_bounds__(256) void roi_align_kernel(
    const float* __restrict__ rois,
    const float* __restrict__ p2, const float* __restrict__ p3,
    const float* __restrict__ p4, const float* __restrict__ p5)
{
    int roi = blockIdx.x;
    int b   = roi / 1000;
    int c   = threadIdx.x;

    const float* r = rois + (size_t)roi * 4;
    float y1 = r[0], x1 = r[1], y2 = r[2], x2 = r[3];
    float hh = y2 - y1, ww = x2 - x1;

    float s   = sqrtf(fmaxf(hh * ww, 1e-12f));
    float lvl = log2f(s / 0.21875f);
    int level = 4 + (int)rintf(lvl);
    level = level < 2 ? 2 : (level > 5 ? 5 : level);

    const float* feat; int H;
    if      (level == 2) { feat = p2; H = 256; }
    else if (level == 3) { feat = p3; H = 128; }
    else if (level == 4) { feat = p4; H = 64;  }
    else                 { feat = p5; H = 32;  }
    float Hm1 = (float)(H - 1);

    const float* plane = feat + (size_t)(b * C_IN + c) * H * H;
    size_t obase = (size_t)roi * KDIM + (size_t)c * 49;

    float wxv[7]; int xi0v[7], xi1v[7];
#pragma unroll
    for (int px = 0; px < 7; px++) {
        float t  = (float)px * (1.0f / 6.0f);
        float xs = (x1 + ww * t) * Hm1;
        float x0 = floorf(xs);
        wxv[px]  = xs - x0;
        int xi = (int)x0;
        xi0v[px] = min(max(xi, 0), H - 1);
        xi1v[px] = min(max(xi + 1, 0), H - 1);
    }
#pragma unroll
    for (int py = 0; py < 7; py++) {
        float t  = (float)py * (1.0f / 6.0f);
        float ys = (y1 + hh * t) * Hm1;
        float y0 = floorf(ys);
        float wy = ys - y0;
        int yi = (int)y0;
        int yi0 = min(max(yi, 0), H - 1);
        int yi1 = min(max(yi + 1, 0), H - 1);
        const float* row0 = plane + yi0 * H;
        const float* row1 = plane + yi1 * H;
#pragma unroll
        for (int px = 0; px < 7; px++) {
            float wx  = wxv[px];
            float v00 = row0[xi0v[px]], v01 = row0[xi1v[px]];
            float v10 = row1[xi0v[px]], v11 = row1[xi1v[px]];
            float val = v00 * (1.f - wy) * (1.f - wx)
                      + v01 * (1.f - wy) * wx
                      + v10 * wy * (1.f - wx)
                      + v11 * wy * wx;
            __nv_bfloat16 h = __float2bfloat16(val);
            g_A1hi[obase + py * 7 + px] = h;
            g_A1lo[obase + py * 7 + px] = __float2bfloat16(val - __bfloat162float(h));
        }
    }
}

// ---------------- fp32 -> bf16 hi/lo split (weights) ----------------
__global__ __launch_bounds__(256) void cvt_kernel(
    const float* __restrict__ in, __nv_bfloat16* __restrict__ hi,
    __nv_bfloat16* __restrict__ lo, int n4)
{
    int i = blockIdx.x * 256 + threadIdx.x;
    if (i >= n4) return;
    float4 v = ((const float4*)in)[i];
    __nv_bfloat16 h0 = __float2bfloat16(v.x), h1 = __float2bfloat16(v.y);
    __nv_bfloat16 h2 = __float2bfloat16(v.z), h3 = __float2bfloat16(v.w);
    __nv_bfloat162* H = (__nv_bfloat162*)hi;
    __nv_bfloat162* L = (__nv_bfloat162*)lo;
    H[i*2]   = __nv_bfloat162(h0, h1);
    H[i*2+1] = __nv_bfloat162(h2, h3);
    L[i*2]   = __nv_bfloat162(__float2bfloat16(v.x - __bfloat162float(h0)),
                              __float2bfloat16(v.y - __bfloat162float(h1)));
    L[i*2+1] = __nv_bfloat162(__float2bfloat16(v.z - __bfloat162float(h2)),
                              __float2bfloat16(v.w - __bfloat162float(h3)));
}

// ---------------- HMMA GEMM: C[M,1024] = A[M,K]*B[1024,K]^T + bias ----------
// bf16x3 split. 128x128 CTA tile, BK=32, 8 warps (2x4), warp tile 64x32.
// SMEM: 4 tiles/stage (Ahi,Alo,Bhi,Blo), 128 rows x 80B (padded), 2 stages.
#define TILE_B  10240           // 128 * 80
#define STAGE_B 40960           // 4 * TILE_B
#define GSMEM   81920           // 2 stages

__device__ __forceinline__ void issue_stage(
    const __nv_bfloat16* __restrict__ Ah, const __nv_bfloat16* __restrict__ Al,
    const __nv_bfloat16* __restrict__ Bh, const __nv_bfloat16* __restrict__ Bl,
    int K, int k0, uint32_t sbase, int tid)
{
    const __nv_bfloat16* gs[4] = {Ah, Al, Bh, Bl};
#pragma unroll
    for (int t = 0; t < 4; t++) {
#pragma unroll
        for (int i = 0; i < 2; i++) {
            int u   = tid + i * 256;
            int row = u >> 2, seg = u & 3;
            const void* g = gs[t] + (size_t)row * K + k0 + seg * 8;
            uint32_t sm   = sbase + t * TILE_B + row * 80 + seg * 16;
            CPA(sm, g);
        }
    }
}

__global__ __launch_bounds__(256, 1) void hmma_gemm(
    const __nv_bfloat16* __restrict__ Ahi, const __nv_bfloat16* __restrict__ Alo,
    const __nv_bfloat16* __restrict__ Bhi, const __nv_bfloat16* __restrict__ Blo,
    const float* __restrict__ bias, float* __restrict__ Co, int K)
{
    extern __shared__ char smem[];
    uint32_t sb = smem_u32(smem);

    int tid  = threadIdx.x;
    int wid  = tid >> 5, lane = tid & 31;
    int wm   = (wid >> 2) * 64;       // 0 / 64
    int wn   = (wid & 3) * 32;        // 0..96
    int bm   = blockIdx.y * 128;
    int bn   = blockIdx.x * 128;

    const __nv_bfloat16* Ah = Ahi + (size_t)bm * K;
    const __nv_bfloat16* Al = Alo + (size_t)bm * K;
    const __nv_bfloat16* Bh = Bhi + (size_t)bn * K;
    const __nv_bfloat16* Bl = Blo + (size_t)bn * K;

    // ldmatrix offsets within a tile (s=0; add 32 bytes for s=1)
    uint32_t offA[4], offB[2];
#pragma unroll
    for (int i = 0; i < 4; i++)
        offA[i] = (wm + i * 16 + (lane & 15)) * 80 + ((lane >> 4) << 4);
#pragma unroll
    for (int j = 0; j < 2; j++)
        offB[j] = (wn + j * 16 + ((lane >> 4) << 3) + (lane & 7)) * 80
                + (((lane >> 3) & 1) << 4);

    float acc[4][4][4];
#pragma unroll
    for (int i = 0; i < 4; i++)
#pragma unroll
        for (int n = 0; n < 4; n++)
#pragma unroll
            for (int q = 0; q < 4; q++) acc[i][n][q] = 0.f;

    int nch = K >> 5;
    issue_stage(Ah, Al, Bh, Bl, K, 0, sb, tid);
    CPA_COMMIT();

    for (int k = 0; k < nch; k++) {
        if (k + 1 < nch) {
            issue_stage(Ah, Al, Bh, Bl, K, (k + 1) << 5,
                        sb + ((k + 1) & 1) * STAGE_B, tid);
            CPA_COMMIT();
            CPA_WAIT1();
        } else {
            CPA_WAIT0();
        }
        __syncthreads();

        uint32_t stb = sb + (k & 1) * STAGE_B;
#pragma unroll
        for (int s = 0; s < 2; s++) {
            uint32_t so = s * 32;
            uint32_t ah[4][4], al[4][4], bh[2][4], bl[2][4];
#pragma unroll
            for (int i = 0; i < 4; i++) {
                ldm4(ah[i], stb + 0 * TILE_B + offA[i] + so);
                ldm4(al[i], stb + 1 * TILE_B + offA[i] + so);
            }
#pragma unroll
            for (int j = 0; j < 2; j++) {
                ldm4(bh[j], stb + 2 * TILE_B + offB[j] + so);
                ldm4(bl[j], stb + 3 * TILE_B + offB[j] + so);
            }
#pragma unroll
            for (int i = 0; i < 4; i++) {
#pragma unroll
                for (int nf = 0; nf < 4; nf++) {
                    const uint32_t* bph = &bh[nf >> 1][(nf & 1) * 2];
                    const uint32_t* bpl = &bl[nf >> 1][(nf & 1) * 2];
                    mma16816(acc[i][nf], ah[i], bph);
                    mma16816(acc[i][nf], ah[i], bpl);
                    mma16816(acc[i][nf], al[i], bph);
                }
            }
        }
        __syncthreads();
    }

    // epilogue
#pragma unroll
    for (int i = 0; i < 4; i++) {
        int r0 = bm + wm + i * 16 + (lane >> 2);
#pragma unroll
        for (int nf = 0; nf < 4; nf++) {
            int c = bn + wn + nf * 8 + (lane & 3) * 2;
            float b0 = bias[c], b1 = bias[c + 1];
            if (r0 < NROI) {
                Co[(size_t)r0 * FDIM + c]     = acc[i][nf][0] + b0;
                Co[(size_t)r0 * FDIM + c + 1] = acc[i][nf][1] + b1;
            }
            if (r0 + 8 < NROI) {
                Co[(size_t)(r0 + 8) * FDIM + c]     = acc[i][nf][2] + b0;
                Co[(size_t)(r0 + 8) * FDIM + c + 1] = acc[i][nf][3] + b1;
            }
        }
    }
}

// ---------------- BN stats over axis=N ----------------
__global__ __launch_bounds__(256) void bn_stats_kernel(int phase)
{
    const float* X = (phase == 0) ? g_x1 : g_x2;
    float* mu      = (phase == 0) ? g_mu1 : g_mu2;
    float* rstd    = (phase == 0) ? g_rstd1 : g_rstd2;

    int b = blockIdx.x;
    int f = blockIdx.y * 256 + threadIdx.x;
    const float* p = X + (size_t)b * 1000 * FDIM + f;

    float s = 0.f, q = 0.f;
#pragma unroll 4
    for (int n = 0; n < 1000; n++) {
        float v = p[(size_t)n * FDIM];
        s += v; q += v * v;
    }
    float m   = s * (1.0f / 1000.0f);
    float var = q * (1.0f / 1000.0f) - m * m;
    mu[b * FDIM + f]   = m;
    rstd[b * FDIM + f] = rsqrtf(var + 1e-5f);
}

// ---------------- BN1+relu apply -> bf16 hi/lo for GEMM2 ----------------
__global__ __launch_bounds__(256) void bn_apply_kernel(
    const float* __restrict__ gam, const float* __restrict__ bet)
{
    int i = blockIdx.x * 256 + threadIdx.x;
    if (i >= NROI * FDIM / 4) return;
    int e   = i * 4;
    int row = e >> 10;
    int b   = (row >= 1000);
    int kg  = e & 1023;

    float4 v   = *(const float4*)(g_x1 + e);
    float4 g4  = *(const float4*)(gam + kg);
    float4 b4  = *(const float4*)(bet + kg);
    float4 mu4 = *(const float4*)(g_mu1 + b * FDIM + kg);
    float4 rs4 = *(const float4*)(g_rstd1 + b * FDIM + kg);
    float o0 = fmaxf(g4.x * (v.x - mu4.x) * rs4.x + b4.x, 0.f);
    float o1 = fmaxf(g4.y * (v.y - mu4.y) * rs4.y + b4.y, 0.f);
    float o2 = fmaxf(g4.z * (v.z - mu4.z) * rs4.z + b4.z, 0.f);
    float o3 = fmaxf(g4.w * (v.w - mu4.w) * rs4.w + b4.w, 0.f);

    __nv_bfloat16 h0 = __float2bfloat16(o0), h1 = __float2bfloat16(o1);
    __nv_bfloat16 h2 = __float2bfloat16(o2), h3 = __float2bfloat16(o3);
    __nv_bfloat162* H = (__nv_bfloat162*)g_A2hi;
    __nv_bfloat162* L = (__nv_bfloat162*)g_A2lo;
    H[i*2]   = __nv_bfloat162(h0, h1);
    H[i*2+1] = __nv_bfloat162(h2, h3);
    L[i*2]   = __nv_bfloat162(__float2bfloat16(o0 - __bfloat162float(h0)),
                              __float2bfloat16(o1 - __bfloat162float(h1)));
    L[i*2+1] = __nv_bfloat162(__float2bfloat16(o2 - __bfloat162float(h2)),
                              __float2bfloat16(o3 - __bfloat162float(h3)));
}

// ---------------- head: bn2_relu -> logits/bbox GEMV + softmax --------------
#define RPB 8
__global__ __launch_bounds__(256) void head_kernel(
    const float* __restrict__ g2, const float* __restrict__ b2,
    const float* __restrict__ Wl, const float* __restrict__ bl,
    const float* __restrict__ Wb, const float* __restrict__ bb,
    float* __restrict__ out)
{
    __shared__ float sh[RPB][FDIM];
    __shared__ float lg[RPB][NCLS];

    int m0  = blockIdx.x * RPB;
    int tid = threadIdx.x;

    for (int r = 0; r < RPB; r++) {
        int m = m0 + r;
        int b = m / 1000;
        for (int k = tid; k < FDIM; k += 256) {
            float v = g_x2[(size_t)m * FDIM + k];
            v = g2[k] * (v - g_mu2[b * FDIM + k]) * g_rstd2[b * FDIM + k] + b2[k];
            sh[r][k] = fmaxf(v, 0.f);
        }
    }
    __syncthreads();

    for (int o = tid; o < NOUT; o += 256) {
        const float* W; float bias;
        if (o < NCLS) { W = Wl + (size_t)o * FDIM;          bias = bl[o]; }
        else          { W = Wb + (size_t)(o - NCLS) * FDIM; bias = bb[o - NCLS]; }

        float acc[RPB];
#pragma unroll
        for (int r = 0; r < RPB; r++) acc[r] = 0.f;

        for (int k = 0; k < FDIM; k += 4) {
            float4 wv = *(const float4*)(W + k);
#pragma unroll
            for (int r = 0; r < RPB; r++) {
                float4 sv = *(const float4*)&sh[r][k];
                acc[r] += sv.x * wv.x + sv.y * wv.y + sv.z * wv.z + sv.w * wv.w;
            }
        }
#pragma unroll
        for (int r = 0; r < RPB; r++) {
            int m = m0 + r;
            float v = acc[r] + bias;
            if (o < NCLS) {
                lg[r][o] = v;
                out[(size_t)m * NCLS + o] = v;
            } else {
                out[324000 + (size_t)m * NBOX + (o - NCLS)] = v;
            }
        }
    }
    __syncthreads();

    int wid = tid >> 5, lane = tid & 31;
    if (wid < RPB) {
        int m = m0 + wid;
        float mx = -1e30f;
        for (int i = lane; i < NCLS; i += 32) mx = fmaxf(mx, lg[wid][i]);
#pragma unroll
        for (int off = 16; off; off >>= 1) mx = fmaxf(mx, __shfl_xor_sync(0xffffffffu, mx, off));
        float sum = 0.f;
        for (int i = lane; i < NCLS; i += 32) sum += expf(lg[wid][i] - mx);
#pragma unroll
        for (int off = 16; off; off >>= 1) sum += __shfl_xor_sync(0xffffffffu, sum, off);
        float inv = 1.0f / sum;
        for (int i = lane; i < NCLS; i += 32)
            out[162000 + (size_t)m * NCLS + i] = expf(lg[wid][i] - mx) * inv;
    }
}

// ---------------- launch ----------------
extern "C" void kernel_launch(void* const* d_in, const int* in_sizes, int n_in,
                              void* d_out, int out_size)
{
    const float* rois    = (const float*)d_in[0];
    const float* p2      = (const float*)d_in[1];
    const float* p3      = (const float*)d_in[2];
    const float* p4      = (const float*)d_in[3];
    const float* p5      = (const float*)d_in[4];
    const float* conv1_w = (const float*)d_in[5];
    const float* conv1_b = (const float*)d_in[6];
    const float* bn1_g   = (const float*)d_in[7];
    const float* bn1_b   = (const float*)d_in[8];
    const float* conv2_w = (const float*)d_in[9];
    const float* conv2_b = (const float*)d_in[10];
    const float* bn2_g   = (const float*)d_in[11];
    const float* bn2_b   = (const float*)d_in[12];
    const float* logitsW = (const float*)d_in[13];
    const float* logitsB = (const float*)d_in[14];
    const float* bboxW   = (const float*)d_in[15];
    const float* bboxB   = (const float*)d_in[16];
    float* out = (float*)d_out;

    cudaFuncSetAttribute(hmma_gemm, cudaFuncAttributeMaxDynamicSharedMemorySize, GSMEM);

    __nv_bfloat16 *a1h, *a1l, *b1h, *b1l, *a2h, *a2l, *b2h, *b2l;
    float *x1, *x2;
    cudaGetSymbolAddress((void**)&a1h, g_A1hi); cudaGetSymbolAddress((void**)&a1l, g_A1lo);
    cudaGetSymbolAddress((void**)&b1h, g_B1hi); cudaGetSymbolAddress((void**)&b1l, g_B1lo);
    cudaGetSymbolAddress((void**)&a2h, g_A2hi); cudaGetSymbolAddress((void**)&a2l, g_A2lo);
    cudaGetSymbolAddress((void**)&b2h, g_B2hi); cudaGetSymbolAddress((void**)&b2l, g_B2lo);
    cudaGetSymbolAddress((void**)&x1, g_x1);    cudaGetSymbolAddress((void**)&x2, g_x2);

    // 1) ROI align -> A1 hi/lo bf16
    roi_align_kernel<<<NROI, 256>>>(rois, p2, p3, p4, p5);

    // 2) split conv1_w -> B1 hi/lo
    cvt_kernel<<<(FDIM * KDIM / 4 + 255) / 256, 256>>>(conv1_w, b1h, b1l, FDIM * KDIM / 4);

    // 3) GEMM1 (HMMA bf16x3)
    hmma_gemm<<<dim3(FDIM / 128, MPAD / 128), 256, GSMEM>>>(
        a1h, a1l, b1h, b1l, conv1_b, x1, KDIM);

    // 4) BN1 stats
    bn_stats_kernel<<<dim3(2, FDIM / 256), 256>>>(0);

    // 5) BN1 apply + relu -> A2 hi/lo
    bn_apply_kernel<<<(NROI * FDIM / 4 + 255) / 256, 256>>>(bn1_g, bn1_b);

    // 6) split conv2_w -> B2 hi/lo
    cvt_kernel<<<(FDIM * FDIM / 4 + 255) / 256, 256>>>(conv2_w, b2h, b2l, FDIM * FDIM / 4);

    // 7) GEMM2 (HMMA bf16x3)
    hmma_gemm<<<dim3(FDIM / 128, MPAD / 128), 256, GSMEM>>>(
        a2h, a2l, b2h, b2l, conv2_b, x2, FDIM);

    // 8) BN2 stats
    bn_stats_kernel<<<dim3(2, FDIM / 256), 256>>>(1);

    // 9) head
    head_kernel<<<NROI / RPB, 256>>>(bn2_g, bn2_b, logitsW, logitsB, bboxW, bboxB, out);
}

// round 4
// speedup vs baseline: 1.9376x; 1.1116x over previous
#include <cuda_runtime.h>
#include <cuda_bf16.h>
#include <cstdint>
#include <math.h>

#define NROI   2000
#define MPAD   2048
#define C_IN   256
#define KDIM   12544      // 256*7*7
#define FDIM   1024
#define NCLS   81
#define NBOX   324
#define NOUT   405

// ---------------- scratch (static device globals; zero-init at load) --------
__device__ __nv_bfloat16 g_A1hi[(size_t)MPAD * KDIM];
__device__ __nv_bfloat16 g_A1lo[(size_t)MPAD * KDIM];
__device__ __nv_bfloat16 g_B1hi[(size_t)FDIM * KDIM];
__device__ __nv_bfloat16 g_B1lo[(size_t)FDIM * KDIM];
__device__ __nv_bfloat16 g_A2hi[(size_t)MPAD * FDIM];
__device__ __nv_bfloat16 g_A2lo[(size_t)MPAD * FDIM];
__device__ __nv_bfloat16 g_B2hi[(size_t)FDIM * FDIM];
__device__ __nv_bfloat16 g_B2lo[(size_t)FDIM * FDIM];
__device__ float g_x1[NROI * FDIM];
__device__ float g_x2[NROI * FDIM];
__device__ float g_mu1[2 * FDIM];
__device__ float g_rstd1[2 * FDIM];
__device__ float g_mu2[2 * FDIM];
__device__ float g_rstd2[2 * FDIM];
__device__ float g_psum[16 * FDIM];      // 8 chunks x 2 batches x 1024
__device__ float g_psq[16 * FDIM];

// ---------------- helpers ----------------
__device__ __forceinline__ uint32_t smem_u32(const void* p) {
    uint32_t a;
    asm("{ .reg .u64 t; cvta.to.shared.u64 t, %1; cvt.u32.u64 %0, t; }" : "=r"(a) : "l"(p));
    return a;
}
#define CPA(dst, src) \
    asm volatile("cp.async.cg.shared.global [%0], [%1], 16;" :: "r"(dst), "l"(src))
#define CPA_COMMIT() asm volatile("cp.async.commit_group;" ::: "memory")
#define CPA_WAIT1()  asm volatile("cp.async.wait_group 1;" ::: "memory")
#define CPA_WAIT0()  asm volatile("cp.async.wait_group 0;" ::: "memory")

__device__ __forceinline__ void ldm4(uint32_t* r, uint32_t addr) {
    asm volatile("ldmatrix.sync.aligned.m8n8.x4.shared.b16 {%0,%1,%2,%3}, [%4];"
        : "=r"(r[0]), "=r"(r[1]), "=r"(r[2]), "=r"(r[3]) : "r"(addr));
}
__device__ __forceinline__ void mma16816(float* d, const uint32_t* a, const uint32_t* b) {
    asm volatile("mma.sync.aligned.m16n8k16.row.col.f32.bf16.bf16.f32 "
        "{%0,%1,%2,%3},{%4,%5,%6,%7},{%8,%9},{%0,%1,%2,%3};"
        : "+f"(d[0]), "+f"(d[1]), "+f"(d[2]), "+f"(d[3])
        : "r"(a[0]), "r"(a[1]), "r"(a[2]), "r"(a[3]), "r"(b[0]), "r"(b[1]));
}

// ---------------- kernel 1: pyramid ROI align -> bf16 hi/lo ----------------
__global__ __launch_bounds__(256) void roi_align_kernel(
    const float* __restrict__ rois,
    const float* __restrict__ p2, const float* __restrict__ p3,
    const float* __restrict__ p4, const float* __restrict__ p5)
{
    int roi = blockIdx.x;
    int b   = roi / 1000;
    int c   = threadIdx.x;

    const float* r = rois + (size_t)roi * 4;
    float y1 = r[0], x1 = r[1], y2 = r[2], x2 = r[3];
    float hh = y2 - y1, ww = x2 - x1;

    float s   = sqrtf(fmaxf(hh * ww, 1e-12f));
    float lvl = log2f(s / 0.21875f);
    int level = 4 + (int)rintf(lvl);
    level = level < 2 ? 2 : (level > 5 ? 5 : level);

    const float* feat; int H;
    if      (level == 2) { feat = p2; H = 256; }
    else if (level == 3) { feat = p3; H = 128; }
    else if (level == 4) { feat = p4; H = 64;  }
    else                 { feat = p5; H = 32;  }
    float Hm1 = (float)(H - 1);

    const float* plane = feat + (size_t)(b * C_IN + c) * H * H;
    size_t obase = (size_t)roi * KDIM + (size_t)c * 49;

    float wxv[7]; int xi0v[7], xi1v[7];
#pragma unroll
    for (int px = 0; px < 7; px++) {
        float t  = (float)px * (1.0f / 6.0f);
        float xs = (x1 + ww * t) * Hm1;
        float x0 = floorf(xs);
        wxv[px]  = xs - x0;
        int xi = (int)x0;
        xi0v[px] = min(max(xi, 0), H - 1);
        xi1v[px] = min(max(xi + 1, 0), H - 1);
    }
#pragma unroll
    for (int py = 0; py < 7; py++) {
        float t  = (float)py * (1.0f / 6.0f);
        float ys = (y1 + hh * t) * Hm1;
        float y0 = floorf(ys);
        float wy = ys - y0;
        int yi = (int)y0;
        int yi0 = min(max(yi, 0), H - 1);
        int yi1 = min(max(yi + 1, 0), H - 1);
        const float* row0 = plane + yi0 * H;
        const float* row1 = plane + yi1 * H;
#pragma unroll
        for (int px = 0; px < 7; px++) {
            float wx  = wxv[px];
            float v00 = row0[xi0v[px]], v01 = row0[xi1v[px]];
            float v10 = row1[xi0v[px]], v11 = row1[xi1v[px]];
            float val = v00 * (1.f - wy) * (1.f - wx)
                      + v01 * (1.f - wy) * wx
                      + v10 * wy * (1.f - wx)
                      + v11 * wy * wx;
            __nv_bfloat16 h = __float2bfloat16(val);
            g_A1hi[obase + py * 7 + px] = h;
            g_A1lo[obase + py * 7 + px] = __float2bfloat16(val - __bfloat162float(h));
        }
    }
}

// ---------------- fp32 -> bf16 hi/lo split (weights) ----------------
__global__ __launch_bounds__(256) void cvt_kernel(
    const float* __restrict__ in, __nv_bfloat16* __restrict__ hi,
    __nv_bfloat16* __restrict__ lo, int n4)
{
    int i = blockIdx.x * 256 + threadIdx.x;
    if (i >= n4) return;
    float4 v = ((const float4*)in)[i];
    __nv_bfloat16 h0 = __float2bfloat16(v.x), h1 = __float2bfloat16(v.y);
    __nv_bfloat16 h2 = __float2bfloat16(v.z), h3 = __float2bfloat16(v.w);
    __nv_bfloat162* H = (__nv_bfloat162*)hi;
    __nv_bfloat162* L = (__nv_bfloat162*)lo;
    H[i*2]   = __nv_bfloat162(h0, h1);
    H[i*2+1] = __nv_bfloat162(h2, h3);
    L[i*2]   = __nv_bfloat162(__float2bfloat16(v.x - __bfloat162float(h0)),
                              __float2bfloat16(v.y - __bfloat162float(h1)));
    L[i*2+1] = __nv_bfloat162(__float2bfloat16(v.z - __bfloat162float(h2)),
                              __float2bfloat16(v.w - __bfloat162float(h3)));
}

// ---------------- HMMA GEMM: C[M,1024] = A[M,K]*B[1024,K]^T + bias ----------
// bf16x3 split. 128x128 CTA tile, BK=32, 8 warps (2x4), warp tile 64x32.
// SMEM: 4 tiles/stage (Ahi,Alo,Bhi,Blo), 128 rows x 80B (padded), 3 stages.
#define TILE_B  10240           // 128 * 80
#define STAGE_B 40960           // 4 * TILE_B
#define GSMEM   122880          // 3 stages

__device__ __forceinline__ void issue_stage(
    const __nv_bfloat16* __restrict__ Ah, const __nv_bfloat16* __restrict__ Al,
    const __nv_bfloat16* __restrict__ Bh, const __nv_bfloat16* __restrict__ Bl,
    int K, int k0, uint32_t sbase, int tid)
{
    const __nv_bfloat16* gs[4] = {Ah, Al, Bh, Bl};
#pragma unroll
    for (int t = 0; t < 4; t++) {
#pragma unroll
        for (int i = 0; i < 2; i++) {
            int u   = tid + i * 256;
            int row = u >> 2, seg = u & 3;
            const void* g = gs[t] + (size_t)row * K + k0 + seg * 8;
            uint32_t sm   = sbase + t * TILE_B + row * 80 + seg * 16;
            CPA(sm, g);
        }
    }
}

__global__ __launch_bounds__(256, 1) void hmma_gemm(
    const __nv_bfloat16* __restrict__ Ahi, const __nv_bfloat16* __restrict__ Alo,
    const __nv_bfloat16* __restrict__ Bhi, const __nv_bfloat16* __restrict__ Blo,
    const float* __restrict__ bias, float* __restrict__ Co, int K)
{
    extern __shared__ char smem[];
    uint32_t sb = smem_u32(smem);

    int tid  = threadIdx.x;
    int wid  = tid >> 5, lane = tid & 31;
    int wm   = (wid >> 2) * 64;       // 0 / 64
    int wn   = (wid & 3) * 32;        // 0..96
    int bm   = blockIdx.y * 128;
    int bn   = blockIdx.x * 128;

    const __nv_bfloat16* Ah = Ahi + (size_t)bm * K;
    const __nv_bfloat16* Al = Alo + (size_t)bm * K;
    const __nv_bfloat16* Bh = Bhi + (size_t)bn * K;
    const __nv_bfloat16* Bl = Blo + (size_t)bn * K;

    uint32_t offA[4], offB[2];
#pragma unroll
    for (int i = 0; i < 4; i++)
        offA[i] = (wm + i * 16 + (lane & 15)) * 80 + ((lane >> 4) << 4);
#pragma unroll
    for (int j = 0; j < 2; j++)
        offB[j] = (wn + j * 16 + ((lane >> 4) << 3) + (lane & 7)) * 80
                + (((lane >> 3) & 1) << 4);

    float acc[4][4][4];
#pragma unroll
    for (int i = 0; i < 4; i++)
#pragma unroll
        for (int n = 0; n < 4; n++)
#pragma unroll
            for (int q = 0; q < 4; q++) acc[i][n][q] = 0.f;

    int nch = K >> 5;

    // prologue: stages 0 and 1 in flight
    issue_stage(Ah, Al, Bh, Bl, K, 0, sb, tid);
    CPA_COMMIT();
    if (nch > 1) {
        issue_stage(Ah, Al, Bh, Bl, K, 32, sb + STAGE_B, tid);
        CPA_COMMIT();
    }

    for (int k = 0; k < nch; k++) {
        if (k == nch - 1) { CPA_WAIT0(); } else { CPA_WAIT1(); }
        __syncthreads();

        // issue stage k+2 into buffer (k+2)%3 (freed by compute of k-1)
        if (k + 2 < nch) {
            issue_stage(Ah, Al, Bh, Bl, K, (k + 2) << 5,
                        sb + ((k + 2) % 3) * STAGE_B, tid);
            CPA_COMMIT();
        }

        uint32_t stb = sb + (k % 3) * STAGE_B;
#pragma unroll
        for (int s = 0; s < 2; s++) {
            uint32_t so = s * 32;
            uint32_t ah[4][4], al[4][4], bh[2][4], bl[2][4];
#pragma unroll
            for (int i = 0; i < 4; i++) {
                ldm4(ah[i], stb + 0 * TILE_B + offA[i] + so);
                ldm4(al[i], stb + 1 * TILE_B + offA[i] + so);
            }
#pragma unroll
            for (int j = 0; j < 2; j++) {
                ldm4(bh[j], stb + 2 * TILE_B + offB[j] + so);
                ldm4(bl[j], stb + 3 * TILE_B + offB[j] + so);
            }
#pragma unroll
            for (int i = 0; i < 4; i++) {
#pragma unroll
                for (int nf = 0; nf < 4; nf++) {
                    const uint32_t* bph = &bh[nf >> 1][(nf & 1) * 2];
                    const uint32_t* bpl = &bl[nf >> 1][(nf & 1) * 2];
                    mma16816(acc[i][nf], ah[i], bph);
                    mma16816(acc[i][nf], ah[i], bpl);
                    mma16816(acc[i][nf], al[i], bph);
                }
            }
        }
        __syncthreads();
    }

    // epilogue
#pragma unroll
    for (int i = 0; i < 4; i++) {
        int r0 = bm + wm + i * 16 + (lane >> 2);
#pragma unroll
        for (int nf = 0; nf < 4; nf++) {
            int c = bn + wn + nf * 8 + (lane & 3) * 2;
            float b0 = bias[c], b1 = bias[c + 1];
            if (r0 < NROI) {
                Co[(size_t)r0 * FDIM + c]     = acc[i][nf][0] + b0;
                Co[(size_t)r0 * FDIM + c + 1] = acc[i][nf][1] + b1;
            }
            if (r0 + 8 < NROI) {
                Co[(size_t)(r0 + 8) * FDIM + c]     = acc[i][nf][2] + b0;
                Co[(size_t)(r0 + 8) * FDIM + c + 1] = acc[i][nf][3] + b1;
            }
        }
    }
}

// ---------------- BN stats: parallel partial sums + deterministic reduce ----
// grid (4, 8, 2): x = 256-col block, y = row chunk (125 rows), z = batch.
__global__ __launch_bounds__(256) void bn_partial_kernel(int phase)
{
    const float* X = (phase == 0) ? g_x1 : g_x2;
    int f  = blockIdx.x * 256 + threadIdx.x;
    int rc = blockIdx.y;
    int b  = blockIdx.z;
    const float* p = X + ((size_t)b * 1000 + rc * 125) * FDIM + f;

    float s = 0.f, q = 0.f;
#pragma unroll 5
    for (int n = 0; n < 125; n++) {
        float v = p[(size_t)n * FDIM];
        s += v; q += v * v;
    }
    int idx = (b * 8 + rc) * FDIM + f;
    g_psum[idx] = s;
    g_psq[idx]  = q;
}

__global__ __launch_bounds__(256) void bn_final_kernel(int phase)
{
    float* mu   = (phase == 0) ? g_mu1   : g_mu2;
    float* rstd = (phase == 0) ? g_rstd1 : g_rstd2;
    int f = blockIdx.y * 256 + threadIdx.x;
    int b = blockIdx.x;

    float s = 0.f, q = 0.f;
#pragma unroll
    for (int rc = 0; rc < 8; rc++) {
        int idx = (b * 8 + rc) * FDIM + f;
        s += g_psum[idx];
        q += g_psq[idx];
    }
    float m   = s * (1.0f / 1000.0f);
    float var = q * (1.0f / 1000.0f) - m * m;
    mu[b * FDIM + f]   = m;
    rstd[b * FDIM + f] = rsqrtf(var + 1e-5f);
}

// ---------------- BN1+relu apply -> bf16 hi/lo for GEMM2 ----------------
__global__ __launch_bounds__(256) void bn_apply_kernel(
    const float* __restrict__ gam, const float* __restrict__ bet)
{
    int i = blockIdx.x * 256 + threadIdx.x;
    if (i >= NROI * FDIM / 4) return;
    int e   = i * 4;
    int row = e >> 10;
    int b   = (row >= 1000);
    int kg  = e & 1023;

    float4 v   = *(const float4*)(g_x1 + e);
    float4 g4  = *(const float4*)(gam + kg);
    float4 b4  = *(const float4*)(bet + kg);
    float4 mu4 = *(const float4*)(g_mu1 + b * FDIM + kg);
    float4 rs4 = *(const float4*)(g_rstd1 + b * FDIM + kg);
    float o0 = fmaxf(g4.x * (v.x - mu4.x) * rs4.x + b4.x, 0.f);
    float o1 = fmaxf(g4.y * (v.y - mu4.y) * rs4.y + b4.y, 0.f);
    float o2 = fmaxf(g4.z * (v.z - mu4.z) * rs4.z + b4.z, 0.f);
    float o3 = fmaxf(g4.w * (v.w - mu4.w) * rs4.w + b4.w, 0.f);

    __nv_bfloat16 h0 = __float2bfloat16(o0), h1 = __float2bfloat16(o1);
    __nv_bfloat16 h2 = __float2bfloat16(o2), h3 = __float2bfloat16(o3);
    __nv_bfloat162* H = (__nv_bfloat162*)g_A2hi;
    __nv_bfloat162* L = (__nv_bfloat162*)g_A2lo;
    H[i*2]   = __nv_bfloat162(h0, h1);
    H[i*2+1] = __nv_bfloat162(h2, h3);
    L[i*2]   = __nv_bfloat162(__float2bfloat16(o0 - __bfloat162float(h0)),
                              __float2bfloat16(o1 - __bfloat162float(h1)));
    L[i*2+1] = __nv_bfloat162(__float2bfloat16(o2 - __bfloat162float(h2)),
                              __float2bfloat16(o3 - __bfloat162float(h3)));
}

// ---------------- head: bn2_relu -> logits/bbox GEMV + softmax --------------
#define RPB 8
__global__ __launch_bounds__(256) void head_kernel(
    const float* __restrict__ g2, const float* __restrict__ b2,
    const float* __restrict__ Wl, const float* __restrict__ bl,
    const float* __restrict__ Wb, const float* __restrict__ bb,
    float* __restrict__ out)
{
    __shared__ float sh[RPB][FDIM];
    __shared__ float lg[RPB][NCLS];

    int m0  = blockIdx.x * RPB;
    int tid = threadIdx.x;

    for (int r = 0; r < RPB; r++) {
        int m = m0 + r;
        int b = m / 1000;
        for (int k = tid; k < FDIM; k += 256) {
            float v = g_x2[(size_t)m * FDIM + k];
            v = g2[k] * (v - g_mu2[b * FDIM + k]) * g_rstd2[b * FDIM + k] + b2[k];
            sh[r][k] = fmaxf(v, 0.f);
        }
    }
    __syncthreads();

    for (int o = tid; o < NOUT; o += 256) {
        const float* W; float bias;
        if (o < NCLS) { W = Wl + (size_t)o * FDIM;          bias = bl[o]; }
        else          { W = Wb + (size_t)(o - NCLS) * FDIM; bias = bb[o - NCLS]; }

        float acc[RPB];
#pragma unroll
        for (int r = 0; r < RPB; r++) acc[r] = 0.f;

        for (int k = 0; k < FDIM; k += 4) {
            float4 wv = *(const float4*)(W + k);
#pragma unroll
            for (int r = 0; r < RPB; r++) {
                float4 sv = *(const float4*)&sh[r][k];
                acc[r] += sv.x * wv.x + sv.y * wv.y + sv.z * wv.z + sv.w * wv.w;
            }
        }
#pragma unroll
        for (int r = 0; r < RPB; r++) {
            int m = m0 + r;
            float v = acc[r] + bias;
            if (o < NCLS) {
                lg[r][o] = v;
                out[(size_t)m * NCLS + o] = v;
            } else {
                out[324000 + (size_t)m * NBOX + (o - NCLS)] = v;
            }
        }
    }
    __syncthreads();

    int wid = tid >> 5, lane = tid & 31;
    if (wid < RPB) {
        int m = m0 + wid;
        float mx = -1e30f;
        for (int i = lane; i < NCLS; i += 32) mx = fmaxf(mx, lg[wid][i]);
#pragma unroll
        for (int off = 16; off; off >>= 1) mx = fmaxf(mx, __shfl_xor_sync(0xffffffffu, mx, off));
        float sum = 0.f;
        for (int i = lane; i < NCLS; i += 32) sum += expf(lg[wid][i] - mx);
#pragma unroll
        for (int off = 16; off; off >>= 1) sum += __shfl_xor_sync(0xffffffffu, sum, off);
        float inv = 1.0f / sum;
        for (int i = lane; i < NCLS; i += 32)
            out[162000 + (size_t)m * NCLS + i] = expf(lg[wid][i] - mx) * inv;
    }
}

// ---------------- launch ----------------
extern "C" void kernel_launch(void* const* d_in, const int* in_sizes, int n_in,
                              void* d_out, int out_size)
{
    const float* rois    = (const float*)d_in[0];
    const float* p2      = (const float*)d_in[1];
    const float* p3      = (const float*)d_in[2];
    const float* p4      = (const float*)d_in[3];
    const float* p5      = (const float*)d_in[4];
    const float* conv1_w = (const float*)d_in[5];
    const float* conv1_b = (const float*)d_in[6];
    const float* bn1_g   = (const float*)d_in[7];
    const float* bn1_b   = (const float*)d_in[8];
    const float* conv2_w = (const float*)d_in[9];
    const float* conv2_b = (const float*)d_in[10];
    const float* bn2_g   = (const float*)d_in[11];
    const float* bn2_b   = (const float*)d_in[12];
    const float* logitsW = (const float*)d_in[13];
    const float* logitsB = (const float*)d_in[14];
    const float* bboxW   = (const float*)d_in[15];
    const float* bboxB   = (const float*)d_in[16];
    float* out = (float*)d_out;

    cudaFuncSetAttribute(hmma_gemm, cudaFuncAttributeMaxDynamicSharedMemorySize, GSMEM);

    __nv_bfloat16 *a1h, *a1l, *b1h, *b1l, *a2h, *a2l, *b2h, *b2l;
    float *x1, *x2;
    cudaGetSymbolAddress((void**)&a1h, g_A1hi); cudaGetSymbolAddress((void**)&a1l, g_A1lo);
    cudaGetSymbolAddress((void**)&b1h, g_B1hi); cudaGetSymbolAddress((void**)&b1l, g_B1lo);
    cudaGetSymbolAddress((void**)&a2h, g_A2hi); cudaGetSymbolAddress((void**)&a2l, g_A2lo);
    cudaGetSymbolAddress((void**)&b2h, g_B2hi); cudaGetSymbolAddress((void**)&b2l, g_B2lo);
    cudaGetSymbolAddress((void**)&x1, g_x1);    cudaGetSymbolAddress((void**)&x2, g_x2);

    // 1) ROI align -> A1 hi/lo bf16
    roi_align_kernel<<<NROI, 256>>>(rois, p2, p3, p4, p5);

    // 2) split conv1_w -> B1 hi/lo
    cvt_kernel<<<(FDIM * KDIM / 4 + 255) / 256, 256>>>(conv1_w, b1h, b1l, FDIM * KDIM / 4);

    // 3) GEMM1 (HMMA bf16x3)
    hmma_gemm<<<dim3(FDIM / 128, MPAD / 128), 256, GSMEM>>>(
        a1h, a1l, b1h, b1l, conv1_b, x1, KDIM);

    // 4) BN1 stats (parallel)
    bn_partial_kernel<<<dim3(4, 8, 2), 256>>>(0);
    bn_final_kernel<<<dim3(2, 4), 256>>>(0);

    // 5) BN1 apply + relu -> A2 hi/lo
    bn_apply_kernel<<<(NROI * FDIM / 4 + 255) / 256, 256>>>(bn1_g, bn1_b);

    // 6) split conv2_w -> B2 hi/lo
    cvt_kernel<<<(FDIM * FDIM / 4 + 255) / 256, 256>>>(conv2_w, b2h, b2l, FDIM * FDIM / 4);

    // 7) GEMM2 (HMMA bf16x3)
    hmma_gemm<<<dim3(FDIM / 128, MPAD / 128), 256, GSMEM>>>(
        a2h, a2l, b2h, b2l, conv2_b, x2, FDIM);

    // 8) BN2 stats (parallel)
    bn_partial_kernel<<<dim3(4, 8, 2), 256>>>(1);
    bn_final_kernel<<<dim3(2, 4), 256>>>(1);

    // 9) head
    head_kernel<<<NROI / RPB, 256>>>(bn2_g, bn2_b, logitsW, logitsB, bboxW, bboxB, out);
}

// round 5
// speedup vs baseline: 2.5011x; 1.2908x over previous
#include <cuda_runtime.h>
#include <cuda_bf16.h>
#include <cstdint>
#include <math.h>

#define NROI   2000
#define MPAD   2048
#define C_IN   256
#define KDIM   12544      // 256*7*7
#define FDIM   1024
#define NCLS   81
#define NBOX   324
#define NOUT   405

// ---------------- scratch (static device globals; zero-init at load) --------
__device__ __nv_bfloat16 g_A1hi[(size_t)MPAD * KDIM];
__device__ __nv_bfloat16 g_A1lo[(size_t)MPAD * KDIM];
__device__ __nv_bfloat16 g_B1hi[(size_t)FDIM * KDIM];
__device__ __nv_bfloat16 g_B1lo[(size_t)FDIM * KDIM];
__device__ __nv_bfloat16 g_A2hi[(size_t)MPAD * FDIM];
__device__ __nv_bfloat16 g_A2lo[(size_t)MPAD * FDIM];
__device__ __nv_bfloat16 g_B2hi[(size_t)FDIM * FDIM];
__device__ __nv_bfloat16 g_B2lo[(size_t)FDIM * FDIM];
__device__ float g_x1[NROI * FDIM];
__device__ float g_x2[NROI * FDIM];
__device__ float g_mu1[2 * FDIM];
__device__ float g_rstd1[2 * FDIM];
__device__ float g_mu2[2 * FDIM];
__device__ float g_rstd2[2 * FDIM];
__device__ float g_psum[16 * FDIM];
__device__ float g_psq[16 * FDIM];

// ---------------- helpers ----------------
__device__ __forceinline__ uint32_t smem_u32(const void* p) {
    uint32_t a;
    asm("{ .reg .u64 t; cvta.to.shared.u64 t, %1; cvt.u32.u64 %0, t; }" : "=r"(a) : "l"(p));
    return a;
}
#define CPA(dst, src) \
    asm volatile("cp.async.cg.shared.global [%0], [%1], 16;" :: "r"(dst), "l"(src))
#define CPA_COMMIT() asm volatile("cp.async.commit_group;" ::: "memory")
#define CPA_WAIT1()  asm volatile("cp.async.wait_group 1;" ::: "memory")
#define CPA_WAIT0()  asm volatile("cp.async.wait_group 0;" ::: "memory")

__device__ __forceinline__ void ldm4(uint32_t* r, uint32_t addr) {
    asm volatile("ldmatrix.sync.aligned.m8n8.x4.shared.b16 {%0,%1,%2,%3}, [%4];"
        : "=r"(r[0]), "=r"(r[1]), "=r"(r[2]), "=r"(r[3]) : "r"(addr));
}
__device__ __forceinline__ void mma16816(float* d, const uint32_t* a, const uint32_t* b) {
    asm volatile("mma.sync.aligned.m16n8k16.row.col.f32.bf16.bf16.f32 "
        "{%0,%1,%2,%3},{%4,%5,%6,%7},{%8,%9},{%0,%1,%2,%3};"
        : "+f"(d[0]), "+f"(d[1]), "+f"(d[2]), "+f"(d[3])
        : "r"(a[0]), "r"(a[1]), "r"(a[2]), "r"(a[3]), "r"(b[0]), "r"(b[1]));
}

// ---------------- kernel 1: pyramid ROI align -> bf16 hi/lo ----------------
// Block per ROI, 8 warps; warp = channel group (32 ch), lane = x within span.
__global__ __launch_bounds__(256) void roi_align_kernel(
    const float* __restrict__ rois,
    const float* __restrict__ p2, const float* __restrict__ p3,
    const float* __restrict__ p4, const float* __restrict__ p5)
{
    int roi  = blockIdx.x;
    int b    = roi / 1000;
    int tid  = threadIdx.x;
    int wid  = tid >> 5, lane = tid & 31;

    const float* r = rois + (size_t)roi * 4;
    float y1 = r[0], x1 = r[1], y2 = r[2], x2 = r[3];
    float hh = y2 - y1, ww = x2 - x1;

    float s   = sqrtf(fmaxf(hh * ww, 1e-12f));
    float lvl = log2f(s / 0.21875f);
    int level = 4 + (int)rintf(lvl);
    level = level < 2 ? 2 : (level > 5 ? 5 : level);

    const float* feat; int H;
    if      (level == 2) { feat = p2; H = 256; }
    else if (level == 3) { feat = p3; H = 128; }
    else if (level == 4) { feat = p4; H = 64;  }
    else                 { feat = p5; H = 32;  }
    float Hm1 = (float)(H - 1);

    // sample grids (uniform across block)
    float wxv[7], wyv[7];
    int xi0v[7], xi1v[7], yi0v[7], yi1v[7];
#pragma unroll
    for (int p = 0; p < 7; p++) {
        float t  = (float)p * (1.0f / 6.0f);
        float xs = (x1 + ww * t) * Hm1;
        float x0 = floorf(xs);
        wxv[p]  = xs - x0;
        int xi = (int)x0;
        xi0v[p] = min(max(xi, 0), H - 1);
        xi1v[p] = min(max(xi + 1, 0), H - 1);
        float ys = (y1 + hh * t) * Hm1;
        float y0 = floorf(ys);
        wyv[p]  = ys - y0;
        int yi = (int)y0;
        yi0v[p] = min(max(yi, 0), H - 1);
        yi1v[p] = min(max(yi + 1, 0), H - 1);
    }

    int xlo  = xi0v[0];
    int span = xi1v[6] - xlo + 1;

    // per-lane shuffle source indices (lanes 0..6 = px)
    int pxl   = lane < 7 ? lane : 0;
    int s0    = xi0v[pxl] - xlo;
    int s1    = xi1v[pxl] - xlo;
    float wxl = wxv[pxl];

    if (span <= 32) {
        // fast path: coalesced row-span loads + shuffle gather
        for (int c = wid * 32; c < wid * 32 + 32; c++) {
            const float* plane = feat + (size_t)(b * C_IN + c) * H * H;
            size_t obase = (size_t)roi * KDIM + (size_t)c * 49;
#pragma unroll
            for (int py = 0; py < 7; py++) {
                float v0 = 0.f, v1 = 0.f;
                if (lane < span) {
                    v0 = plane[yi0v[py] * H + xlo + lane];
                    v1 = plane[yi1v[py] * H + xlo + lane];
                }
                float a0 = __shfl_sync(0xffffffffu, v0, s0);
                float a1 = __shfl_sync(0xffffffffu, v0, s1);
                float c0 = __shfl_sync(0xffffffffu, v1, s0);
                float c1 = __shfl_sync(0xffffffffu, v1, s1);
                if (lane < 7) {
                    float wy = wyv[py], wx = wxl;
                    float val = a0 * (1.f - wy) * (1.f - wx)
                              + a1 * (1.f - wy) * wx
                              + c0 * wy * (1.f - wx)
                              + c1 * wy * wx;
                    __nv_bfloat16 h = __float2bfloat16(val);
                    g_A1hi[obase + py * 7 + lane] = h;
                    g_A1lo[obase + py * 7 + lane] =
                        __float2bfloat16(val - __bfloat162float(h));
                }
            }
        }
    } else {
        // slow path (rare wide ROIs): lanes 0..6 gather directly
        for (int c = wid * 32; c < wid * 32 + 32; c++) {
            const float* plane = feat + (size_t)(b * C_IN + c) * H * H;
            size_t obase = (size_t)roi * KDIM + (size_t)c * 49;
            if (lane < 7) {
#pragma unroll
                for (int py = 0; py < 7; py++) {
                    const float* row0 = plane + yi0v[py] * H;
                    const float* row1 = plane + yi1v[py] * H;
                    float wy = wyv[py], wx = wxl;
                    float v00 = row0[xi0v[lane]], v01 = row0[xi1v[lane]];
                    float v10 = row1[xi0v[lane]], v11 = row1[xi1v[lane]];
                    float val = v00 * (1.f - wy) * (1.f - wx)
                              + v01 * (1.f - wy) * wx
                              + v10 * wy * (1.f - wx)
                              + v11 * wy * wx;
                    __nv_bfloat16 h = __float2bfloat16(val);
                    g_A1hi[obase + py * 7 + lane] = h;
                    g_A1lo[obase + py * 7 + lane] =
                        __float2bfloat16(val - __bfloat162float(h));
                }
            }
        }
    }
}

// ---------------- fp32 -> bf16 hi/lo split (weights) ----------------
__global__ __launch_bounds__(256) void cvt_kernel(
    const float* __restrict__ in, __nv_bfloat16* __restrict__ hi,
    __nv_bfloat16* __restrict__ lo, int n4)
{
    int i = blockIdx.x * 256 + threadIdx.x;
    if (i >= n4) return;
    float4 v = ((const float4*)in)[i];
    __nv_bfloat16 h0 = __float2bfloat16(v.x), h1 = __float2bfloat16(v.y);
    __nv_bfloat16 h2 = __float2bfloat16(v.z), h3 = __float2bfloat16(v.w);
    __nv_bfloat162* H = (__nv_bfloat162*)hi;
    __nv_bfloat162* L = (__nv_bfloat162*)lo;
    H[i*2]   = __nv_bfloat162(h0, h1);
    H[i*2+1] = __nv_bfloat162(h2, h3);
    L[i*2]   = __nv_bfloat162(__float2bfloat16(v.x - __bfloat162float(h0)),
                              __float2bfloat16(v.y - __bfloat162float(h1)));
    L[i*2+1] = __nv_bfloat162(__float2bfloat16(v.z - __bfloat162float(h2)),
                              __float2bfloat16(v.w - __bfloat162float(h3)));
}

// ---------------- HMMA GEMM: C[M,1024] = A[M,K]*B[1024,K]^T + bias ----------
#define TILE_B  10240           // 128 * 80
#define STAGE_B 40960           // 4 * TILE_B
#define GSMEM   122880          // 3 stages

__device__ __forceinline__ void issue_stage(
    const __nv_bfloat16* __restrict__ Ah, const __nv_bfloat16* __restrict__ Al,
    const __nv_bfloat16* __restrict__ Bh, const __nv_bfloat16* __restrict__ Bl,
    int K, int k0, uint32_t sbase, int tid)
{
    const __nv_bfloat16* gs[4] = {Ah, Al, Bh, Bl};
#pragma unroll
    for (int t = 0; t < 4; t++) {
#pragma unroll
        for (int i = 0; i < 2; i++) {
            int u   = tid + i * 256;
            int row = u >> 2, seg = u & 3;
            const void* g = gs[t] + (size_t)row * K + k0 + seg * 8;
            uint32_t sm   = sbase + t * TILE_B + row * 80 + seg * 16;
            CPA(sm, g);
        }
    }
}

__global__ __launch_bounds__(256, 1) void hmma_gemm(
    const __nv_bfloat16* __restrict__ Ahi, const __nv_bfloat16* __restrict__ Alo,
    const __nv_bfloat16* __restrict__ Bhi, const __nv_bfloat16* __restrict__ Blo,
    const float* __restrict__ bias, float* __restrict__ Co, int K)
{
    extern __shared__ char smem[];
    uint32_t sb = smem_u32(smem);

    int tid  = threadIdx.x;
    int wid  = tid >> 5, lane = tid & 31;
    int wm   = (wid >> 2) * 64;
    int wn   = (wid & 3) * 32;
    int bm   = blockIdx.y * 128;
    int bn   = blockIdx.x * 128;

    const __nv_bfloat16* Ah = Ahi + (size_t)bm * K;
    const __nv_bfloat16* Al = Alo + (size_t)bm * K;
    const __nv_bfloat16* Bh = Bhi + (size_t)bn * K;
    const __nv_bfloat16* Bl = Blo + (size_t)bn * K;

    uint32_t offA[4], offB[2];
#pragma unroll
    for (int i = 0; i < 4; i++)
        offA[i] = (wm + i * 16 + (lane & 15)) * 80 + ((lane >> 4) << 4);
#pragma unroll
    for (int j = 0; j < 2; j++)
        offB[j] = (wn + j * 16 + ((lane >> 4) << 3) + (lane & 7)) * 80
                + (((lane >> 3) & 1) << 4);

    float acc[4][4][4];
#pragma unroll
    for (int i = 0; i < 4; i++)
#pragma unroll
        for (int n = 0; n < 4; n++)
#pragma unroll
            for (int q = 0; q < 4; q++) acc[i][n][q] = 0.f;

    int nch = K >> 5;

    issue_stage(Ah, Al, Bh, Bl, K, 0, sb, tid);
    CPA_COMMIT();
    if (nch > 1) {
        issue_stage(Ah, Al, Bh, Bl, K, 32, sb + STAGE_B, tid);
        CPA_COMMIT();
    }

    for (int k = 0; k < nch; k++) {
        if (k == nch - 1) { CPA_WAIT0(); } else { CPA_WAIT1(); }
        __syncthreads();   // single barrier per chunk: also protects buffer reuse

        if (k + 2 < nch) {
            issue_stage(Ah, Al, Bh, Bl, K, (k + 2) << 5,
                        sb + ((k + 2) % 3) * STAGE_B, tid);
            CPA_COMMIT();
        }

        uint32_t stb = sb + (k % 3) * STAGE_B;
#pragma unroll
        for (int s = 0; s < 2; s++) {
            uint32_t so = s * 32;
            uint32_t ah[4][4], al[4][4], bh[2][4], bl[2][4];
#pragma unroll
            for (int i = 0; i < 4; i++) {
                ldm4(ah[i], stb + 0 * TILE_B + offA[i] + so);
                ldm4(al[i], stb + 1 * TILE_B + offA[i] + so);
            }
#pragma unroll
            for (int j = 0; j < 2; j++) {
                ldm4(bh[j], stb + 2 * TILE_B + offB[j] + so);
                ldm4(bl[j], stb + 3 * TILE_B + offB[j] + so);
            }
#pragma unroll
            for (int i = 0; i < 4; i++) {
#pragma unroll
                for (int nf = 0; nf < 4; nf++) {
                    const uint32_t* bph = &bh[nf >> 1][(nf & 1) * 2];
                    const uint32_t* bpl = &bl[nf >> 1][(nf & 1) * 2];
                    mma16816(acc[i][nf], ah[i], bph);
                    mma16816(acc[i][nf], ah[i], bpl);
                    mma16816(acc[i][nf], al[i], bph);
                }
            }
        }
        // no trailing barrier: next-iteration top barrier provides the guarantee
    }

    // epilogue
#pragma unroll
    for (int i = 0; i < 4; i++) {
        int r0 = bm + wm + i * 16 + (lane >> 2);
#pragma unroll
        for (int nf = 0; nf < 4; nf++) {
            int c = bn + wn + nf * 8 + (lane & 3) * 2;
            float b0 = bias[c], b1 = bias[c + 1];
            if (r0 < NROI) {
                Co[(size_t)r0 * FDIM + c]     = acc[i][nf][0] + b0;
                Co[(size_t)r0 * FDIM + c + 1] = acc[i][nf][1] + b1;
            }
            if (r0 + 8 < NROI) {
                Co[(size_t)(r0 + 8) * FDIM + c]     = acc[i][nf][2] + b0;
                Co[(size_t)(r0 + 8) * FDIM + c + 1] = acc[i][nf][3] + b1;
            }
        }
    }
}

// ---------------- BN stats: parallel partial sums + deterministic reduce ----
__global__ __launch_bounds__(256) void bn_partial_kernel(int phase)
{
    const float* X = (phase == 0) ? g_x1 : g_x2;
    int f  = blockIdx.x * 256 + threadIdx.x;
    int rc = blockIdx.y;
    int b  = blockIdx.z;
    const float* p = X + ((size_t)b * 1000 + rc * 125) * FDIM + f;

    float s = 0.f, q = 0.f;
#pragma unroll 5
    for (int n = 0; n < 125; n++) {
        float v = p[(size_t)n * FDIM];
        s += v; q += v * v;
    }
    int idx = (b * 8 + rc) * FDIM + f;
    g_psum[idx] = s;
    g_psq[idx]  = q;
}

__global__ __launch_bounds__(256) void bn_final_kernel(int phase)
{
    float* mu   = (phase == 0) ? g_mu1   : g_mu2;
    float* rstd = (phase == 0) ? g_rstd1 : g_rstd2;
    int f = blockIdx.y * 256 + threadIdx.x;
    int b = blockIdx.x;

    float s = 0.f, q = 0.f;
#pragma unroll
    for (int rc = 0; rc < 8; rc++) {
        int idx = (b * 8 + rc) * FDIM + f;
        s += g_psum[idx];
        q += g_psq[idx];
    }
    float m   = s * (1.0f / 1000.0f);
    float var = q * (1.0f / 1000.0f) - m * m;
    mu[b * FDIM + f]   = m;
    rstd[b * FDIM + f] = rsqrtf(var + 1e-5f);
}

// ---------------- BN1+relu apply -> bf16 hi/lo for GEMM2 ----------------
__global__ __launch_bounds__(256) void bn_apply_kernel(
    const float* __restrict__ gam, const float* __restrict__ bet)
{
    int i = blockIdx.x * 256 + threadIdx.x;
    if (i >= NROI * FDIM / 4) return;
    int e   = i * 4;
    int row = e >> 10;
    int b   = (row >= 1000);
    int kg  = e & 1023;

    float4 v   = *(const float4*)(g_x1 + e);
    float4 g4  = *(const float4*)(gam + kg);
    float4 b4  = *(const float4*)(bet + kg);
    float4 mu4 = *(const float4*)(g_mu1 + b * FDIM + kg);
    float4 rs4 = *(const float4*)(g_rstd1 + b * FDIM + kg);
    float o0 = fmaxf(g4.x * (v.x - mu4.x) * rs4.x + b4.x, 0.f);
    float o1 = fmaxf(g4.y * (v.y - mu4.y) * rs4.y + b4.y, 0.f);
    float o2 = fmaxf(g4.z * (v.z - mu4.z) * rs4.z + b4.z, 0.f);
    float o3 = fmaxf(g4.w * (v.w - mu4.w) * rs4.w + b4.w, 0.f);

    __nv_bfloat16 h0 = __float2bfloat16(o0), h1 = __float2bfloat16(o1);
    __nv_bfloat16 h2 = __float2bfloat16(o2), h3 = __float2bfloat16(o3);
    __nv_bfloat162* H = (__nv_bfloat162*)g_A2hi;
    __nv_bfloat162* L = (__nv_bfloat162*)g_A2lo;
    H[i*2]   = __nv_bfloat162(h0, h1);
    H[i*2+1] = __nv_bfloat162(h2, h3);
    L[i*2]   = __nv_bfloat162(__float2bfloat16(o0 - __bfloat162float(h0)),
                              __float2bfloat16(o1 - __bfloat162float(h1)));
    L[i*2+1] = __nv_bfloat162(__float2bfloat16(o2 - __bfloat162float(h2)),
                              __float2bfloat16(o3 - __bfloat162float(h3)));
}

// ---------------- head: bn2_relu -> logits/bbox GEMV + softmax --------------
#define RPB 8
__global__ __launch_bounds__(256) void head_kernel(
    const float* __restrict__ g2, const float* __restrict__ b2,
    const float* __restrict__ Wl, const float* __restrict__ bl,
    const float* __restrict__ Wb, const float* __restrict__ bb,
    float* __restrict__ out)
{
    __shared__ float sh[RPB][FDIM];
    __shared__ float lg[RPB][NCLS];

    int m0  = blockIdx.x * RPB;
    int tid = threadIdx.x;

    for (int r = 0; r < RPB; r++) {
        int m = m0 + r;
        int b = m / 1000;
        for (int k = tid; k < FDIM; k += 256) {
            float v = g_x2[(size_t)m * FDIM + k];
            v = g2[k] * (v - g_mu2[b * FDIM + k]) * g_rstd2[b * FDIM + k] + b2[k];
            sh[r][k] = fmaxf(v, 0.f);
        }
    }
    __syncthreads();

    for (int o = tid; o < NOUT; o += 256) {
        const float* W; float bias;
        if (o < NCLS) { W = Wl + (size_t)o * FDIM;          bias = bl[o]; }
        else          { W = Wb + (size_t)(o - NCLS) * FDIM; bias = bb[o - NCLS]; }

        float acc[RPB];
#pragma unroll
        for (int r = 0; r < RPB; r++) acc[r] = 0.f;

        for (int k = 0; k < FDIM; k += 4) {
            float4 wv = *(const float4*)(W + k);
#pragma unroll
            for (int r = 0; r < RPB; r++) {
                float4 sv = *(const float4*)&sh[r][k];
                acc[r] += sv.x * wv.x + sv.y * wv.y + sv.z * wv.z + sv.w * wv.w;
            }
        }
#pragma unroll
        for (int r = 0; r < RPB; r++) {
            int m = m0 + r;
            float v = acc[r] + bias;
            if (o < NCLS) {
                lg[r][o] = v;
                out[(size_t)m * NCLS + o] = v;
            } else {
                out[324000 + (size_t)m * NBOX + (o - NCLS)] = v;
            }
        }
    }
    __syncthreads();

    int wid = tid >> 5, lane = tid & 31;
    if (wid < RPB) {
        int m = m0 + wid;
        float mx = -1e30f;
        for (int i = lane; i < NCLS; i += 32) mx = fmaxf(mx, lg[wid][i]);
#pragma unroll
        for (int off = 16; off; off >>= 1) mx = fmaxf(mx, __shfl_xor_sync(0xffffffffu, mx, off));
        float sum = 0.f;
        for (int i = lane; i < NCLS; i += 32) sum += expf(lg[wid][i] - mx);
#pragma unroll
        for (int off = 16; off; off >>= 1) sum += __shfl_xor_sync(0xffffffffu, sum, off);
        float inv = 1.0f / sum;
        for (int i = lane; i < NCLS; i += 32)
            out[162000 + (size_t)m * NCLS + i] = expf(lg[wid][i] - mx) * inv;
    }
}

// ---------------- launch ----------------
extern "C" void kernel_launch(void* const* d_in, const int* in_sizes, int n_in,
                              void* d_out, int out_size)
{
    const float* rois    = (const float*)d_in[0];
    const float* p2      = (const float*)d_in[1];
    const float* p3      = (const float*)d_in[2];
    const float* p4      = (const float*)d_in[3];
    const float* p5      = (const float*)d_in[4];
    const float* conv1_w = (const float*)d_in[5];
    const float* conv1_b = (const float*)d_in[6];
    const float* bn1_g   = (const float*)d_in[7];
    const float* bn1_b   = (const float*)d_in[8];
    const float* conv2_w = (const float*)d_in[9];
    const float* conv2_b = (const float*)d_in[10];
    const float* bn2_g   = (const float*)d_in[11];
    const float* bn2_b   = (const float*)d_in[12];
    const float* logitsW = (const float*)d_in[13];
    const float* logitsB = (const float*)d_in[14];
    const float* bboxW   = (const float*)d_in[15];
    const float* bboxB   = (const float*)d_in[16];
    float* out = (float*)d_out;

    cudaFuncSetAttribute(hmma_gemm, cudaFuncAttributeMaxDynamicSharedMemorySize, GSMEM);

    __nv_bfloat16 *a1h, *a1l, *b1h, *b1l, *a2h, *a2l, *b2h, *b2l;
    float *x1, *x2;
    cudaGetSymbolAddress((void**)&a1h, g_A1hi); cudaGetSymbolAddress((void**)&a1l, g_A1lo);
    cudaGetSymbolAddress((void**)&b1h, g_B1hi); cudaGetSymbolAddress((void**)&b1l, g_B1lo);
    cudaGetSymbolAddress((void**)&a2h, g_A2hi); cudaGetSymbolAddress((void**)&a2l, g_A2lo);
    cudaGetSymbolAddress((void**)&b2h, g_B2hi); cudaGetSymbolAddress((void**)&b2l, g_B2lo);
    cudaGetSymbolAddress((void**)&x1, g_x1);    cudaGetSymbolAddress((void**)&x2, g_x2);

    // 1) ROI align -> A1 hi/lo bf16 (coalesced span + shfl gather)
    roi_align_kernel<<<NROI, 256>>>(rois, p2, p3, p4, p5);

    // 2) split conv1_w -> B1 hi/lo
    cvt_kernel<<<(FDIM * KDIM / 4 + 255) / 256, 256>>>(conv1_w, b1h, b1l, FDIM * KDIM / 4);

    // 3) GEMM1 (HMMA bf16x3)
    hmma_gemm<<<dim3(FDIM / 128, MPAD / 128), 256, GSMEM>>>(
        a1h, a1l, b1h, b1l, conv1_b, x1, KDIM);

    // 4) BN1 stats (parallel)
    bn_partial_kernel<<<dim3(4, 8, 2), 256>>>(0);
    bn_final_kernel<<<dim3(2, 4), 256>>>(0);

    // 5) BN1 apply + relu -> A2 hi/lo
    bn_apply_kernel<<<(NROI * FDIM / 4 + 255) / 256, 256>>>(bn1_g, bn1_b);

    // 6) split conv2_w -> B2 hi/lo
    cvt_kernel<<<(FDIM * FDIM / 4 + 255) / 256, 256>>>(conv2_w, b2h, b2l, FDIM * FDIM / 4);

    // 7) GEMM2 (HMMA bf16x3)
    hmma_gemm<<<dim3(FDIM / 128, MPAD / 128), 256, GSMEM>>>(
        a2h, a2l, b2h, b2l, conv2_b, x2, FDIM);

    // 8) BN2 stats (parallel)
    bn_partial_kernel<<<dim3(4, 8, 2), 256>>>(1);
    bn_final_kernel<<<dim3(2, 4), 256>>>(1);

    // 9) head
    head_kernel<<<NROI / RPB, 256>>>(bn2_g, bn2_b, logitsW, logitsB, bboxW, bboxB, out);
}

// round 6
// speedup vs baseline: 2.6649x; 1.0655x over previous
#include <cuda_runtime.h>
#include <cuda_fp16.h>
#include <cstdint>
#include <math.h>

#define NROI   2000
#define MPAD   2048
#define C_IN   256
#define KDIM   12544      // 256*7*7
#define FDIM   1024
#define NCLS   81
#define NBOX   324
#define NOUT   405

// ---------------- scratch (static device globals; zero-init at load) --------
__device__ __half g_A1hi[(size_t)MPAD * KDIM];
__device__ __half g_A1lo[(size_t)MPAD * KDIM];
__device__ __half g_B1hi[(size_t)FDIM * KDIM];
__device__ __half g_B1lo[(size_t)FDIM * KDIM];     // unused by 2-pass GEMM1 but kept for layout symmetry
__device__ __half g_A2hi[(size_t)MPAD * FDIM];
__device__ __half g_A2lo[(size_t)MPAD * FDIM];
__device__ __half g_B2hi[(size_t)FDIM * FDIM];
__device__ __half g_B2lo[(size_t)FDIM * FDIM];
__device__ float g_x1[NROI * FDIM];
__device__ float g_x2[NROI * FDIM];
__device__ float g_mu1[2 * FDIM];
__device__ float g_rstd1[2 * FDIM];
__device__ float g_mu2[2 * FDIM];
__device__ float g_rstd2[2 * FDIM];
__device__ float g_psum[16 * FDIM];
__device__ float g_psq[16 * FDIM];

// ---------------- helpers ----------------
__device__ __forceinline__ uint32_t smem_u32(const void* p) {
    uint32_t a;
    asm("{ .reg .u64 t; cvta.to.shared.u64 t, %1; cvt.u32.u64 %0, t; }" : "=r"(a) : "l"(p));
    return a;
}
#define CPA(dst, src) \
    asm volatile("cp.async.cg.shared.global [%0], [%1], 16;" :: "r"(dst), "l"(src))
#define CPA_COMMIT() asm volatile("cp.async.commit_group;" ::: "memory")
#define CPA_WAIT1()  asm volatile("cp.async.wait_group 1;" ::: "memory")
#define CPA_WAIT0()  asm volatile("cp.async.wait_group 0;" ::: "memory")

__device__ __forceinline__ void ldm4(uint32_t* r, uint32_t addr) {
    asm volatile("ldmatrix.sync.aligned.m8n8.x4.shared.b16 {%0,%1,%2,%3}, [%4];"
        : "=r"(r[0]), "=r"(r[1]), "=r"(r[2]), "=r"(r[3]) : "r"(addr));
}
__device__ __forceinline__ void mma16816(float* d, const uint32_t* a, const uint32_t* b) {
    asm volatile("mma.sync.aligned.m16n8k16.row.col.f32.f16.f16.f32 "
        "{%0,%1,%2,%3},{%4,%5,%6,%7},{%8,%9},{%0,%1,%2,%3};"
        : "+f"(d[0]), "+f"(d[1]), "+f"(d[2]), "+f"(d[3])
        : "r"(a[0]), "r"(a[1]), "r"(a[2]), "r"(a[3]), "r"(b[0]), "r"(b[1]));
}

// ---------------- kernel 1: pyramid ROI align -> fp16 hi/lo ----------------
// Grid 1000 blocks per launch (batch passed in). Warp = 32 channels, lane = x.
__global__ __launch_bounds__(256) void roi_align_kernel(
    const float* __restrict__ rois, int b,
    const float* __restrict__ p2, const float* __restrict__ p3,
    const float* __restrict__ p4, const float* __restrict__ p5)
{
    int roi  = b * 1000 + blockIdx.x;
    int tid  = threadIdx.x;
    int wid  = tid >> 5, lane = tid & 31;

    const float* r = rois + (size_t)roi * 4;
    float y1 = r[0], x1 = r[1], y2 = r[2], x2 = r[3];
    float hh = y2 - y1, ww = x2 - x1;

    float s   = sqrtf(fmaxf(hh * ww, 1e-12f));
    float lvl = log2f(s / 0.21875f);
    int level = 4 + (int)rintf(lvl);
    level = level < 2 ? 2 : (level > 5 ? 5 : level);

    const float* feat; int H;
    if      (level == 2) { feat = p2; H = 256; }
    else if (level == 3) { feat = p3; H = 128; }
    else if (level == 4) { feat = p4; H = 64;  }
    else                 { feat = p5; H = 32;  }
    float Hm1 = (float)(H - 1);

    float wxv[7], wyv[7];
    int xi0v[7], xi1v[7], yi0v[7], yi1v[7];
#pragma unroll
    for (int p = 0; p < 7; p++) {
        float t  = (float)p * (1.0f / 6.0f);
        float xs = (x1 + ww * t) * Hm1;
        float x0 = floorf(xs);
        wxv[p]  = xs - x0;
        int xi = (int)x0;
        xi0v[p] = min(max(xi, 0), H - 1);
        xi1v[p] = min(max(xi + 1, 0), H - 1);
        float ys = (y1 + hh * t) * Hm1;
        float y0 = floorf(ys);
        wyv[p]  = ys - y0;
        int yi = (int)y0;
        yi0v[p] = min(max(yi, 0), H - 1);
        yi1v[p] = min(max(yi + 1, 0), H - 1);
    }

    int xlo  = xi0v[0];
    int span = xi1v[6] - xlo + 1;

    int pxl   = lane < 7 ? lane : 0;
    int s0    = xi0v[pxl] - xlo;
    int s1    = xi1v[pxl] - xlo;
    float wxl = wxv[pxl];

    if (span <= 32) {
        for (int c = wid * 32; c < wid * 32 + 32; c++) {
            const float* plane = feat + (size_t)(b * C_IN + c) * H * H;
            size_t obase = (size_t)roi * KDIM + (size_t)c * 49;
#pragma unroll
            for (int py = 0; py < 7; py++) {
                float v0 = 0.f, v1 = 0.f;
                if (lane < span) {
                    v0 = plane[yi0v[py] * H + xlo + lane];
                    v1 = plane[yi1v[py] * H + xlo + lane];
                }
                float a0 = __shfl_sync(0xffffffffu, v0, s0);
                float a1 = __shfl_sync(0xffffffffu, v0, s1);
                float c0 = __shfl_sync(0xffffffffu, v1, s0);
                float c1 = __shfl_sync(0xffffffffu, v1, s1);
                if (lane < 7) {
                    float wy = wyv[py], wx = wxl;
                    float val = a0 * (1.f - wy) * (1.f - wx)
                              + a1 * (1.f - wy) * wx
                              + c0 * wy * (1.f - wx)
                              + c1 * wy * wx;
                    __half h = __float2half_rn(val);
                    g_A1hi[obase + py * 7 + lane] = h;
                    g_A1lo[obase + py * 7 + lane] =
                        __float2half_rn(val - __half2float(h));
                }
            }
        }
    } else {
        for (int c = wid * 32; c < wid * 32 + 32; c++) {
            const float* plane = feat + (size_t)(b * C_IN + c) * H * H;
            size_t obase = (size_t)roi * KDIM + (size_t)c * 49;
            if (lane < 7) {
#pragma unroll
                for (int py = 0; py < 7; py++) {
                    const float* row0 = plane + yi0v[py] * H;
                    const float* row1 = plane + yi1v[py] * H;
                    float wy = wyv[py], wx = wxl;
                    float v00 = row0[xi0v[lane]], v01 = row0[xi1v[lane]];
                    float v10 = row1[xi0v[lane]], v11 = row1[xi1v[lane]];
                    float val = v00 * (1.f - wy) * (1.f - wx)
                              + v01 * (1.f - wy) * wx
                              + v10 * wy * (1.f - wx)
                              + v11 * wy * wx;
                    __half h = __float2half_rn(val);
                    g_A1hi[obase + py * 7 + lane] = h;
                    g_A1lo[obase + py * 7 + lane] =
                        __float2half_rn(val - __half2float(h));
                }
            }
        }
    }
}

// ---------------- fp32 -> fp16 hi/lo split ----------------
__global__ __launch_bounds__(256) void cvt_kernel(
    const float* __restrict__ in, __half* __restrict__ hi,
    __half* __restrict__ lo, int off4, int n4)
{
    int i = off4 + blockIdx.x * 256 + threadIdx.x;
    if (i >= n4) return;
    float4 v = ((const float4*)in)[i];
    __half h0 = __float2half_rn(v.x), h1 = __float2half_rn(v.y);
    __half h2 = __float2half_rn(v.z), h3 = __float2half_rn(v.w);
    __half2* H = (__half2*)hi;
    __half2* L = (__half2*)lo;
    H[i*2]   = __half2(h0, h1);
    H[i*2+1] = __half2(h2, h3);
    L[i*2]   = __half2(__float2half_rn(v.x - __half2float(h0)),
                       __float2half_rn(v.y - __half2float(h1)));
    L[i*2+1] = __half2(__float2half_rn(v.z - __half2float(h2)),
                       __float2half_rn(v.w - __half2float(h3)));
}

// ---------------- HMMA GEMM: C[M,1024] = A[M,K]*B[1024,K]^T + bias ----------
// fp16 split. PASSES=2: D = Ah*Bh + Al*Bh. PASSES=3: + Ah*Bl.
// 128x128 CTA tile, BK=32, 8 warps (2x4), warp tile 64x32, 3-stage cp.async.
#define TILE_B  10240           // 128 * 80
#define STAGE_B 40960           // 4 * TILE_B (Bl slot unused when PASSES=2)
#define GSMEM   122880          // 3 stages

template<int PASSES>
__device__ __forceinline__ void issue_stage(
    const __half* __restrict__ Ah, const __half* __restrict__ Al,
    const __half* __restrict__ Bh, const __half* __restrict__ Bl,
    int K, int k0, uint32_t sbase, int tid)
{
    const __half* gs[4] = {Ah, Al, Bh, Bl};
    const int NT = (PASSES == 3) ? 4 : 3;
#pragma unroll
    for (int t = 0; t < NT; t++) {
#pragma unroll
        for (int i = 0; i < 2; i++) {
            int u   = tid + i * 256;
            int row = u >> 2, seg = u & 3;
            const void* g = gs[t] + (size_t)row * K + k0 + seg * 8;
            uint32_t sm   = sbase + t * TILE_B + row * 80 + seg * 16;
            CPA(sm, g);
        }
    }
}

template<int PASSES>
__global__ __launch_bounds__(256, 1) void hmma_gemm(
    const __half* __restrict__ Ahi, const __half* __restrict__ Alo,
    const __half* __restrict__ Bhi, const __half* __restrict__ Blo,
    const float* __restrict__ bias, float* __restrict__ Co, int K)
{
    extern __shared__ char smem[];
    uint32_t sb = smem_u32(smem);

    int tid  = threadIdx.x;
    int wid  = tid >> 5, lane = tid & 31;
    int wm   = (wid >> 2) * 64;
    int wn   = (wid & 3) * 32;
    int bm   = blockIdx.y * 128;
    int bn   = blockIdx.x * 128;

    const __half* Ah = Ahi + (size_t)bm * K;
    const __half* Al = Alo + (size_t)bm * K;
    const __half* Bh = Bhi + (size_t)bn * K;
    const __half* Bl = Blo + (size_t)bn * K;

    uint32_t offA[4], offB[2];
#pragma unroll
    for (int i = 0; i < 4; i++)
        offA[i] = (wm + i * 16 + (lane & 15)) * 80 + ((lane >> 4) << 4);
#pragma unroll
    for (int j = 0; j < 2; j++)
        offB[j] = (wn + j * 16 + ((lane >> 4) << 3) + (lane & 7)) * 80
                + (((lane >> 3) & 1) << 4);

    float acc[4][4][4];
#pragma unroll
    for (int i = 0; i < 4; i++)
#pragma unroll
        for (int n = 0; n < 4; n++)
#pragma unroll
            for (int q = 0; q < 4; q++) acc[i][n][q] = 0.f;

    int nch = K >> 5;

    issue_stage<PASSES>(Ah, Al, Bh, Bl, K, 0, sb, tid);
    CPA_COMMIT();
    if (nch > 1) {
        issue_stage<PASSES>(Ah, Al, Bh, Bl, K, 32, sb + STAGE_B, tid);
        CPA_COMMIT();
    }

    for (int k = 0; k < nch; k++) {
        if (k == nch - 1) { CPA_WAIT0(); } else { CPA_WAIT1(); }
        __syncthreads();

        if (k + 2 < nch) {
            issue_stage<PASSES>(Ah, Al, Bh, Bl, K, (k + 2) << 5,
                                sb + ((k + 2) % 3) * STAGE_B, tid);
            CPA_COMMIT();
        }

        uint32_t stb = sb + (k % 3) * STAGE_B;
#pragma unroll
        for (int s = 0; s < 2; s++) {
            uint32_t so = s * 32;
            uint32_t ah[4][4], al[4][4], bh[2][4], bl[2][4];
#pragma unroll
            for (int i = 0; i < 4; i++) {
                ldm4(ah[i], stb + 0 * TILE_B + offA[i] + so);
                ldm4(al[i], stb + 1 * TILE_B + offA[i] + so);
            }
#pragma unroll
            for (int j = 0; j < 2; j++) {
                ldm4(bh[j], stb + 2 * TILE_B + offB[j] + so);
                if (PASSES == 3)
                    ldm4(bl[j], stb + 3 * TILE_B + offB[j] + so);
            }
#pragma unroll
            for (int i = 0; i < 4; i++) {
#pragma unroll
                for (int nf = 0; nf < 4; nf++) {
                    const uint32_t* bph = &bh[nf >> 1][(nf & 1) * 2];
                    mma16816(acc[i][nf], ah[i], bph);
                    mma16816(acc[i][nf], al[i], bph);
                    if (PASSES == 3) {
                        const uint32_t* bpl = &bl[nf >> 1][(nf & 1) * 2];
                        mma16816(acc[i][nf], ah[i], bpl);
                    }
                }
            }
        }
    }

    // epilogue
#pragma unroll
    for (int i = 0; i < 4; i++) {
        int r0 = bm + wm + i * 16 + (lane >> 2);
#pragma unroll
        for (int nf = 0; nf < 4; nf++) {
            int c = bn + wn + nf * 8 + (lane & 3) * 2;
            float b0 = bias[c], b1 = bias[c + 1];
            if (r0 < NROI) {
                Co[(size_t)r0 * FDIM + c]     = acc[i][nf][0] + b0;
                Co[(size_t)r0 * FDIM + c + 1] = acc[i][nf][1] + b1;
            }
            if (r0 + 8 < NROI) {
                Co[(size_t)(r0 + 8) * FDIM + c]     = acc[i][nf][2] + b0;
                Co[(size_t)(r0 + 8) * FDIM + c + 1] = acc[i][nf][3] + b1;
            }
        }
    }
}

// ---------------- BN stats: parallel partial sums + deterministic reduce ----
__global__ __launch_bounds__(256) void bn_partial_kernel(int phase)
{
    const float* X = (phase == 0) ? g_x1 : g_x2;
    int f  = blockIdx.x * 256 + threadIdx.x;
    int rc = blockIdx.y;
    int b  = blockIdx.z;
    const float* p = X + ((size_t)b * 1000 + rc * 125) * FDIM + f;

    float s = 0.f, q = 0.f;
#pragma unroll 5
    for (int n = 0; n < 125; n++) {
        float v = p[(size_t)n * FDIM];
        s += v; q += v * v;
    }
    int idx = (b * 8 + rc) * FDIM + f;
    g_psum[idx] = s;
    g_psq[idx]  = q;
}

__global__ __launch_bounds__(256) void bn_final_kernel(int phase)
{
    float* mu   = (phase == 0) ? g_mu1   : g_mu2;
    float* rstd = (phase == 0) ? g_rstd1 : g_rstd2;
    int f = blockIdx.y * 256 + threadIdx.x;
    int b = blockIdx.x;

    float s = 0.f, q = 0.f;
#pragma unroll
    for (int rc = 0; rc < 8; rc++) {
        int idx = (b * 8 + rc) * FDIM + f;
        s += g_psum[idx];
        q += g_psq[idx];
    }
    float m   = s * (1.0f / 1000.0f);
    float var = q * (1.0f / 1000.0f) - m * m;
    mu[b * FDIM + f]   = m;
    rstd[b * FDIM + f] = rsqrtf(var + 1e-5f);
}

// ---------------- BN1+relu apply -> fp16 hi/lo for GEMM2 ----------------
__global__ __launch_bounds__(256) void bn_apply_kernel(
    const float* __restrict__ gam, const float* __restrict__ bet)
{
    int i = blockIdx.x * 256 + threadIdx.x;
    if (i >= NROI * FDIM / 4) return;
    int e   = i * 4;
    int row = e >> 10;
    int b   = (row >= 1000);
    int kg  = e & 1023;

    float4 v   = *(const float4*)(g_x1 + e);
    float4 g4  = *(const float4*)(gam + kg);
    float4 b4  = *(const float4*)(bet + kg);
    float4 mu4 = *(const float4*)(g_mu1 + b * FDIM + kg);
    float4 rs4 = *(const float4*)(g_rstd1 + b * FDIM + kg);
    float o0 = fmaxf(g4.x * (v.x - mu4.x) * rs4.x + b4.x, 0.f);
    float o1 = fmaxf(g4.y * (v.y - mu4.y) * rs4.y + b4.y, 0.f);
    float o2 = fmaxf(g4.z * (v.z - mu4.z) * rs4.z + b4.z, 0.f);
    float o3 = fmaxf(g4.w * (v.w - mu4.w) * rs4.w + b4.w, 0.f);

    __half h0 = __float2half_rn(o0), h1 = __float2half_rn(o1);
    __half h2 = __float2half_rn(o2), h3 = __float2half_rn(o3);
    __half2* H = (__half2*)g_A2hi;
    __half2* L = (__half2*)g_A2lo;
    H[i*2]   = __half2(h0, h1);
    H[i*2+1] = __half2(h2, h3);
    L[i*2]   = __half2(__float2half_rn(o0 - __half2float(h0)),
                       __float2half_rn(o1 - __half2float(h1)));
    L[i*2+1] = __half2(__float2half_rn(o2 - __half2float(h2)),
                       __float2half_rn(o3 - __half2float(h3)));
}

// ---------------- head: bn2_relu -> logits/bbox GEMV + softmax --------------
#define RPB 8
__global__ __launch_bounds__(256) void head_kernel(
    const float* __restrict__ g2, const float* __restrict__ b2,
    const float* __restrict__ Wl, const float* __restrict__ bl,
    const float* __restrict__ Wb, const float* __restrict__ bb,
    float* __restrict__ out)
{
    __shared__ float sh[RPB][FDIM];
    __shared__ float lg[RPB][NCLS];

    int m0  = blockIdx.x * RPB;
    int tid = threadIdx.x;

    for (int r = 0; r < RPB; r++) {
        int m = m0 + r;
        int b = m / 1000;
        for (int k = tid; k < FDIM; k += 256) {
            float v = g_x2[(size_t)m * FDIM + k];
            v = g2[k] * (v - g_mu2[b * FDIM + k]) * g_rstd2[b * FDIM + k] + b2[k];
            sh[r][k] = fmaxf(v, 0.f);
        }
    }
    __syncthreads();

    for (int o = tid; o < NOUT; o += 256) {
        const float* W; float bias;
        if (o < NCLS) { W = Wl + (size_t)o * FDIM;          bias = bl[o]; }
        else          { W = Wb + (size_t)(o - NCLS) * FDIM; bias = bb[o - NCLS]; }

        float acc[RPB];
#pragma unroll
        for (int r = 0; r < RPB; r++) acc[r] = 0.f;

        for (int k = 0; k < FDIM; k += 4) {
            float4 wv = *(const float4*)(W + k);
#pragma unroll
            for (int r = 0; r < RPB; r++) {
                float4 sv = *(const float4*)&sh[r][k];
                acc[r] += sv.x * wv.x + sv.y * wv.y + sv.z * wv.z + sv.w * wv.w;
            }
        }
#pragma unroll
        for (int r = 0; r < RPB; r++) {
            int m = m0 + r;
            float v = acc[r] + bias;
            if (o < NCLS) {
                lg[r][o] = v;
                out[(size_t)m * NCLS + o] = v;
            } else {
                out[324000 + (size_t)m * NBOX + (o - NCLS)] = v;
            }
        }
    }
    __syncthreads();

    int wid = tid >> 5, lane = tid & 31;
    if (wid < RPB) {
        int m = m0 + wid;
        float mx = -1e30f;
        for (int i = lane; i < NCLS; i += 32) mx = fmaxf(mx, lg[wid][i]);
#pragma unroll
        for (int off = 16; off; off >>= 1) mx = fmaxf(mx, __shfl_xor_sync(0xffffffffu, mx, off));
        float sum = 0.f;
        for (int i = lane; i < NCLS; i += 32) sum += expf(lg[wid][i] - mx);
#pragma unroll
        for (int off = 16; off; off >>= 1) sum += __shfl_xor_sync(0xffffffffu, sum, off);
        float inv = 1.0f / sum;
        for (int i = lane; i < NCLS; i += 32)
            out[162000 + (size_t)m * NCLS + i] = expf(lg[wid][i] - mx) * inv;
    }
}

// ---------------- launch ----------------
extern "C" void kernel_launch(void* const* d_in, const int* in_sizes, int n_in,
                              void* d_out, int out_size)
{
    const float* rois    = (const float*)d_in[0];
    const float* p2      = (const float*)d_in[1];
    const float* p3      = (const float*)d_in[2];
    const float* p4      = (const float*)d_in[3];
    const float* p5      = (const float*)d_in[4];
    const float* conv1_w = (const float*)d_in[5];
    const float* conv1_b = (const float*)d_in[6];
    const float* bn1_g   = (const float*)d_in[7];
    const float* bn1_b   = (const float*)d_in[8];
    const float* conv2_w = (const float*)d_in[9];
    const float* conv2_b = (const float*)d_in[10];
    const float* bn2_g   = (const float*)d_in[11];
    const float* bn2_b   = (const float*)d_in[12];
    const float* logitsW = (const float*)d_in[13];
    const float* logitsB = (const float*)d_in[14];
    const float* bboxW   = (const float*)d_in[15];
    const float* bboxB   = (const float*)d_in[16];
    float* out = (float*)d_out;

    cudaFuncSetAttribute(hmma_gemm<2>, cudaFuncAttributeMaxDynamicSharedMemorySize, GSMEM);
    cudaFuncSetAttribute(hmma_gemm<3>, cudaFuncAttributeMaxDynamicSharedMemorySize, GSMEM);

    __half *a1h, *a1l, *b1h, *b1l, *a2h, *a2l, *b2h, *b2l;
    float *x1, *x2;
    cudaGetSymbolAddress((void**)&a1h, g_A1hi); cudaGetSymbolAddress((void**)&a1l, g_A1lo);
    cudaGetSymbolAddress((void**)&b1h, g_B1hi); cudaGetSymbolAddress((void**)&b1l, g_B1lo);
    cudaGetSymbolAddress((void**)&a2h, g_A2hi); cudaGetSymbolAddress((void**)&a2l, g_A2lo);
    cudaGetSymbolAddress((void**)&b2h, g_B2hi); cudaGetSymbolAddress((void**)&b2l, g_B2lo);
    cudaGetSymbolAddress((void**)&x1, g_x1);    cudaGetSymbolAddress((void**)&x2, g_x2);

    const int n4_1 = FDIM * KDIM / 4;     // conv1_w float4 count
    const int n4_2 = FDIM * FDIM / 4;

    // launches 1-5 (so ncu -s 5 -c 1 captures GEMM1 as launch 6)
    roi_align_kernel<<<1000, 256>>>(rois, 0, p2, p3, p4, p5);
    roi_align_kernel<<<1000, 256>>>(rois, 1, p2, p3, p4, p5);
    cvt_kernel<<<(n4_1 / 2 + 255) / 256, 256>>>(conv1_w, b1h, b1l, 0, n4_1 / 2);
    cvt_kernel<<<(n4_1 - n4_1 / 2 + 255) / 256, 256>>>(conv1_w, b1h, b1l, n4_1 / 2, n4_1);
    cvt_kernel<<<(n4_2 + 255) / 256, 256>>>(conv2_w, b2h, b2l, 0, n4_2);

    // 6) GEMM1 (fp16 2-pass)
    hmma_gemm<2><<<dim3(FDIM / 128, MPAD / 128), 256, GSMEM>>>(
        a1h, a1l, b1h, b1l, conv1_b, x1, KDIM);

    // BN1
    bn_partial_kernel<<<dim3(4, 8, 2), 256>>>(0);
    bn_final_kernel<<<dim3(2, 4), 256>>>(0);
    bn_apply_kernel<<<(NROI * FDIM / 4 + 255) / 256, 256>>>(bn1_g, bn1_b);

    // GEMM2 (fp16 3-pass)
    hmma_gemm<3><<<dim3(FDIM / 128, MPAD / 128), 256, GSMEM>>>(
        a2h, a2l, b2h, b2l, conv2_b, x2, FDIM);

    // BN2
    bn_partial_kernel<<<dim3(4, 8, 2), 256>>>(1);
    bn_final_kernel<<<dim3(2, 4), 256>>>(1);

    // head
    head_kernel<<<NROI / RPB, 256>>>(bn2_g, bn2_b, logitsW, logitsB, bboxW, bboxB, out);
}

// round 7
// speedup vs baseline: 2.8350x; 1.0638x over previous
#include <cuda_runtime.h>
#include <cuda_fp16.h>
#include <cstdint>
#include <math.h>

#define NROI   2000
#define MPAD   2048
#define C_IN   256
#define KDIM   12544      // 256*7*7
#define FDIM   1024
#define NCLS   81
#define NBOX   324
#define NOUT   405

// ---------------- scratch (static device globals; zero-init at load) --------
__device__ __half g_A1hi[(size_t)MPAD * KDIM];
__device__ __half g_A1lo[(size_t)MPAD * KDIM];
__device__ __half g_B1hi[(size_t)FDIM * KDIM];
__device__ __half g_B1lo[(size_t)FDIM * KDIM];     // unused by 2-pass GEMM1
__device__ __half g_A2hi[(size_t)MPAD * FDIM];
__device__ __half g_A2lo[(size_t)MPAD * FDIM];
__device__ __half g_B2hi[(size_t)FDIM * FDIM];
__device__ __half g_B2lo[(size_t)FDIM * FDIM];
__device__ float g_x1[NROI * FDIM];
__device__ float g_x2[NROI * FDIM];
__device__ float g_mu1[2 * FDIM];
__device__ float g_rstd1[2 * FDIM];
__device__ float g_mu2[2 * FDIM];
__device__ float g_rstd2[2 * FDIM];
__device__ float g_psum[16 * FDIM];
__device__ float g_psq[16 * FDIM];

// ---------------- helpers ----------------
__device__ __forceinline__ uint32_t smem_u32(const void* p) {
    uint32_t a;
    asm("{ .reg .u64 t; cvta.to.shared.u64 t, %1; cvt.u32.u64 %0, t; }" : "=r"(a) : "l"(p));
    return a;
}
#define CPA(dst, src) \
    asm volatile("cp.async.cg.shared.global [%0], [%1], 16;" :: "r"(dst), "l"(src))
#define CPA_COMMIT() asm volatile("cp.async.commit_group;" ::: "memory")
#define CPA_WAIT1()  asm volatile("cp.async.wait_group 1;" ::: "memory")
#define CPA_WAIT0()  asm volatile("cp.async.wait_group 0;" ::: "memory")

__device__ __forceinline__ void ldm4(uint32_t* r, uint32_t addr) {
    asm volatile("ldmatrix.sync.aligned.m8n8.x4.shared.b16 {%0,%1,%2,%3}, [%4];"
        : "=r"(r[0]), "=r"(r[1]), "=r"(r[2]), "=r"(r[3]) : "r"(addr));
}
__device__ __forceinline__ void mma16816(float* d, const uint32_t* a, const uint32_t* b) {
    asm volatile("mma.sync.aligned.m16n8k16.row.col.f32.f16.f16.f32 "
        "{%0,%1,%2,%3},{%4,%5,%6,%7},{%8,%9},{%0,%1,%2,%3};"
        : "+f"(d[0]), "+f"(d[1]), "+f"(d[2]), "+f"(d[3])
        : "r"(a[0]), "r"(a[1]), "r"(a[2]), "r"(a[3]), "r"(b[0]), "r"(b[1]));
}

// ---------------- kernel 1: pyramid ROI align -> fp16 hi/lo ----------------
__global__ __launch_bounds__(256) void roi_align_kernel(
    const float* __restrict__ rois, int b,
    const float* __restrict__ p2, const float* __restrict__ p3,
    const float* __restrict__ p4, const float* __restrict__ p5)
{
    int roi  = b * 1000 + blockIdx.x;
    int tid  = threadIdx.x;
    int wid  = tid >> 5, lane = tid & 31;

    const float* r = rois + (size_t)roi * 4;
    float y1 = r[0], x1 = r[1], y2 = r[2], x2 = r[3];
    float hh = y2 - y1, ww = x2 - x1;

    float s   = sqrtf(fmaxf(hh * ww, 1e-12f));
    float lvl = log2f(s / 0.21875f);
    int level = 4 + (int)rintf(lvl);
    level = level < 2 ? 2 : (level > 5 ? 5 : level);

    const float* feat; int H;
    if      (level == 2) { feat = p2; H = 256; }
    else if (level == 3) { feat = p3; H = 128; }
    else if (level == 4) { feat = p4; H = 64;  }
    else                 { feat = p5; H = 32;  }
    float Hm1 = (float)(H - 1);

    float wxv[7], wyv[7];
    int xi0v[7], xi1v[7], yi0v[7], yi1v[7];
#pragma unroll
    for (int p = 0; p < 7; p++) {
        float t  = (float)p * (1.0f / 6.0f);
        float xs = (x1 + ww * t) * Hm1;
        float x0 = floorf(xs);
        wxv[p]  = xs - x0;
        int xi = (int)x0;
        xi0v[p] = min(max(xi, 0), H - 1);
        xi1v[p] = min(max(xi + 1, 0), H - 1);
        float ys = (y1 + hh * t) * Hm1;
        float y0 = floorf(ys);
        wyv[p]  = ys - y0;
        int yi = (int)y0;
        yi0v[p] = min(max(yi, 0), H - 1);
        yi1v[p] = min(max(yi + 1, 0), H - 1);
    }

    int xlo  = xi0v[0];
    int span = xi1v[6] - xlo + 1;

    int pxl   = lane < 7 ? lane : 0;
    int s0    = xi0v[pxl] - xlo;
    int s1    = xi1v[pxl] - xlo;
    float wxl = wxv[pxl];

    if (span <= 32) {
        for (int c = wid * 32; c < wid * 32 + 32; c++) {
            const float* plane = feat + (size_t)(b * C_IN + c) * H * H;
            size_t obase = (size_t)roi * KDIM + (size_t)c * 49;
#pragma unroll
            for (int py = 0; py < 7; py++) {
                float v0 = 0.f, v1 = 0.f;
                if (lane < span) {
                    v0 = plane[yi0v[py] * H + xlo + lane];
                    v1 = plane[yi1v[py] * H + xlo + lane];
                }
                float a0 = __shfl_sync(0xffffffffu, v0, s0);
                float a1 = __shfl_sync(0xffffffffu, v0, s1);
                float c0 = __shfl_sync(0xffffffffu, v1, s0);
                float c1 = __shfl_sync(0xffffffffu, v1, s1);
                if (lane < 7) {
                    float wy = wyv[py], wx = wxl;
                    float val = a0 * (1.f - wy) * (1.f - wx)
                              + a1 * (1.f - wy) * wx
                              + c0 * wy * (1.f - wx)
                              + c1 * wy * wx;
                    __half h = __float2half_rn(val);
                    g_A1hi[obase + py * 7 + lane] = h;
                    g_A1lo[obase + py * 7 + lane] =
                        __float2half_rn(val - __half2float(h));
                }
            }
        }
    } else {
        for (int c = wid * 32; c < wid * 32 + 32; c++) {
            const float* plane = feat + (size_t)(b * C_IN + c) * H * H;
            size_t obase = (size_t)roi * KDIM + (size_t)c * 49;
            if (lane < 7) {
#pragma unroll
                for (int py = 0; py < 7; py++) {
                    const float* row0 = plane + yi0v[py] * H;
                    const float* row1 = plane + yi1v[py] * H;
                    float wy = wyv[py], wx = wxl;
                    float v00 = row0[xi0v[lane]], v01 = row0[xi1v[lane]];
                    float v10 = row1[xi0v[lane]], v11 = row1[xi1v[lane]];
                    float val = v00 * (1.f - wy) * (1.f - wx)
                              + v01 * (1.f - wy) * wx
                              + v10 * wy * (1.f - wx)
                              + v11 * wy * wx;
                    __half h = __float2half_rn(val);
                    g_A1hi[obase + py * 7 + lane] = h;
                    g_A1lo[obase + py * 7 + lane] =
                        __float2half_rn(val - __half2float(h));
                }
            }
        }
    }
}

// ---------------- fp32 -> fp16 hi/lo split ----------------
__global__ __launch_bounds__(256) void cvt_kernel(
    const float* __restrict__ in, __half* __restrict__ hi,
    __half* __restrict__ lo, int off4, int n4)
{
    int i = off4 + blockIdx.x * 256 + threadIdx.x;
    if (i >= n4) return;
    float4 v = ((const float4*)in)[i];
    __half h0 = __float2half_rn(v.x), h1 = __float2half_rn(v.y);
    __half h2 = __float2half_rn(v.z), h3 = __float2half_rn(v.w);
    __half2* H = (__half2*)hi;
    __half2* L = (__half2*)lo;
    H[i*2]   = __half2(h0, h1);
    H[i*2+1] = __half2(h2, h3);
    L[i*2]   = __half2(__float2half_rn(v.x - __half2float(h0)),
                       __float2half_rn(v.y - __half2float(h1)));
    L[i*2+1] = __half2(__float2half_rn(v.z - __half2float(h2)),
                       __float2half_rn(v.w - __half2float(h3)));
}

// ---------------- HMMA GEMM: C[M,1024] = A[M,K]*B[1024,K]^T + bias ----------
// fp16 split. PASSES=2: Ah*Bh + Al*Bh. PASSES=3: + Ah*Bl.
// 128x128 CTA tile, BK=64, 8 warps (4Mx2N), warp tile 32x64, 3-stage cp.async.
// Row stride 144B (128B data + 16 pad -> conflict-free ldmatrix).
#define ROWB    144
#define TILE_B  18432           // 128 * 144

template<int PASSES>
__device__ __forceinline__ void issue_stage(
    const __half* __restrict__ Ah, const __half* __restrict__ Al,
    const __half* __restrict__ Bh, const __half* __restrict__ Bl,
    int K, int k0, uint32_t sbase, int tid)
{
    const __half* gs[4] = {Ah, Al, Bh, Bl};
    const int NT = (PASSES == 3) ? 4 : 3;
#pragma unroll
    for (int t = 0; t < NT; t++) {
#pragma unroll
        for (int i = 0; i < 4; i++) {
            int u   = tid + i * 256;
            int row = u >> 3, seg = u & 7;
            const void* g = gs[t] + (size_t)row * K + k0 + seg * 8;
            uint32_t sm   = sbase + t * TILE_B + row * ROWB + seg * 16;
            CPA(sm, g);
        }
    }
}

template<int PASSES>
__global__ __launch_bounds__(256, 1) void hmma_gemm(
    const __half* __restrict__ Ahi, const __half* __restrict__ Alo,
    const __half* __restrict__ Bhi, const __half* __restrict__ Blo,
    const float* __restrict__ bias, float* __restrict__ Co, int K)
{
    const int NT = (PASSES == 3) ? 4 : 3;
    const uint32_t STAGE = NT * TILE_B;

    extern __shared__ char smem[];
    uint32_t sb = smem_u32(smem);

    int tid  = threadIdx.x;
    int wid  = tid >> 5, lane = tid & 31;
    int wm   = (wid & 3) * 32;        // 4 M-rows of warps
    int wn   = (wid >> 2) * 64;       // 2 N-cols of warps
    int bm   = blockIdx.y * 128;
    int bn   = blockIdx.x * 128;

    const __half* Ah = Ahi + (size_t)bm * K;
    const __half* Al = Alo + (size_t)bm * K;
    const __half* Bh = Bhi + (size_t)bn * K;
    const __half* Bl = Blo + (size_t)bn * K;

    uint32_t offA[2], offB[4];
#pragma unroll
    for (int i = 0; i < 2; i++)
        offA[i] = (wm + i * 16 + (lane & 15)) * ROWB + ((lane >> 4) << 4);
#pragma unroll
    for (int j = 0; j < 4; j++)
        offB[j] = (wn + j * 16 + ((lane >> 4) << 3) + (lane & 7)) * ROWB
                + (((lane >> 3) & 1) << 4);

    float acc[2][8][4];
#pragma unroll
    for (int i = 0; i < 2; i++)
#pragma unroll
        for (int n = 0; n < 8; n++)
#pragma unroll
            for (int q = 0; q < 4; q++) acc[i][n][q] = 0.f;

    int nch = K >> 6;

    issue_stage<PASSES>(Ah, Al, Bh, Bl, K, 0, sb, tid);
    CPA_COMMIT();
    if (nch > 1) {
        issue_stage<PASSES>(Ah, Al, Bh, Bl, K, 64, sb + STAGE, tid);
        CPA_COMMIT();
    }

    for (int k = 0; k < nch; k++) {
        if (k == nch - 1) { CPA_WAIT0(); } else { CPA_WAIT1(); }
        __syncthreads();   // single barrier: data visible + prev buffer free

        if (k + 2 < nch) {
            issue_stage<PASSES>(Ah, Al, Bh, Bl, K, (k + 2) << 6,
                                sb + ((k + 2) % 3) * STAGE, tid);
            CPA_COMMIT();
        }

        uint32_t stb = sb + (k % 3) * STAGE;
#pragma unroll
        for (int s = 0; s < 4; s++) {
            uint32_t so = s * 32;
            uint32_t ah[2][4], al[2][4], bh[4][4], bl[4][4];
#pragma unroll
            for (int i = 0; i < 2; i++) {
                ldm4(ah[i], stb + 0 * TILE_B + offA[i] + so);
                ldm4(al[i], stb + 1 * TILE_B + offA[i] + so);
            }
#pragma unroll
            for (int j = 0; j < 4; j++) {
                ldm4(bh[j], stb + 2 * TILE_B + offB[j] + so);
                if (PASSES == 3)
                    ldm4(bl[j], stb + 3 * TILE_B + offB[j] + so);
            }
#pragma unroll
            for (int i = 0; i < 2; i++) {
#pragma unroll
                for (int nf = 0; nf < 8; nf++) {
                    const uint32_t* bph = &bh[nf >> 1][(nf & 1) * 2];
                    mma16816(acc[i][nf], ah[i], bph);
                    mma16816(acc[i][nf], al[i], bph);
                    if (PASSES == 3) {
                        const uint32_t* bpl = &bl[nf >> 1][(nf & 1) * 2];
                        mma16816(acc[i][nf], ah[i], bpl);
                    }
                }
            }
        }
    }

    // epilogue
#pragma unroll
    for (int i = 0; i < 2; i++) {
        int r0 = bm + wm + i * 16 + (lane >> 2);
#pragma unroll
        for (int nf = 0; nf < 8; nf++) {
            int c = bn + wn + nf * 8 + (lane & 3) * 2;
            float b0 = bias[c], b1 = bias[c + 1];
            if (r0 < NROI) {
                Co[(size_t)r0 * FDIM + c]     = acc[i][nf][0] + b0;
                Co[(size_t)r0 * FDIM + c + 1] = acc[i][nf][1] + b1;
            }
            if (r0 + 8 < NROI) {
                Co[(size_t)(r0 + 8) * FDIM + c]     = acc[i][nf][2] + b0;
                Co[(size_t)(r0 + 8) * FDIM + c + 1] = acc[i][nf][3] + b1;
            }
        }
    }
}

#define GSMEM2P (3 * 3 * TILE_B)    // 165888
#define GSMEM3P (3 * 4 * TILE_B)    // 221184

// ---------------- BN stats: parallel partial sums + deterministic reduce ----
__global__ __launch_bounds__(256) void bn_partial_kernel(int phase)
{
    const float* X = (phase == 0) ? g_x1 : g_x2;
    int f  = blockIdx.x * 256 + threadIdx.x;
    int rc = blockIdx.y;
    int b  = blockIdx.z;
    const float* p = X + ((size_t)b * 1000 + rc * 125) * FDIM + f;

    float s = 0.f, q = 0.f;
#pragma unroll 5
    for (int n = 0; n < 125; n++) {
        float v = p[(size_t)n * FDIM];
        s += v; q += v * v;
    }
    int idx = (b * 8 + rc) * FDIM + f;
    g_psum[idx] = s;
    g_psq[idx]  = q;
}

__global__ __launch_bounds__(256) void bn_final_kernel(int phase)
{
    float* mu   = (phase == 0) ? g_mu1   : g_mu2;
    float* rstd = (phase == 0) ? g_rstd1 : g_rstd2;
    int f = blockIdx.y * 256 + threadIdx.x;
    int b = blockIdx.x;

    float s = 0.f, q = 0.f;
#pragma unroll
    for (int rc = 0; rc < 8; rc++) {
        int idx = (b * 8 + rc) * FDIM + f;
        s += g_psum[idx];
        q += g_psq[idx];
    }
    float m   = s * (1.0f / 1000.0f);
    float var = q * (1.0f / 1000.0f) - m * m;
    mu[b * FDIM + f]   = m;
    rstd[b * FDIM + f] = rsqrtf(var + 1e-5f);
}

// ---------------- BN1+relu apply -> fp16 hi/lo for GEMM2 ----------------
__global__ __launch_bounds__(256) void bn_apply_kernel(
    const float* __restrict__ gam, const float* __restrict__ bet)
{
    int i = blockIdx.x * 256 + threadIdx.x;
    if (i >= NROI * FDIM / 4) return;
    int e   = i * 4;
    int row = e >> 10;
    int b   = (row >= 1000);
    int kg  = e & 1023;

    float4 v   = *(const float4*)(g_x1 + e);
    float4 g4  = *(const float4*)(gam + kg);
    float4 b4  = *(const float4*)(bet + kg);
    float4 mu4 = *(const float4*)(g_mu1 + b * FDIM + kg);
    float4 rs4 = *(const float4*)(g_rstd1 + b * FDIM + kg);
    float o0 = fmaxf(g4.x * (v.x - mu4.x) * rs4.x + b4.x, 0.f);
    float o1 = fmaxf(g4.y * (v.y - mu4.y) * rs4.y + b4.y, 0.f);
    float o2 = fmaxf(g4.z * (v.z - mu4.z) * rs4.z + b4.z, 0.f);
    float o3 = fmaxf(g4.w * (v.w - mu4.w) * rs4.w + b4.w, 0.f);

    __half h0 = __float2half_rn(o0), h1 = __float2half_rn(o1);
    __half h2 = __float2half_rn(o2), h3 = __float2half_rn(o3);
    __half2* H = (__half2*)g_A2hi;
    __half2* L = (__half2*)g_A2lo;
    H[i*2]   = __half2(h0, h1);
    H[i*2+1] = __half2(h2, h3);
    L[i*2]   = __half2(__float2half_rn(o0 - __half2float(h0)),
                       __float2half_rn(o1 - __half2float(h1)));
    L[i*2+1] = __half2(__float2half_rn(o2 - __half2float(h2)),
                       __float2half_rn(o3 - __half2float(h3)));
}

// ---------------- head: bn2_relu -> logits/bbox GEMV + softmax --------------
#define RPB 8
__global__ __launch_bounds__(256) void head_kernel(
    const float* __restrict__ g2, const float* __restrict__ b2,
    const float* __restrict__ Wl, const float* __restrict__ bl,
    const float* __restrict__ Wb, const float* __restrict__ bb,
    float* __restrict__ out)
{
    __shared__ float sh[RPB][FDIM];
    __shared__ float lg[RPB][NCLS];

    int m0  = blockIdx.x * RPB;
    int tid = threadIdx.x;

    for (int r = 0; r < RPB; r++) {
        int m = m0 + r;
        int b = m / 1000;
        for (int k = tid; k < FDIM; k += 256) {
            float v = g_x2[(size_t)m * FDIM + k];
            v = g2[k] * (v - g_mu2[b * FDIM + k]) * g_rstd2[b * FDIM + k] + b2[k];
            sh[r][k] = fmaxf(v, 0.f);
        }
    }
    __syncthreads();

    for (int o = tid; o < NOUT; o += 256) {
        const float* W; float bias;
        if (o < NCLS) { W = Wl + (size_t)o * FDIM;          bias = bl[o]; }
        else          { W = Wb + (size_t)(o - NCLS) * FDIM; bias = bb[o - NCLS]; }

        float acc[RPB];
#pragma unroll
        for (int r = 0; r < RPB; r++) acc[r] = 0.f;

        for (int k = 0; k < FDIM; k += 4) {
            float4 wv = *(const float4*)(W + k);
#pragma unroll
            for (int r = 0; r < RPB; r++) {
                float4 sv = *(const float4*)&sh[r][k];
                acc[r] += sv.x * wv.x + sv.y * wv.y + sv.z * wv.z + sv.w * wv.w;
            }
        }
#pragma unroll
        for (int r = 0; r < RPB; r++) {
            int m = m0 + r;
            float v = acc[r] + bias;
            if (o < NCLS) {
                lg[r][o] = v;
                out[(size_t)m * NCLS + o] = v;
            } else {
                out[324000 + (size_t)m * NBOX + (o - NCLS)] = v;
            }
        }
    }
    __syncthreads();

    int wid = tid >> 5, lane = tid & 31;
    if (wid < RPB) {
        int m = m0 + wid;
        float mx = -1e30f;
        for (int i = lane; i < NCLS; i += 32) mx = fmaxf(mx, lg[wid][i]);
#pragma unroll
        for (int off = 16; off; off >>= 1) mx = fmaxf(mx, __shfl_xor_sync(0xffffffffu, mx, off));
        float sum = 0.f;
        for (int i = lane; i < NCLS; i += 32) sum += expf(lg[wid][i] - mx);
#pragma unroll
        for (int off = 16; off; off >>= 1) sum += __shfl_xor_sync(0xffffffffu, sum, off);
        float inv = 1.0f / sum;
        for (int i = lane; i < NCLS; i += 32)
            out[162000 + (size_t)m * NCLS + i] = expf(lg[wid][i] - mx) * inv;
    }
}

// ---------------- launch ----------------
extern "C" void kernel_launch(void* const* d_in, const int* in_sizes, int n_in,
                              void* d_out, int out_size)
{
    const float* rois    = (const float*)d_in[0];
    const float* p2      = (const float*)d_in[1];
    const float* p3      = (const float*)d_in[2];
    const float* p4      = (const float*)d_in[3];
    const float* p5      = (const float*)d_in[4];
    const float* conv1_w = (const float*)d_in[5];
    const float* conv1_b = (const float*)d_in[6];
    const float* bn1_g   = (const float*)d_in[7];
    const float* bn1_b   = (const float*)d_in[8];
    const float* conv2_w = (const float*)d_in[9];
    const float* conv2_b = (const float*)d_in[10];
    const float* bn2_g   = (const float*)d_in[11];
    const float* bn2_b   = (const float*)d_in[12];
    const float* logitsW = (const float*)d_in[13];
    const float* logitsB = (const float*)d_in[14];
    const float* bboxW   = (const float*)d_in[15];
    const float* bboxB   = (const float*)d_in[16];
    float* out = (float*)d_out;

    cudaFuncSetAttribute(hmma_gemm<2>, cudaFuncAttributeMaxDynamicSharedMemorySize, GSMEM2P);
    cudaFuncSetAttribute(hmma_gemm<3>, cudaFuncAttributeMaxDynamicSharedMemorySize, GSMEM3P);

    __half *a1h, *a1l, *b1h, *b1l, *a2h, *a2l, *b2h, *b2l;
    float *x1, *x2;
    cudaGetSymbolAddress((void**)&a1h, g_A1hi); cudaGetSymbolAddress((void**)&a1l, g_A1lo);
    cudaGetSymbolAddress((void**)&b1h, g_B1hi); cudaGetSymbolAddress((void**)&b1l, g_B1lo);
    cudaGetSymbolAddress((void**)&a2h, g_A2hi); cudaGetSymbolAddress((void**)&a2l, g_A2lo);
    cudaGetSymbolAddress((void**)&b2h, g_B2hi); cudaGetSymbolAddress((void**)&b2l, g_B2lo);
    cudaGetSymbolAddress((void**)&x1, g_x1);    cudaGetSymbolAddress((void**)&x2, g_x2);

    const int n4_1 = FDIM * KDIM / 4;
    const int n4_2 = FDIM * FDIM / 4;

    roi_align_kernel<<<1000, 256>>>(rois, 0, p2, p3, p4, p5);
    roi_align_kernel<<<1000, 256>>>(rois, 1, p2, p3, p4, p5);
    cvt_kernel<<<(n4_1 / 2 + 255) / 256, 256>>>(conv1_w, b1h, b1l, 0, n4_1 / 2);
    cvt_kernel<<<(n4_1 - n4_1 / 2 + 255) / 256, 256>>>(conv1_w, b1h, b1l, n4_1 / 2, n4_1);
    cvt_kernel<<<(n4_2 + 255) / 256, 256>>>(conv2_w, b2h, b2l, 0, n4_2);

    // GEMM1 (fp16 2-pass, BK=64)
    hmma_gemm<2><<<dim3(FDIM / 128, MPAD / 128), 256, GSMEM2P>>>(
        a1h, a1l, b1h, b1l, conv1_b, x1, KDIM);

    // BN1
    bn_partial_kernel<<<dim3(4, 8, 2), 256>>>(0);
    bn_final_kernel<<<dim3(2, 4), 256>>>(0);
    bn_apply_kernel<<<(NROI * FDIM / 4 + 255) / 256, 256>>>(bn1_g, bn1_b);

    // GEMM2 (fp16 3-pass, BK=64)
    hmma_gemm<3><<<dim3(FDIM / 128, MPAD / 128), 256, GSMEM3P>>>(
        a2h, a2l, b2h, b2l, conv2_b, x2, FDIM);

    // BN2
    bn_partial_kernel<<<dim3(4, 8, 2), 256>>>(1);
    bn_final_kernel<<<dim3(2, 4), 256>>>(1);

    // head
    head_kernel<<<NROI / RPB, 256>>>(bn2_g, bn2_b, logitsW, logitsB, bboxW, bboxB, out);
}

// round 8
// speedup vs baseline: 3.2791x; 1.1567x over previous
#include <cuda_runtime.h>
#include <cuda_fp16.h>
#include <cstdint>
#include <math.h>

#define NROI   2000
#define MPAD   2048
#define C_IN   256
#define KDIM   12544      // 256*7*7
#define FDIM   1024
#define NCLS   81
#define NBOX   324
#define NOUT   405

// ---------------- scratch (static device globals; zero-init at load) --------
__device__ __half g_A1hi[(size_t)MPAD * KDIM];
__device__ __half g_B1hi[(size_t)FDIM * KDIM];
__device__ __half g_A2hi[(size_t)MPAD * FDIM];
__device__ __half g_A2lo[(size_t)MPAD * FDIM];
__device__ __half g_B2hi[(size_t)FDIM * FDIM];
__device__ __half g_B2lo[(size_t)FDIM * FDIM];
__device__ float g_x1[NROI * FDIM];
__device__ float g_x2[NROI * FDIM];
__device__ float g_mu1[2 * FDIM];
__device__ float g_rstd1[2 * FDIM];
__device__ float g_mu2[2 * FDIM];
__device__ float g_rstd2[2 * FDIM];
__device__ float g_psum[16 * FDIM];
__device__ float g_psq[16 * FDIM];

// ---------------- helpers ----------------
__device__ __forceinline__ uint32_t smem_u32(const void* p) {
    uint32_t a;
    asm("{ .reg .u64 t; cvta.to.shared.u64 t, %1; cvt.u32.u64 %0, t; }" : "=r"(a) : "l"(p));
    return a;
}
#define CPA(dst, src) \
    asm volatile("cp.async.cg.shared.global [%0], [%1], 16;" :: "r"(dst), "l"(src))
#define CPA_COMMIT() asm volatile("cp.async.commit_group;" ::: "memory")
#define CPA_WAIT1()  asm volatile("cp.async.wait_group 1;" ::: "memory")
#define CPA_WAIT0()  asm volatile("cp.async.wait_group 0;" ::: "memory")

__device__ __forceinline__ void ldm4(uint32_t* r, uint32_t addr) {
    asm volatile("ldmatrix.sync.aligned.m8n8.x4.shared.b16 {%0,%1,%2,%3}, [%4];"
        : "=r"(r[0]), "=r"(r[1]), "=r"(r[2]), "=r"(r[3]) : "r"(addr));
}
__device__ __forceinline__ void mma16816(float* d, const uint32_t* a, const uint32_t* b) {
    asm volatile("mma.sync.aligned.m16n8k16.row.col.f32.f16.f16.f32 "
        "{%0,%1,%2,%3},{%4,%5,%6,%7},{%8,%9},{%0,%1,%2,%3};"
        : "+f"(d[0]), "+f"(d[1]), "+f"(d[2]), "+f"(d[3])
        : "r"(a[0]), "r"(a[1]), "r"(a[2]), "r"(a[3]), "r"(b[0]), "r"(b[1]));
}

// ---------------- kernel 1: pyramid ROI align -> fp16 (hi only) ------------
__global__ __launch_bounds__(256) void roi_align_kernel(
    const float* __restrict__ rois, int b,
    const float* __restrict__ p2, const float* __restrict__ p3,
    const float* __restrict__ p4, const float* __restrict__ p5)
{
    int roi  = b * 1000 + blockIdx.x;
    int tid  = threadIdx.x;
    int wid  = tid >> 5, lane = tid & 31;

    const float* r = rois + (size_t)roi * 4;
    float y1 = r[0], x1 = r[1], y2 = r[2], x2 = r[3];
    float hh = y2 - y1, ww = x2 - x1;

    float s   = sqrtf(fmaxf(hh * ww, 1e-12f));
    float lvl = log2f(s / 0.21875f);
    int level = 4 + (int)rintf(lvl);
    level = level < 2 ? 2 : (level > 5 ? 5 : level);

    const float* feat; int H;
    if      (level == 2) { feat = p2; H = 256; }
    else if (level == 3) { feat = p3; H = 128; }
    else if (level == 4) { feat = p4; H = 64;  }
    else                 { feat = p5; H = 32;  }
    float Hm1 = (float)(H - 1);

    float wxv[7], wyv[7];
    int xi0v[7], xi1v[7], yi0v[7], yi1v[7];
#pragma unroll
    for (int p = 0; p < 7; p++) {
        float t  = (float)p * (1.0f / 6.0f);
        float xs = (x1 + ww * t) * Hm1;
        float x0 = floorf(xs);
        wxv[p]  = xs - x0;
        int xi = (int)x0;
        xi0v[p] = min(max(xi, 0), H - 1);
        xi1v[p] = min(max(xi + 1, 0), H - 1);
        float ys = (y1 + hh * t) * Hm1;
        float y0 = floorf(ys);
        wyv[p]  = ys - y0;
        int yi = (int)y0;
        yi0v[p] = min(max(yi, 0), H - 1);
        yi1v[p] = min(max(yi + 1, 0), H - 1);
    }

    int xlo  = xi0v[0];
    int span = xi1v[6] - xlo + 1;

    int pxl   = lane < 7 ? lane : 0;
    int s0    = xi0v[pxl] - xlo;
    int s1    = xi1v[pxl] - xlo;
    float wxl = wxv[pxl];

    if (span <= 32) {
        for (int c = wid * 32; c < wid * 32 + 32; c++) {
            const float* plane = feat + (size_t)(b * C_IN + c) * H * H;
            size_t obase = (size_t)roi * KDIM + (size_t)c * 49;
#pragma unroll
            for (int py = 0; py < 7; py++) {
                float v0 = 0.f, v1 = 0.f;
                if (lane < span) {
                    v0 = plane[yi0v[py] * H + xlo + lane];
                    v1 = plane[yi1v[py] * H + xlo + lane];
                }
                float a0 = __shfl_sync(0xffffffffu, v0, s0);
                float a1 = __shfl_sync(0xffffffffu, v0, s1);
                float c0 = __shfl_sync(0xffffffffu, v1, s0);
                float c1 = __shfl_sync(0xffffffffu, v1, s1);
                if (lane < 7) {
                    float wy = wyv[py], wx = wxl;
                    float val = a0 * (1.f - wy) * (1.f - wx)
                              + a1 * (1.f - wy) * wx
                              + c0 * wy * (1.f - wx)
                              + c1 * wy * wx;
                    g_A1hi[obase + py * 7 + lane] = __float2half_rn(val);
                }
            }
        }
    } else {
        for (int c = wid * 32; c < wid * 32 + 32; c++) {
            const float* plane = feat + (size_t)(b * C_IN + c) * H * H;
            size_t obase = (size_t)roi * KDIM + (size_t)c * 49;
            if (lane < 7) {
#pragma unroll
                for (int py = 0; py < 7; py++) {
                    const float* row0 = plane + yi0v[py] * H;
                    const float* row1 = plane + yi1v[py] * H;
                    float wy = wyv[py], wx = wxl;
                    float v00 = row0[xi0v[lane]], v01 = row0[xi1v[lane]];
                    float v10 = row1[xi0v[lane]], v11 = row1[xi1v[lane]];
                    float val = v00 * (1.f - wy) * (1.f - wx)
                              + v01 * (1.f - wy) * wx
                              + v10 * wy * (1.f - wx)
                              + v11 * wy * wx;
                    g_A1hi[obase + py * 7 + lane] = __float2half_rn(val);
                }
            }
        }
    }
}

// ---------------- fp32 -> fp16 hi-only convert ----------------
__global__ __launch_bounds__(256) void cvt_hi_kernel(
    const float* __restrict__ in, __half* __restrict__ hi, int off4, int n4)
{
    int i = off4 + blockIdx.x * 256 + threadIdx.x;
    if (i >= n4) return;
    float4 v = ((const float4*)in)[i];
    __half2* H = (__half2*)hi;
    H[i*2]   = __half2(__float2half_rn(v.x), __float2half_rn(v.y));
    H[i*2+1] = __half2(__float2half_rn(v.z), __float2half_rn(v.w));
}

// ---------------- fp32 -> fp16 hi/lo split ----------------
__global__ __launch_bounds__(256) void cvt_kernel(
    const float* __restrict__ in, __half* __restrict__ hi,
    __half* __restrict__ lo, int off4, int n4)
{
    int i = off4 + blockIdx.x * 256 + threadIdx.x;
    if (i >= n4) return;
    float4 v = ((const float4*)in)[i];
    __half h0 = __float2half_rn(v.x), h1 = __float2half_rn(v.y);
    __half h2 = __float2half_rn(v.z), h3 = __float2half_rn(v.w);
    __half2* H = (__half2*)hi;
    __half2* L = (__half2*)lo;
    H[i*2]   = __half2(h0, h1);
    H[i*2+1] = __half2(h2, h3);
    L[i*2]   = __half2(__float2half_rn(v.x - __half2float(h0)),
                       __float2half_rn(v.y - __half2float(h1)));
    L[i*2+1] = __half2(__float2half_rn(v.z - __half2float(h2)),
                       __float2half_rn(v.w - __half2float(h3)));
}

// ---------------- HMMA GEMM: C[M,1024] = A[M,K]*B[1024,K]^T + bias ----------
// fp16 split. PASSES=1: Ah*Bh. PASSES=3: + Al*Bh + Ah*Bl.
// Tile order in SMEM: [Ah, Bh, Al, Bl].
// 128x128 CTA tile, BK=64, 8 warps (4Mx2N), warp tile 32x64, 3-stage cp.async.
#define ROWB    144
#define TILE_B  18432           // 128 * 144

template<int PASSES>
__device__ __forceinline__ void issue_stage(
    const __half* __restrict__ Ah, const __half* __restrict__ Bh,
    const __half* __restrict__ Al, const __half* __restrict__ Bl,
    int K, int k0, uint32_t sbase, int tid)
{
    const __half* gs[4] = {Ah, Bh, Al, Bl};
    const int NT = (PASSES == 3) ? 4 : 2;
#pragma unroll
    for (int t = 0; t < NT; t++) {
#pragma unroll
        for (int i = 0; i < 4; i++) {
            int u   = tid + i * 256;
            int row = u >> 3, seg = u & 7;
            const void* g = gs[t] + (size_t)row * K + k0 + seg * 8;
            uint32_t sm   = sbase + t * TILE_B + row * ROWB + seg * 16;
            CPA(sm, g);
        }
    }
}

template<int PASSES>
__global__ __launch_bounds__(256, 1) void hmma_gemm(
    const __half* __restrict__ Ahi, const __half* __restrict__ Alo,
    const __half* __restrict__ Bhi, const __half* __restrict__ Blo,
    const float* __restrict__ bias, float* __restrict__ Co, int K)
{
    const int NT = (PASSES == 3) ? 4 : 2;
    const uint32_t STAGE = NT * TILE_B;

    extern __shared__ char smem[];
    uint32_t sb = smem_u32(smem);

    int tid  = threadIdx.x;
    int wid  = tid >> 5, lane = tid & 31;
    int wm   = (wid & 3) * 32;
    int wn   = (wid >> 2) * 64;
    int bm   = blockIdx.y * 128;
    int bn   = blockIdx.x * 128;

    const __half* Ah = Ahi + (size_t)bm * K;
    const __half* Al = (PASSES == 3) ? Alo + (size_t)bm * K : Ahi + (size_t)bm * K;
    const __half* Bh = Bhi + (size_t)bn * K;
    const __half* Bl = (PASSES == 3) ? Blo + (size_t)bn * K : Bhi + (size_t)bn * K;

    uint32_t offA[2], offB[4];
#pragma unroll
    for (int i = 0; i < 2; i++)
        offA[i] = (wm + i * 16 + (lane & 15)) * ROWB + ((lane >> 4) << 4);
#pragma unroll
    for (int j = 0; j < 4; j++)
        offB[j] = (wn + j * 16 + ((lane >> 4) << 3) + (lane & 7)) * ROWB
                + (((lane >> 3) & 1) << 4);

    float acc[2][8][4];
#pragma unroll
    for (int i = 0; i < 2; i++)
#pragma unroll
        for (int n = 0; n < 8; n++)
#pragma unroll
            for (int q = 0; q < 4; q++) acc[i][n][q] = 0.f;

    int nch = K >> 6;

    issue_stage<PASSES>(Ah, Bh, Al, Bl, K, 0, sb, tid);
    CPA_COMMIT();
    if (nch > 1) {
        issue_stage<PASSES>(Ah, Bh, Al, Bl, K, 64, sb + STAGE, tid);
        CPA_COMMIT();
    }

    for (int k = 0; k < nch; k++) {
        if (k == nch - 1) { CPA_WAIT0(); } else { CPA_WAIT1(); }
        __syncthreads();

        if (k + 2 < nch) {
            issue_stage<PASSES>(Ah, Bh, Al, Bl, K, (k + 2) << 6,
                                sb + ((k + 2) % 3) * STAGE, tid);
            CPA_COMMIT();
        }

        uint32_t stb = sb + (k % 3) * STAGE;
#pragma unroll
        for (int s = 0; s < 4; s++) {
            uint32_t so = s * 32;
            uint32_t ah[2][4], al[2][4], bh[4][4], bl[4][4];
#pragma unroll
            for (int i = 0; i < 2; i++) {
                ldm4(ah[i], stb + 0 * TILE_B + offA[i] + so);
                if (PASSES == 3)
                    ldm4(al[i], stb + 2 * TILE_B + offA[i] + so);
            }
#pragma unroll
            for (int j = 0; j < 4; j++) {
                ldm4(bh[j], stb + 1 * TILE_B + offB[j] + so);
                if (PASSES == 3)
                    ldm4(bl[j], stb + 3 * TILE_B + offB[j] + so);
            }
#pragma unroll
            for (int i = 0; i < 2; i++) {
#pragma unroll
                for (int nf = 0; nf < 8; nf++) {
                    const uint32_t* bph = &bh[nf >> 1][(nf & 1) * 2];
                    mma16816(acc[i][nf], ah[i], bph);
                    if (PASSES == 3) {
                        const uint32_t* bpl = &bl[nf >> 1][(nf & 1) * 2];
                        mma16816(acc[i][nf], al[i], bph);
                        mma16816(acc[i][nf], ah[i], bpl);
                    }
                }
            }
        }
    }

    // epilogue
#pragma unroll
    for (int i = 0; i < 2; i++) {
        int r0 = bm + wm + i * 16 + (lane >> 2);
#pragma unroll
        for (int nf = 0; nf < 8; nf++) {
            int c = bn + wn + nf * 8 + (lane & 3) * 2;
            float b0 = bias[c], b1 = bias[c + 1];
            if (r0 < NROI) {
                Co[(size_t)r0 * FDIM + c]     = acc[i][nf][0] + b0;
                Co[(size_t)r0 * FDIM + c + 1] = acc[i][nf][1] + b1;
            }
            if (r0 + 8 < NROI) {
                Co[(size_t)(r0 + 8) * FDIM + c]     = acc[i][nf][2] + b0;
                Co[(size_t)(r0 + 8) * FDIM + c + 1] = acc[i][nf][3] + b1;
            }
        }
    }
}

#define GSMEM1P (3 * 2 * TILE_B)    // 110592
#define GSMEM3P (3 * 4 * TILE_B)    // 221184

// ---------------- BN stats: parallel partial sums + deterministic reduce ----
__global__ __launch_bounds__(256) void bn_partial_kernel(int phase)
{
    const float* X = (phase == 0) ? g_x1 : g_x2;
    int f  = blockIdx.x * 256 + threadIdx.x;
    int rc = blockIdx.y;
    int b  = blockIdx.z;
    const float* p = X + ((size_t)b * 1000 + rc * 125) * FDIM + f;

    float s = 0.f, q = 0.f;
#pragma unroll 5
    for (int n = 0; n < 125; n++) {
        float v = p[(size_t)n * FDIM];
        s += v; q += v * v;
    }
    int idx = (b * 8 + rc) * FDIM + f;
    g_psum[idx] = s;
    g_psq[idx]  = q;
}

__global__ __launch_bounds__(256) void bn_final_kernel(int phase)
{
    float* mu   = (phase == 0) ? g_mu1   : g_mu2;
    float* rstd = (phase == 0) ? g_rstd1 : g_rstd2;
    int f = blockIdx.y * 256 + threadIdx.x;
    int b = blockIdx.x;

    float s = 0.f, q = 0.f;
#pragma unroll
    for (int rc = 0; rc < 8; rc++) {
        int idx = (b * 8 + rc) * FDIM + f;
        s += g_psum[idx];
        q += g_psq[idx];
    }
    float m   = s * (1.0f / 1000.0f);
    float var = q * (1.0f / 1000.0f) - m * m;
    mu[b * FDIM + f]   = m;
    rstd[b * FDIM + f] = rsqrtf(var + 1e-5f);
}

// ---------------- BN1+relu apply -> fp16 hi/lo for GEMM2 ----------------
__global__ __launch_bounds__(256) void bn_apply_kernel(
    const float* __restrict__ gam, const float* __restrict__ bet)
{
    int i = blockIdx.x * 256 + threadIdx.x;
    if (i >= NROI * FDIM / 4) return;
    int e   = i * 4;
    int row = e >> 10;
    int b   = (row >= 1000);
    int kg  = e & 1023;

    float4 v   = *(const float4*)(g_x1 + e);
    float4 g4  = *(const float4*)(gam + kg);
    float4 b4  = *(const float4*)(bet + kg);
    float4 mu4 = *(const float4*)(g_mu1 + b * FDIM + kg);
    float4 rs4 = *(const float4*)(g_rstd1 + b * FDIM + kg);
    float o0 = fmaxf(g4.x * (v.x - mu4.x) * rs4.x + b4.x, 0.f);
    float o1 = fmaxf(g4.y * (v.y - mu4.y) * rs4.y + b4.y, 0.f);
    float o2 = fmaxf(g4.z * (v.z - mu4.z) * rs4.z + b4.z, 0.f);
    float o3 = fmaxf(g4.w * (v.w - mu4.w) * rs4.w + b4.w, 0.f);

    __half h0 = __float2half_rn(o0), h1 = __float2half_rn(o1);
    __half h2 = __float2half_rn(o2), h3 = __float2half_rn(o3);
    __half2* H = (__half2*)g_A2hi;
    __half2* L = (__half2*)g_A2lo;
    H[i*2]   = __half2(h0, h1);
    H[i*2+1] = __half2(h2, h3);
    L[i*2]   = __half2(__float2half_rn(o0 - __half2float(h0)),
                       __float2half_rn(o1 - __half2float(h1)));
    L[i*2+1] = __half2(__float2half_rn(o2 - __half2float(h2)),
                       __float2half_rn(o3 - __half2float(h3)));
}

// ---------------- head: bn2_relu -> logits/bbox GEMV + softmax --------------
#define RPB 8
__global__ __launch_bounds__(256) void head_kernel(
    const float* __restrict__ g2, const float* __restrict__ b2,
    const float* __restrict__ Wl, const float* __restrict__ bl,
    const float* __restrict__ Wb, const float* __restrict__ bb,
    float* __restrict__ out)
{
    __shared__ float sh[RPB][FDIM];
    __shared__ float lg[RPB][NCLS];

    int m0  = blockIdx.x * RPB;
    int tid = threadIdx.x;

    for (int r = 0; r < RPB; r++) {
        int m = m0 + r;
        int b = m / 1000;
        for (int k = tid; k < FDIM; k += 256) {
            float v = g_x2[(size_t)m * FDIM + k];
            v = g2[k] * (v - g_mu2[b * FDIM + k]) * g_rstd2[b * FDIM + k] + b2[k];
            sh[r][k] = fmaxf(v, 0.f);
        }
    }
    __syncthreads();

    for (int o = tid; o < NOUT; o += 256) {
        const float* W; float bias;
        if (o < NCLS) { W = Wl + (size_t)o * FDIM;          bias = bl[o]; }
        else          { W = Wb + (size_t)(o - NCLS) * FDIM; bias = bb[o - NCLS]; }

        float acc[RPB];
#pragma unroll
        for (int r = 0; r < RPB; r++) acc[r] = 0.f;

        for (int k = 0; k < FDIM; k += 4) {
            float4 wv = *(const float4*)(W + k);
#pragma unroll
            for (int r = 0; r < RPB; r++) {
                float4 sv = *(const float4*)&sh[r][k];
                acc[r] += sv.x * wv.x + sv.y * wv.y + sv.z * wv.z + sv.w * wv.w;
            }
        }
#pragma unroll
        for (int r = 0; r < RPB; r++) {
            int m = m0 + r;
            float v = acc[r] + bias;
            if (o < NCLS) {
                lg[r][o] = v;
                out[(size_t)m * NCLS + o] = v;
            } else {
                out[324000 + (size_t)m * NBOX + (o - NCLS)] = v;
            }
        }
    }
    __syncthreads();

    int wid = tid >> 5, lane = tid & 31;
    if (wid < RPB) {
        int m = m0 + wid;
        float mx = -1e30f;
        for (int i = lane; i < NCLS; i += 32) mx = fmaxf(mx, lg[wid][i]);
#pragma unroll
        for (int off = 16; off; off >>= 1) mx = fmaxf(mx, __shfl_xor_sync(0xffffffffu, mx, off));
        float sum = 0.f;
        for (int i = lane; i < NCLS; i += 32) sum += expf(lg[wid][i] - mx);
#pragma unroll
        for (int off = 16; off; off >>= 1) sum += __shfl_xor_sync(0xffffffffu, sum, off);
        float inv = 1.0f / sum;
        for (int i = lane; i < NCLS; i += 32)
            out[162000 + (size_t)m * NCLS + i] = expf(lg[wid][i] - mx) * inv;
    }
}

// ---------------- launch ----------------
extern "C" void kernel_launch(void* const* d_in, const int* in_sizes, int n_in,
                              void* d_out, int out_size)
{
    const float* rois    = (const float*)d_in[0];
    const float* p2      = (const float*)d_in[1];
    const float* p3      = (const float*)d_in[2];
    const float* p4      = (const float*)d_in[3];
    const float* p5      = (const float*)d_in[4];
    const float* conv1_w = (const float*)d_in[5];
    const float* conv1_b = (const float*)d_in[6];
    const float* bn1_g   = (const float*)d_in[7];
    const float* bn1_b   = (const float*)d_in[8];
    const float* conv2_w = (const float*)d_in[9];
    const float* conv2_b = (const float*)d_in[10];
    const float* bn2_g   = (const float*)d_in[11];
    const float* bn2_b   = (const float*)d_in[12];
    const float* logitsW = (const float*)d_in[13];
    const float* logitsB = (const float*)d_in[14];
    const float* bboxW   = (const float*)d_in[15];
    const float* bboxB   = (const float*)d_in[16];
    float* out = (float*)d_out;

    cudaFuncSetAttribute(hmma_gemm<1>, cudaFuncAttributeMaxDynamicSharedMemorySize, GSMEM1P);
    cudaFuncSetAttribute(hmma_gemm<3>, cudaFuncAttributeMaxDynamicSharedMemorySize, GSMEM3P);

    __half *a1h, *b1h, *a2h, *a2l, *b2h, *b2l;
    float *x1, *x2;
    cudaGetSymbolAddress((void**)&a1h, g_A1hi);
    cudaGetSymbolAddress((void**)&b1h, g_B1hi);
    cudaGetSymbolAddress((void**)&a2h, g_A2hi); cudaGetSymbolAddress((void**)&a2l, g_A2lo);
    cudaGetSymbolAddress((void**)&b2h, g_B2hi); cudaGetSymbolAddress((void**)&b2l, g_B2lo);
    cudaGetSymbolAddress((void**)&x1, g_x1);    cudaGetSymbolAddress((void**)&x2, g_x2);

    const int n4_1 = FDIM * KDIM / 4;
    const int n4_2 = FDIM * FDIM / 4;

    roi_align_kernel<<<1000, 256>>>(rois, 0, p2, p3, p4, p5);
    roi_align_kernel<<<1000, 256>>>(rois, 1, p2, p3, p4, p5);
    cvt_hi_kernel<<<(n4_1 + 255) / 256, 256>>>(conv1_w, b1h, 0, n4_1);
    cvt_kernel<<<(n4_2 / 2 + 255) / 256, 256>>>(conv2_w, b2h, b2l, 0, n4_2 / 2);
    cvt_kernel<<<(n4_2 - n4_2 / 2 + 255) / 256, 256>>>(conv2_w, b2h, b2l, n4_2 / 2, n4_2);

    // GEMM1 (fp16 single-pass, BK=64)
    hmma_gemm<1><<<dim3(FDIM / 128, MPAD / 128), 256, GSMEM1P>>>(
        a1h, nullptr, b1h, nullptr, conv1_b, x1, KDIM);

    // BN1
    bn_partial_kernel<<<dim3(4, 8, 2), 256>>>(0);
    bn_final_kernel<<<dim3(2, 4), 256>>>(0);
    bn_apply_kernel<<<(NROI * FDIM / 4 + 255) / 256, 256>>>(bn1_g, bn1_b);

    // GEMM2 (fp16 3-pass, BK=64)
    hmma_gemm<3><<<dim3(FDIM / 128, MPAD / 128), 256, GSMEM3P>>>(
        a2h, a2l, b2h, b2l, conv2_b, x2, FDIM);

    // BN2
    bn_partial_kernel<<<dim3(4, 8, 2), 256>>>(1);
    bn_final_kernel<<<dim3(2, 4), 256>>>(1);

    // head
    head_kernel<<<NROI / RPB, 256>>>(bn2_g, bn2_b, logitsW, logitsB, bboxW, bboxB, out);
}

// round 9
// speedup vs baseline: 3.4462x; 1.0509x over previous
#include <cuda_runtime.h>
#include <cuda_fp16.h>
#include <cstdint>
#include <math.h>

#define NROI   2000
#define MPAD   2048
#define C_IN   256
#define KDIM   12544      // 256*7*7
#define KHALF  6272
#define FDIM   1024
#define NCLS   81
#define NBOX   324
#define NOUT   405

// ---------------- scratch ----------------
__device__ __half g_A1hi[(size_t)MPAD * KDIM];
__device__ __half g_B1hi[(size_t)FDIM * KDIM];
__device__ __half g_A2hi[(size_t)MPAD * FDIM];
__device__ __half g_A2lo[(size_t)MPAD * FDIM];
__device__ __half g_B2hi[(size_t)FDIM * FDIM];
__device__ __half g_B2lo[(size_t)FDIM * FDIM];
__device__ float g_x1[NROI * FDIM];
__device__ float g_x1b[NROI * FDIM];
__device__ float g_x2[NROI * FDIM];
__device__ float g_mu1[2 * FDIM];
__device__ float g_rstd1[2 * FDIM];
__device__ float g_mu2[2 * FDIM];
__device__ float g_rstd2[2 * FDIM];
__device__ float g_psum[16 * FDIM];
__device__ float g_psq[16 * FDIM];

// ---------------- helpers ----------------
__device__ __forceinline__ uint32_t smem_u32(const void* p) {
    uint32_t a;
    asm("{ .reg .u64 t; cvta.to.shared.u64 t, %1; cvt.u32.u64 %0, t; }" : "=r"(a) : "l"(p));
    return a;
}
#define CPA(dst, src) \
    asm volatile("cp.async.cg.shared.global [%0], [%1], 16;" :: "r"(dst), "l"(src))
#define CPA_COMMIT() asm volatile("cp.async.commit_group;" ::: "memory")
#define CPA_WAIT1()  asm volatile("cp.async.wait_group 1;" ::: "memory")
#define CPA_WAIT0()  asm volatile("cp.async.wait_group 0;" ::: "memory")

__device__ __forceinline__ void ldm4(uint32_t* r, uint32_t addr) {
    asm volatile("ldmatrix.sync.aligned.m8n8.x4.shared.b16 {%0,%1,%2,%3}, [%4];"
        : "=r"(r[0]), "=r"(r[1]), "=r"(r[2]), "=r"(r[3]) : "r"(addr));
}
__device__ __forceinline__ void mma16816(float* d, const uint32_t* a, const uint32_t* b) {
    asm volatile("mma.sync.aligned.m16n8k16.row.col.f32.f16.f16.f32 "
        "{%0,%1,%2,%3},{%4,%5,%6,%7},{%8,%9},{%0,%1,%2,%3};"
        : "+f"(d[0]), "+f"(d[1]), "+f"(d[2]), "+f"(d[3])
        : "r"(a[0]), "r"(a[1]), "r"(a[2]), "r"(a[3]), "r"(b[0]), "r"(b[1]));
}

// ---------------- kernel 1: pyramid ROI align -> fp16 (hi only) ------------
__global__ __launch_bounds__(256) void roi_align_kernel(
    const float* __restrict__ rois, int b,
    const float* __restrict__ p2, const float* __restrict__ p3,
    const float* __restrict__ p4, const float* __restrict__ p5)
{
    int roi  = b * 1000 + blockIdx.x;
    int tid  = threadIdx.x;
    int wid  = tid >> 5, lane = tid & 31;

    const float* r = rois + (size_t)roi * 4;
    float y1 = r[0], x1 = r[1], y2 = r[2], x2 = r[3];
    float hh = y2 - y1, ww = x2 - x1;

    float s   = sqrtf(fmaxf(hh * ww, 1e-12f));
    float lvl = log2f(s / 0.21875f);
    int level = 4 + (int)rintf(lvl);
    level = level < 2 ? 2 : (level > 5 ? 5 : level);

    const float* feat; int H;
    if      (level == 2) { feat = p2; H = 256; }
    else if (level == 3) { feat = p3; H = 128; }
    else if (level == 4) { feat = p4; H = 64;  }
    else                 { feat = p5; H = 32;  }
    float Hm1 = (float)(H - 1);

    float wxv[7], wyv[7];
    int xi0v[7], xi1v[7], yi0v[7], yi1v[7];
#pragma unroll
    for (int p = 0; p < 7; p++) {
        float t  = (float)p * (1.0f / 6.0f);
        float xs = (x1 + ww * t) * Hm1;
        float x0 = floorf(xs);
        wxv[p]  = xs - x0;
        int xi = (int)x0;
        xi0v[p] = min(max(xi, 0), H - 1);
        xi1v[p] = min(max(xi + 1, 0), H - 1);
        float ys = (y1 + hh * t) * Hm1;
        float y0 = floorf(ys);
        wyv[p]  = ys - y0;
        int yi = (int)y0;
        yi0v[p] = min(max(yi, 0), H - 1);
        yi1v[p] = min(max(yi + 1, 0), H - 1);
    }

    int xlo  = xi0v[0];
    int span = xi1v[6] - xlo + 1;

    int pxl   = lane < 7 ? lane : 0;
    int s0    = xi0v[pxl] - xlo;
    int s1    = xi1v[pxl] - xlo;
    float wxl = wxv[pxl];

    if (span <= 32) {
        for (int c = wid * 32; c < wid * 32 + 32; c++) {
            const float* plane = feat + (size_t)(b * C_IN + c) * H * H;
            size_t obase = (size_t)roi * KDIM + (size_t)c * 49;
#pragma unroll
            for (int py = 0; py < 7; py++) {
                float v0 = 0.f, v1 = 0.f;
                if (lane < span) {
                    v0 = plane[yi0v[py] * H + xlo + lane];
                    v1 = plane[yi1v[py] * H + xlo + lane];
                }
                float a0 = __shfl_sync(0xffffffffu, v0, s0);
                float a1 = __shfl_sync(0xffffffffu, v0, s1);
                float c0 = __shfl_sync(0xffffffffu, v1, s0);
                float c1 = __shfl_sync(0xffffffffu, v1, s1);
                if (lane < 7) {
                    float wy = wyv[py], wx = wxl;
                    float val = a0 * (1.f - wy) * (1.f - wx)
                              + a1 * (1.f - wy) * wx
                              + c0 * wy * (1.f - wx)
                              + c1 * wy * wx;
                    g_A1hi[obase + py * 7 + lane] = __float2half_rn(val);
                }
            }
        }
    } else {
        for (int c = wid * 32; c < wid * 32 + 32; c++) {
            const float* plane = feat + (size_t)(b * C_IN + c) * H * H;
            size_t obase = (size_t)roi * KDIM + (size_t)c * 49;
            if (lane < 7) {
#pragma unroll
                for (int py = 0; py < 7; py++) {
                    const float* row0 = plane + yi0v[py] * H;
                    const float* row1 = plane + yi1v[py] * H;
                    float wy = wyv[py], wx = wxl;
                    float v00 = row0[xi0v[lane]], v01 = row0[xi1v[lane]];
                    float v10 = row1[xi0v[lane]], v11 = row1[xi1v[lane]];
                    float val = v00 * (1.f - wy) * (1.f - wx)
                              + v01 * (1.f - wy) * wx
                              + v10 * wy * (1.f - wx)
                              + v11 * wy * wx;
                    g_A1hi[obase + py * 7 + lane] = __float2half_rn(val);
                }
            }
        }
    }
}

// ---------------- fp32 -> fp16 hi-only convert ----------------
__global__ __launch_bounds__(256) void cvt_hi_kernel(
    const float* __restrict__ in, __half* __restrict__ hi, int off4, int n4)
{
    int i = off4 + blockIdx.x * 256 + threadIdx.x;
    if (i >= n4) return;
    float4 v = ((const float4*)in)[i];
    __half2* H = (__half2*)hi;
    H[i*2]   = __half2(__float2half_rn(v.x), __float2half_rn(v.y));
    H[i*2+1] = __half2(__float2half_rn(v.z), __float2half_rn(v.w));
}

// ---------------- fp32 -> fp16 hi/lo split ----------------
__global__ __launch_bounds__(256) void cvt_kernel(
    const float* __restrict__ in, __half* __restrict__ hi,
    __half* __restrict__ lo, int off4, int n4)
{
    int i = off4 + blockIdx.x * 256 + threadIdx.x;
    if (i >= n4) return;
    float4 v = ((const float4*)in)[i];
    __half h0 = __float2half_rn(v.x), h1 = __float2half_rn(v.y);
    __half h2 = __float2half_rn(v.z), h3 = __float2half_rn(v.w);
    __half2* H = (__half2*)hi;
    __half2* L = (__half2*)lo;
    H[i*2]   = __half2(h0, h1);
    H[i*2+1] = __half2(h2, h3);
    L[i*2]   = __half2(__float2half_rn(v.x - __half2float(h0)),
                       __float2half_rn(v.y - __half2float(h1)));
    L[i*2+1] = __half2(__float2half_rn(v.z - __half2float(h2)),
                       __float2half_rn(v.w - __half2float(h3)));
}

// ---------------- GEMM common defs ----------------
#define ROWB    144
#define TILE_B  18432           // 128 * 144

// ---------------- GEMM1: split-K x2, single-pass fp16, 2 CTAs/SM -----------
__device__ __forceinline__ void issue_stage2(
    const __half* __restrict__ Ah, const __half* __restrict__ Bh,
    int K, int k0, uint32_t sbase, int tid)
{
    const __half* gs[2] = {Ah, Bh};
#pragma unroll
    for (int t = 0; t < 2; t++) {
#pragma unroll
        for (int i = 0; i < 4; i++) {
            int u   = tid + i * 256;
            int row = u >> 3, seg = u & 7;
            const void* g = gs[t] + (size_t)row * K + k0 + seg * 8;
            uint32_t sm   = sbase + t * TILE_B + row * ROWB + seg * 16;
            CPA(sm, g);
        }
    }
}

__global__ __launch_bounds__(256, 2) void hmma_gemm1(
    const __half* __restrict__ Ahi, const __half* __restrict__ Bhi,
    const float* __restrict__ bias,
    float* __restrict__ CoA, float* __restrict__ CoB)
{
    const int K = KDIM;
    const uint32_t STAGE = 2 * TILE_B;

    extern __shared__ char smem[];
    uint32_t sb = smem_u32(smem);

    int tid  = threadIdx.x;
    int wid  = tid >> 5, lane = tid & 31;
    int wm   = (wid & 3) * 32;
    int wn   = (wid >> 2) * 64;
    int bm   = blockIdx.y * 128;
    int bn   = blockIdx.x * 128;
    int kh   = blockIdx.z;

    const __half* Ah = Ahi + (size_t)bm * K + kh * KHALF;
    const __half* Bh = Bhi + (size_t)bn * K + kh * KHALF;

    uint32_t offA[2], offB[4];
#pragma unroll
    for (int i = 0; i < 2; i++)
        offA[i] = (wm + i * 16 + (lane & 15)) * ROWB + ((lane >> 4) << 4);
#pragma unroll
    for (int j = 0; j < 4; j++)
        offB[j] = (wn + j * 16 + ((lane >> 4) << 3) + (lane & 7)) * ROWB
                + (((lane >> 3) & 1) << 4);

    float acc[2][8][4];
#pragma unroll
    for (int i = 0; i < 2; i++)
#pragma unroll
        for (int n = 0; n < 8; n++)
#pragma unroll
            for (int q = 0; q < 4; q++) acc[i][n][q] = 0.f;

    const int nch = KHALF >> 6;   // 98

    issue_stage2(Ah, Bh, K, 0, sb, tid);
    CPA_COMMIT();
    issue_stage2(Ah, Bh, K, 64, sb + STAGE, tid);
    CPA_COMMIT();

    for (int k = 0; k < nch; k++) {
        if (k == nch - 1) { CPA_WAIT0(); } else { CPA_WAIT1(); }
        __syncthreads();

        if (k + 2 < nch) {
            issue_stage2(Ah, Bh, K, (k + 2) << 6,
                         sb + ((k + 2) % 3) * STAGE, tid);
            CPA_COMMIT();
        }

        uint32_t stb = sb + (k % 3) * STAGE;
#pragma unroll
        for (int s = 0; s < 4; s++) {
            uint32_t so = s * 32;
            uint32_t ah[2][4], bh[4][4];
#pragma unroll
            for (int i = 0; i < 2; i++)
                ldm4(ah[i], stb + 0 * TILE_B + offA[i] + so);
#pragma unroll
            for (int j = 0; j < 4; j++)
                ldm4(bh[j], stb + 1 * TILE_B + offB[j] + so);
#pragma unroll
            for (int i = 0; i < 2; i++)
#pragma unroll
                for (int nf = 0; nf < 8; nf++)
                    mma16816(acc[i][nf], ah[i], &bh[nf >> 1][(nf & 1) * 2]);
        }
    }

    float* Co = kh ? CoB : CoA;
#pragma unroll
    for (int i = 0; i < 2; i++) {
        int r0 = bm + wm + i * 16 + (lane >> 2);
#pragma unroll
        for (int nf = 0; nf < 8; nf++) {
            int c = bn + wn + nf * 8 + (lane & 3) * 2;
            float b0 = kh ? 0.f : bias[c];
            float b1 = kh ? 0.f : bias[c + 1];
            if (r0 < NROI) {
                Co[(size_t)r0 * FDIM + c]     = acc[i][nf][0] + b0;
                Co[(size_t)r0 * FDIM + c + 1] = acc[i][nf][1] + b1;
            }
            if (r0 + 8 < NROI) {
                Co[(size_t)(r0 + 8) * FDIM + c]     = acc[i][nf][2] + b0;
                Co[(size_t)(r0 + 8) * FDIM + c + 1] = acc[i][nf][3] + b1;
            }
        }
    }
}
#define GSMEM1 (3 * 2 * TILE_B)    // 110592

// ---------------- GEMM2: 3-pass fp16 (Ah*Bh + Al*Bh + Ah*Bl) ----------------
__device__ __forceinline__ void issue_stage4(
    const __half* __restrict__ Ah, const __half* __restrict__ Bh,
    const __half* __restrict__ Al, const __half* __restrict__ Bl,
    int K, int k0, uint32_t sbase, int tid)
{
    const __half* gs[4] = {Ah, Bh, Al, Bl};
#pragma unroll
    for (int t = 0; t < 4; t++) {
#pragma unroll
        for (int i = 0; i < 4; i++) {
            int u   = tid + i * 256;
            int row = u >> 3, seg = u & 7;
            const void* g = gs[t] + (size_t)row * K + k0 + seg * 8;
            uint32_t sm   = sbase + t * TILE_B + row * ROWB + seg * 16;
            CPA(sm, g);
        }
    }
}

__global__ __launch_bounds__(256, 1) void hmma_gemm3(
    const __half* __restrict__ Ahi, const __half* __restrict__ Alo,
    const __half* __restrict__ Bhi, const __half* __restrict__ Blo,
    const float* __restrict__ bias, float* __restrict__ Co, int K)
{
    const uint32_t STAGE = 4 * TILE_B;

    extern __shared__ char smem[];
    uint32_t sb = smem_u32(smem);

    int tid  = threadIdx.x;
    int wid  = tid >> 5, lane = tid & 31;
    int wm   = (wid & 3) * 32;
    int wn   = (wid >> 2) * 64;
    int bm   = blockIdx.y * 128;
    int bn   = blockIdx.x * 128;

    const __half* Ah = Ahi + (size_t)bm * K;
    const __half* Al = Alo + (size_t)bm * K;
    const __half* Bh = Bhi + (size_t)bn * K;
    const __half* Bl = Blo + (size_t)bn * K;

    uint32_t offA[2], offB[4];
#pragma unroll
    for (int i = 0; i < 2; i++)
        offA[i] = (wm + i * 16 + (lane & 15)) * ROWB + ((lane >> 4) << 4);
#pragma unroll
    for (int j = 0; j < 4; j++)
        offB[j] = (wn + j * 16 + ((lane >> 4) << 3) + (lane & 7)) * ROWB
                + (((lane >> 3) & 1) << 4);

    float acc[2][8][4];
#pragma unroll
    for (int i = 0; i < 2; i++)
#pragma unroll
        for (int n = 0; n < 8; n++)
#pragma unroll
            for (int q = 0; q < 4; q++) acc[i][n][q] = 0.f;

    int nch = K >> 6;

    issue_stage4(Ah, Bh, Al, Bl, K, 0, sb, tid);
    CPA_COMMIT();
    if (nch > 1) {
        issue_stage4(Ah, Bh, Al, Bl, K, 64, sb + STAGE, tid);
        CPA_COMMIT();
    }

    for (int k = 0; k < nch; k++) {
        if (k == nch - 1) { CPA_WAIT0(); } else { CPA_WAIT1(); }
        __syncthreads();

        if (k + 2 < nch) {
            issue_stage4(Ah, Bh, Al, Bl, K, (k + 2) << 6,
                         sb + ((k + 2) % 3) * STAGE, tid);
            CPA_COMMIT();
        }

        uint32_t stb = sb + (k % 3) * STAGE;
#pragma unroll
        for (int s = 0; s < 4; s++) {
            uint32_t so = s * 32;
            uint32_t ah[2][4], al[2][4], bh[4][4], bl[4][4];
#pragma unroll
            for (int i = 0; i < 2; i++) {
                ldm4(ah[i], stb + 0 * TILE_B + offA[i] + so);
                ldm4(al[i], stb + 2 * TILE_B + offA[i] + so);
            }
#pragma unroll
            for (int j = 0; j < 4; j++) {
                ldm4(bh[j], stb + 1 * TILE_B + offB[j] + so);
                ldm4(bl[j], stb + 3 * TILE_B + offB[j] + so);
            }
#pragma unroll
            for (int i = 0; i < 2; i++) {
#pragma unroll
                for (int nf = 0; nf < 8; nf++) {
                    const uint32_t* bph = &bh[nf >> 1][(nf & 1) * 2];
                    const uint32_t* bpl = &bl[nf >> 1][(nf & 1) * 2];
                    mma16816(acc[i][nf], ah[i], bph);
                    mma16816(acc[i][nf], al[i], bph);
                    mma16816(acc[i][nf], ah[i], bpl);
                }
            }
        }
    }

#pragma unroll
    for (int i = 0; i < 2; i++) {
        int r0 = bm + wm + i * 16 + (lane >> 2);
#pragma unroll
        for (int nf = 0; nf < 8; nf++) {
            int c = bn + wn + nf * 8 + (lane & 3) * 2;
            float b0 = bias[c], b1 = bias[c + 1];
            if (r0 < NROI) {
                Co[(size_t)r0 * FDIM + c]     = acc[i][nf][0] + b0;
                Co[(size_t)r0 * FDIM + c + 1] = acc[i][nf][1] + b1;
            }
            if (r0 + 8 < NROI) {
                Co[(size_t)(r0 + 8) * FDIM + c]     = acc[i][nf][2] + b0;
                Co[(size_t)(r0 + 8) * FDIM + c + 1] = acc[i][nf][3] + b1;
            }
        }
    }
}
#define GSMEM3 (3 * 4 * TILE_B)    // 221184

// ---------------- BN stats ----------------
// phase 0 sums split-K partials (x1 + x1b); phase 1 reads x2.
__global__ __launch_bounds__(256) void bn_partial_kernel(int phase)
{
    int f  = blockIdx.x * 256 + threadIdx.x;
    int rc = blockIdx.y;
    int b  = blockIdx.z;
    size_t base = ((size_t)b * 1000 + rc * 125) * FDIM + f;

    float s = 0.f, q = 0.f;
    if (phase == 0) {
        const float* pa = g_x1 + base;
        const float* pb = g_x1b + base;
#pragma unroll 5
        for (int n = 0; n < 125; n++) {
            float v = pa[(size_t)n * FDIM] + pb[(size_t)n * FDIM];
            s += v; q += v * v;
        }
    } else {
        const float* p = g_x2 + base;
#pragma unroll 5
        for (int n = 0; n < 125; n++) {
            float v = p[(size_t)n * FDIM];
            s += v; q += v * v;
        }
    }
    int idx = (b * 8 + rc) * FDIM + f;
    g_psum[idx] = s;
    g_psq[idx]  = q;
}

__global__ __launch_bounds__(256) void bn_final_kernel(int phase)
{
    float* mu   = (phase == 0) ? g_mu1   : g_mu2;
    float* rstd = (phase == 0) ? g_rstd1 : g_rstd2;
    int f = blockIdx.y * 256 + threadIdx.x;
    int b = blockIdx.x;

    float s = 0.f, q = 0.f;
#pragma unroll
    for (int rc = 0; rc < 8; rc++) {
        int idx = (b * 8 + rc) * FDIM + f;
        s += g_psum[idx];
        q += g_psq[idx];
    }
    float m   = s * (1.0f / 1000.0f);
    float var = q * (1.0f / 1000.0f) - m * m;
    mu[b * FDIM + f]   = m;
    rstd[b * FDIM + f] = rsqrtf(var + 1e-5f);
}

// ---------------- BN1+relu apply (x1 + x1b) -> fp16 hi/lo for GEMM2 --------
__global__ __launch_bounds__(256) void bn_apply_kernel(
    const float* __restrict__ gam, const float* __restrict__ bet)
{
    int i = blockIdx.x * 256 + threadIdx.x;
    if (i >= NROI * FDIM / 4) return;
    int e   = i * 4;
    int row = e >> 10;
    int b   = (row >= 1000);
    int kg  = e & 1023;

    float4 va  = *(const float4*)(g_x1 + e);
    float4 vb  = *(const float4*)(g_x1b + e);
    float4 g4  = *(const float4*)(gam + kg);
    float4 b4  = *(const float4*)(bet + kg);
    float4 mu4 = *(const float4*)(g_mu1 + b * FDIM + kg);
    float4 rs4 = *(const float4*)(g_rstd1 + b * FDIM + kg);
    float v0 = va.x + vb.x, v1 = va.y + vb.y, v2 = va.z + vb.z, v3 = va.w + vb.w;
    float o0 = fmaxf(g4.x * (v0 - mu4.x) * rs4.x + b4.x, 0.f);
    float o1 = fmaxf(g4.y * (v1 - mu4.y) * rs4.y + b4.y, 0.f);
    float o2 = fmaxf(g4.z * (v2 - mu4.z) * rs4.z + b4.z, 0.f);
    float o3 = fmaxf(g4.w * (v3 - mu4.w) * rs4.w + b4.w, 0.f);

    __half h0 = __float2half_rn(o0), h1 = __float2half_rn(o1);
    __half h2 = __float2half_rn(o2), h3 = __float2half_rn(o3);
    __half2* H = (__half2*)g_A2hi;
    __half2* L = (__half2*)g_A2lo;
    H[i*2]   = __half2(h0, h1);
    H[i*2+1] = __half2(h2, h3);
    L[i*2]   = __half2(__float2half_rn(o0 - __half2float(h0)),
                       __float2half_rn(o1 - __half2float(h1)));
    L[i*2+1] = __half2(__float2half_rn(o2 - __half2float(h2)),
                       __float2half_rn(o3 - __half2float(h3)));
}

// ---------------- head ----------------
#define RPB 8
__global__ __launch_bounds__(256) void head_kernel(
    const float* __restrict__ g2, const float* __restrict__ b2,
    const float* __restrict__ Wl, const float* __restrict__ bl,
    const float* __restrict__ Wb, const float* __restrict__ bb,
    float* __restrict__ out)
{
    __shared__ float sh[RPB][FDIM];
    __shared__ float lg[RPB][NCLS];

    int m0  = blockIdx.x * RPB;
    int tid = threadIdx.x;

    for (int r = 0; r < RPB; r++) {
        int m = m0 + r;
        int b = m / 1000;
        for (int k = tid; k < FDIM; k += 256) {
            float v = g_x2[(size_t)m * FDIM + k];
            v = g2[k] * (v - g_mu2[b * FDIM + k]) * g_rstd2[b * FDIM + k] + b2[k];
            sh[r][k] = fmaxf(v, 0.f);
        }
    }
    __syncthreads();

    for (int o = tid; o < NOUT; o += 256) {
        const float* W; float bias;
        if (o < NCLS) { W = Wl + (size_t)o * FDIM;          bias = bl[o]; }
        else          { W = Wb + (size_t)(o - NCLS) * FDIM; bias = bb[o - NCLS]; }

        float acc[RPB];
#pragma unroll
        for (int r = 0; r < RPB; r++) acc[r] = 0.f;

        for (int k = 0; k < FDIM; k += 4) {
            float4 wv = *(const float4*)(W + k);
#pragma unroll
            for (int r = 0; r < RPB; r++) {
                float4 sv = *(const float4*)&sh[r][k];
                acc[r] += sv.x * wv.x + sv.y * wv.y + sv.z * wv.z + sv.w * wv.w;
            }
        }
#pragma unroll
        for (int r = 0; r < RPB; r++) {
            int m = m0 + r;
            float v = acc[r] + bias;
            if (o < NCLS) {
                lg[r][o] = v;
                out[(size_t)m * NCLS + o] = v;
            } else {
                out[324000 + (size_t)m * NBOX + (o - NCLS)] = v;
            }
        }
    }
    __syncthreads();

    int wid = tid >> 5, lane = tid & 31;
    if (wid < RPB) {
        int m = m0 + wid;
        float mx = -1e30f;
        for (int i = lane; i < NCLS; i += 32) mx = fmaxf(mx, lg[wid][i]);
#pragma unroll
        for (int off = 16; off; off >>= 1) mx = fmaxf(mx, __shfl_xor_sync(0xffffffffu, mx, off));
        float sum = 0.f;
        for (int i = lane; i < NCLS; i += 32) sum += expf(lg[wid][i] - mx);
#pragma unroll
        for (int off = 16; off; off >>= 1) sum += __shfl_xor_sync(0xffffffffu, sum, off);
        float inv = 1.0f / sum;
        for (int i = lane; i < NCLS; i += 32)
            out[162000 + (size_t)m * NCLS + i] = expf(lg[wid][i] - mx) * inv;
    }
}

// ---------------- launch ----------------
extern "C" void kernel_launch(void* const* d_in, const int* in_sizes, int n_in,
                              void* d_out, int out_size)
{
    const float* rois    = (const float*)d_in[0];
    const float* p2      = (const float*)d_in[1];
    const float* p3      = (const float*)d_in[2];
    const float* p4      = (const float*)d_in[3];
    const float* p5      = (const float*)d_in[4];
    const float* conv1_w = (const float*)d_in[5];
    const float* conv1_b = (const float*)d_in[6];
    const float* bn1_g   = (const float*)d_in[7];
    const float* bn1_b   = (const float*)d_in[8];
    const float* conv2_w = (const float*)d_in[9];
    const float* conv2_b = (const float*)d_in[10];
    const float* bn2_g   = (const float*)d_in[11];
    const float* bn2_b   = (const float*)d_in[12];
    const float* logitsW = (const float*)d_in[13];
    const float* logitsB = (const float*)d_in[14];
    const float* bboxW   = (const float*)d_in[15];
    const float* bboxB   = (const float*)d_in[16];
    float* out = (float*)d_out;

    cudaFuncSetAttribute(hmma_gemm1, cudaFuncAttributeMaxDynamicSharedMemorySize, GSMEM1);
    cudaFuncSetAttribute(hmma_gemm3, cudaFuncAttributeMaxDynamicSharedMemorySize, GSMEM3);

    __half *a1h, *b1h, *a2h, *a2l, *b2h, *b2l;
    float *x1, *x1b, *x2;
    cudaGetSymbolAddress((void**)&a1h, g_A1hi);
    cudaGetSymbolAddress((void**)&b1h, g_B1hi);
    cudaGetSymbolAddress((void**)&a2h, g_A2hi); cudaGetSymbolAddress((void**)&a2l, g_A2lo);
    cudaGetSymbolAddress((void**)&b2h, g_B2hi); cudaGetSymbolAddress((void**)&b2l, g_B2lo);
    cudaGetSymbolAddress((void**)&x1, g_x1);    cudaGetSymbolAddress((void**)&x1b, g_x1b);
    cudaGetSymbolAddress((void**)&x2, g_x2);

    const int n4_1 = FDIM * KDIM / 4;
    const int n4_2 = FDIM * FDIM / 4;

    // launches 1-3
    roi_align_kernel<<<1000, 256>>>(rois, 0, p2, p3, p4, p5);
    roi_align_kernel<<<1000, 256>>>(rois, 1, p2, p3, p4, p5);
    cvt_hi_kernel<<<(n4_1 + 255) / 256, 256>>>(conv1_w, b1h, 0, n4_1);

    // launch 4: GEMM1 (split-K x2, 2 CTAs/SM) — ncu capture slot
    hmma_gemm1<<<dim3(FDIM / 128, MPAD / 128, 2), 256, GSMEM1>>>(
        a1h, b1h, conv1_b, x1, x1b);

    // BN1 (sums split-K partials)
    bn_partial_kernel<<<dim3(4, 8, 2), 256>>>(0);
    bn_final_kernel<<<dim3(2, 4), 256>>>(0);
    bn_apply_kernel<<<(NROI * FDIM / 4 + 255) / 256, 256>>>(bn1_g, bn1_b);

    // conv2 weights split
    cvt_kernel<<<(n4_2 + 255) / 256, 256>>>(conv2_w, b2h, b2l, 0, n4_2);

    // GEMM2 (fp16 3-pass)
    hmma_gemm3<<<dim3(FDIM / 128, MPAD / 128), 256, GSMEM3>>>(
        a2h, a2l, b2h, b2l, conv2_b, x2, FDIM);

    // BN2
    bn_partial_kernel<<<dim3(4, 8, 2), 256>>>(1);
    bn_final_kernel<<<dim3(2, 4), 256>>>(1);

    // head
    head_kernel<<<NROI / RPB, 256>>>(bn2_g, bn2_b, logitsW, logitsB, bboxW, bboxB, out);
}

// round 10
// speedup vs baseline: 3.5175x; 1.0207x over previous
#include <cuda_runtime.h>
#include <cuda_fp16.h>
#include <cstdint>
#include <math.h>

#define NROI   2000
#define MPAD   2048
#define C_IN   256
#define KDIM   12544      // 256*7*7
#define KHALF  6272
#define FDIM   1024
#define NCLS   81
#define NBOX   324
#define NOUT   405

// ---------------- scratch ----------------
__device__ __half g_A1hi[(size_t)MPAD * KDIM];
__device__ __half g_B1hi[(size_t)FDIM * KDIM];
__device__ __half g_A2hi[(size_t)MPAD * FDIM];
__device__ __half g_A2lo[(size_t)MPAD * FDIM];
__device__ __half g_B2hi[(size_t)FDIM * FDIM];
__device__ __half g_B2lo[(size_t)FDIM * FDIM];   // kept (cvt writes it) but unused by 2-pass GEMM2
__device__ float g_x1[NROI * FDIM];
__device__ float g_x1b[NROI * FDIM];
__device__ float g_x2[NROI * FDIM];
__device__ float g_x2b[NROI * FDIM];
__device__ float g_mu1[2 * FDIM];
__device__ float g_rstd1[2 * FDIM];
__device__ float g_mu2[2 * FDIM];
__device__ float g_rstd2[2 * FDIM];
__device__ float g_psum[16 * FDIM];
__device__ float g_psq[16 * FDIM];

// ---------------- helpers ----------------
__device__ __forceinline__ uint32_t smem_u32(const void* p) {
    uint32_t a;
    asm("{ .reg .u64 t; cvta.to.shared.u64 t, %1; cvt.u32.u64 %0, t; }" : "=r"(a) : "l"(p));
    return a;
}
#define CPA(dst, src) \
    asm volatile("cp.async.cg.shared.global [%0], [%1], 16;" :: "r"(dst), "l"(src))
#define CPA_COMMIT() asm volatile("cp.async.commit_group;" ::: "memory")
#define CPA_WAIT1()  asm volatile("cp.async.wait_group 1;" ::: "memory")
#define CPA_WAIT0()  asm volatile("cp.async.wait_group 0;" ::: "memory")

__device__ __forceinline__ void ldm4(uint32_t* r, uint32_t addr) {
    asm volatile("ldmatrix.sync.aligned.m8n8.x4.shared.b16 {%0,%1,%2,%3}, [%4];"
        : "=r"(r[0]), "=r"(r[1]), "=r"(r[2]), "=r"(r[3]) : "r"(addr));
}
__device__ __forceinline__ void mma16816(float* d, const uint32_t* a, const uint32_t* b) {
    asm volatile("mma.sync.aligned.m16n8k16.row.col.f32.f16.f16.f32 "
        "{%0,%1,%2,%3},{%4,%5,%6,%7},{%8,%9},{%0,%1,%2,%3};"
        : "+f"(d[0]), "+f"(d[1]), "+f"(d[2]), "+f"(d[3])
        : "r"(a[0]), "r"(a[1]), "r"(a[2]), "r"(a[3]), "r"(b[0]), "r"(b[1]));
}

// ---------------- kernel 1: pyramid ROI align -> fp16 (hi only) ------------
__global__ __launch_bounds__(256) void roi_align_kernel(
    const float* __restrict__ rois, int b,
    const float* __restrict__ p2, const float* __restrict__ p3,
    const float* __restrict__ p4, const float* __restrict__ p5)
{
    int roi  = b * 1000 + blockIdx.x;
    int tid  = threadIdx.x;
    int wid  = tid >> 5, lane = tid & 31;

    const float* r = rois + (size_t)roi * 4;
    float y1 = r[0], x1 = r[1], y2 = r[2], x2 = r[3];
    float hh = y2 - y1, ww = x2 - x1;

    float s   = sqrtf(fmaxf(hh * ww, 1e-12f));
    float lvl = log2f(s / 0.21875f);
    int level = 4 + (int)rintf(lvl);
    level = level < 2 ? 2 : (level > 5 ? 5 : level);

    const float* feat; int H;
    if      (level == 2) { feat = p2; H = 256; }
    else if (level == 3) { feat = p3; H = 128; }
    else if (level == 4) { feat = p4; H = 64;  }
    else                 { feat = p5; H = 32;  }
    float Hm1 = (float)(H - 1);

    float wxv[7], wyv[7];
    int xi0v[7], xi1v[7], yi0v[7], yi1v[7];
#pragma unroll
    for (int p = 0; p < 7; p++) {
        float t  = (float)p * (1.0f / 6.0f);
        float xs = (x1 + ww * t) * Hm1;
        float x0 = floorf(xs);
        wxv[p]  = xs - x0;
        int xi = (int)x0;
        xi0v[p] = min(max(xi, 0), H - 1);
        xi1v[p] = min(max(xi + 1, 0), H - 1);
        float ys = (y1 + hh * t) * Hm1;
        float y0 = floorf(ys);
        wyv[p]  = ys - y0;
        int yi = (int)y0;
        yi0v[p] = min(max(yi, 0), H - 1);
        yi1v[p] = min(max(yi + 1, 0), H - 1);
    }

    int xlo  = xi0v[0];
    int span = xi1v[6] - xlo + 1;

    int pxl   = lane < 7 ? lane : 0;
    int s0    = xi0v[pxl] - xlo;
    int s1    = xi1v[pxl] - xlo;
    float wxl = wxv[pxl];

    if (span <= 32) {
        for (int c = wid * 32; c < wid * 32 + 32; c++) {
            const float* plane = feat + (size_t)(b * C_IN + c) * H * H;
            size_t obase = (size_t)roi * KDIM + (size_t)c * 49;
#pragma unroll
            for (int py = 0; py < 7; py++) {
                float v0 = 0.f, v1 = 0.f;
                if (lane < span) {
                    v0 = plane[yi0v[py] * H + xlo + lane];
                    v1 = plane[yi1v[py] * H + xlo + lane];
                }
                float a0 = __shfl_sync(0xffffffffu, v0, s0);
                float a1 = __shfl_sync(0xffffffffu, v0, s1);
                float c0 = __shfl_sync(0xffffffffu, v1, s0);
                float c1 = __shfl_sync(0xffffffffu, v1, s1);
                if (lane < 7) {
                    float wy = wyv[py], wx = wxl;
                    float val = a0 * (1.f - wy) * (1.f - wx)
                              + a1 * (1.f - wy) * wx
                              + c0 * wy * (1.f - wx)
                              + c1 * wy * wx;
                    g_A1hi[obase + py * 7 + lane] = __float2half_rn(val);
                }
            }
        }
    } else {
        for (int c = wid * 32; c < wid * 32 + 32; c++) {
            const float* plane = feat + (size_t)(b * C_IN + c) * H * H;
            size_t obase = (size_t)roi * KDIM + (size_t)c * 49;
            if (lane < 7) {
#pragma unroll
                for (int py = 0; py < 7; py++) {
                    const float* row0 = plane + yi0v[py] * H;
                    const float* row1 = plane + yi1v[py] * H;
                    float wy = wyv[py], wx = wxl;
                    float v00 = row0[xi0v[lane]], v01 = row0[xi1v[lane]];
                    float v10 = row1[xi0v[lane]], v11 = row1[xi1v[lane]];
                    float val = v00 * (1.f - wy) * (1.f - wx)
                              + v01 * (1.f - wy) * wx
                              + v10 * wy * (1.f - wx)
                              + v11 * wy * wx;
                    g_A1hi[obase + py * 7 + lane] = __float2half_rn(val);
                }
            }
        }
    }
}

// ---------------- fp32 -> fp16 hi-only convert ----------------
__global__ __launch_bounds__(256) void cvt_hi_kernel(
    const float* __restrict__ in, __half* __restrict__ hi, int off4, int n4)
{
    int i = off4 + blockIdx.x * 256 + threadIdx.x;
    if (i >= n4) return;
    float4 v = ((const float4*)in)[i];
    __half2* H = (__half2*)hi;
    H[i*2]   = __half2(__float2half_rn(v.x), __float2half_rn(v.y));
    H[i*2+1] = __half2(__float2half_rn(v.z), __float2half_rn(v.w));
}

// ---------------- fp32 -> fp16 hi/lo split ----------------
__global__ __launch_bounds__(256) void cvt_kernel(
    const float* __restrict__ in, __half* __restrict__ hi,
    __half* __restrict__ lo, int off4, int n4)
{
    int i = off4 + blockIdx.x * 256 + threadIdx.x;
    if (i >= n4) return;
    float4 v = ((const float4*)in)[i];
    __half h0 = __float2half_rn(v.x), h1 = __float2half_rn(v.y);
    __half h2 = __float2half_rn(v.z), h3 = __float2half_rn(v.w);
    __half2* H = (__half2*)hi;
    __half2* L = (__half2*)lo;
    H[i*2]   = __half2(h0, h1);
    H[i*2+1] = __half2(h2, h3);
    L[i*2]   = __half2(__float2half_rn(v.x - __half2float(h0)),
                       __float2half_rn(v.y - __half2float(h1)));
    L[i*2+1] = __half2(__float2half_rn(v.z - __half2float(h2)),
                       __float2half_rn(v.w - __half2float(h3)));
}

// ---------------- GEMM1: split-K x2, single-pass fp16, 2 CTAs/SM -----------
#define ROWB    144
#define TILE_B  18432           // 128 * 144 (BK=64)

__device__ __forceinline__ void issue_stage2(
    const __half* __restrict__ Ah, const __half* __restrict__ Bh,
    int K, int k0, uint32_t sbase, int tid)
{
    const __half* gs[2] = {Ah, Bh};
#pragma unroll
    for (int t = 0; t < 2; t++) {
#pragma unroll
        for (int i = 0; i < 4; i++) {
            int u   = tid + i * 256;
            int row = u >> 3, seg = u & 7;
            const void* g = gs[t] + (size_t)row * K + k0 + seg * 8;
            uint32_t sm   = sbase + t * TILE_B + row * ROWB + seg * 16;
            CPA(sm, g);
        }
    }
}

__global__ __launch_bounds__(256, 2) void hmma_gemm1(
    const __half* __restrict__ Ahi, const __half* __restrict__ Bhi,
    const float* __restrict__ bias,
    float* __restrict__ CoA, float* __restrict__ CoB)
{
    const int K = KDIM;
    const uint32_t STAGE = 2 * TILE_B;

    extern __shared__ char smem[];
    uint32_t sb = smem_u32(smem);

    int tid  = threadIdx.x;
    int wid  = tid >> 5, lane = tid & 31;
    int wm   = (wid & 3) * 32;
    int wn   = (wid >> 2) * 64;
    int bm   = blockIdx.y * 128;
    int bn   = blockIdx.x * 128;
    int kh   = blockIdx.z;

    const __half* Ah = Ahi + (size_t)bm * K + kh * KHALF;
    const __half* Bh = Bhi + (size_t)bn * K + kh * KHALF;

    uint32_t offA[2], offB[4];
#pragma unroll
    for (int i = 0; i < 2; i++)
        offA[i] = (wm + i * 16 + (lane & 15)) * ROWB + ((lane >> 4) << 4);
#pragma unroll
    for (int j = 0; j < 4; j++)
        offB[j] = (wn + j * 16 + ((lane >> 4) << 3) + (lane & 7)) * ROWB
                + (((lane >> 3) & 1) << 4);

    float acc[2][8][4];
#pragma unroll
    for (int i = 0; i < 2; i++)
#pragma unroll
        for (int n = 0; n < 8; n++)
#pragma unroll
            for (int q = 0; q < 4; q++) acc[i][n][q] = 0.f;

    const int nch = KHALF >> 6;   // 98

    issue_stage2(Ah, Bh, K, 0, sb, tid);
    CPA_COMMIT();
    issue_stage2(Ah, Bh, K, 64, sb + STAGE, tid);
    CPA_COMMIT();

    for (int k = 0; k < nch; k++) {
        if (k == nch - 1) { CPA_WAIT0(); } else { CPA_WAIT1(); }
        __syncthreads();

        if (k + 2 < nch) {
            issue_stage2(Ah, Bh, K, (k + 2) << 6,
                         sb + ((k + 2) % 3) * STAGE, tid);
            CPA_COMMIT();
        }

        uint32_t stb = sb + (k % 3) * STAGE;
#pragma unroll
        for (int s = 0; s < 4; s++) {
            uint32_t so = s * 32;
            uint32_t ah[2][4], bh[4][4];
#pragma unroll
            for (int i = 0; i < 2; i++)
                ldm4(ah[i], stb + 0 * TILE_B + offA[i] + so);
#pragma unroll
            for (int j = 0; j < 4; j++)
                ldm4(bh[j], stb + 1 * TILE_B + offB[j] + so);
#pragma unroll
            for (int i = 0; i < 2; i++)
#pragma unroll
                for (int nf = 0; nf < 8; nf++)
                    mma16816(acc[i][nf], ah[i], &bh[nf >> 1][(nf & 1) * 2]);
        }
    }

    float* Co = kh ? CoB : CoA;
#pragma unroll
    for (int i = 0; i < 2; i++) {
        int r0 = bm + wm + i * 16 + (lane >> 2);
#pragma unroll
        for (int nf = 0; nf < 8; nf++) {
            int c = bn + wn + nf * 8 + (lane & 3) * 2;
            float b0 = kh ? 0.f : bias[c];
            float b1 = kh ? 0.f : bias[c + 1];
            if (r0 < NROI) {
                Co[(size_t)r0 * FDIM + c]     = acc[i][nf][0] + b0;
                Co[(size_t)r0 * FDIM + c + 1] = acc[i][nf][1] + b1;
            }
            if (r0 + 8 < NROI) {
                Co[(size_t)(r0 + 8) * FDIM + c]     = acc[i][nf][2] + b0;
                Co[(size_t)(r0 + 8) * FDIM + c + 1] = acc[i][nf][3] + b1;
            }
        }
    }
}
#define GSMEM1 (3 * 2 * TILE_B)    // 110592

// ---------------- GEMM2: split-K x2, 2-pass fp16 (Ah*Bh + Al*Bh), BK=32 ----
// 3 tiles/stage (Ah, Bh, Al) x 10240B, 3 stages = 92160B -> 2 CTAs/SM.
#define ROWB2   80
#define TILE2_B 10240           // 128 * 80 (BK=32)

__device__ __forceinline__ void issue_stage3(
    const __half* __restrict__ Ah, const __half* __restrict__ Bh,
    const __half* __restrict__ Al, int K, int k0, uint32_t sbase, int tid)
{
    const __half* gs[3] = {Ah, Bh, Al};
#pragma unroll
    for (int t = 0; t < 3; t++) {
#pragma unroll
        for (int i = 0; i < 2; i++) {
            int u   = tid + i * 256;
            int row = u >> 2, seg = u & 3;
            const void* g = gs[t] + (size_t)row * K + k0 + seg * 8;
            uint32_t sm   = sbase + t * TILE2_B + row * ROWB2 + seg * 16;
            CPA(sm, g);
        }
    }
}

__global__ __launch_bounds__(256, 2) void hmma_gemm2(
    const __half* __restrict__ Ahi, const __half* __restrict__ Alo,
    const __half* __restrict__ Bhi, const float* __restrict__ bias,
    float* __restrict__ CoA, float* __restrict__ CoB)
{
    const int K = FDIM;
    const uint32_t STAGE = 3 * TILE2_B;

    extern __shared__ char smem[];
    uint32_t sb = smem_u32(smem);

    int tid  = threadIdx.x;
    int wid  = tid >> 5, lane = tid & 31;
    int wm   = (wid & 3) * 32;
    int wn   = (wid >> 2) * 64;
    int bm   = blockIdx.y * 128;
    int bn   = blockIdx.x * 128;
    int kh   = blockIdx.z;

    const __half* Ah = Ahi + (size_t)bm * K + kh * (FDIM / 2);
    const __half* Al = Alo + (size_t)bm * K + kh * (FDIM / 2);
    const __half* Bh = Bhi + (size_t)bn * K + kh * (FDIM / 2);

    uint32_t offA[2], offB[4];
#pragma unroll
    for (int i = 0; i < 2; i++)
        offA[i] = (wm + i * 16 + (lane & 15)) * ROWB2 + ((lane >> 4) << 4);
#pragma unroll
    for (int j = 0; j < 4; j++)
        offB[j] = (wn + j * 16 + ((lane >> 4) << 3) + (lane & 7)) * ROWB2
                + (((lane >> 3) & 1) << 4);

    float acc[2][8][4];
#pragma unroll
    for (int i = 0; i < 2; i++)
#pragma unroll
        for (int n = 0; n < 8; n++)
#pragma unroll
            for (int q = 0; q < 4; q++) acc[i][n][q] = 0.f;

    const int nch = (FDIM / 2) >> 5;   // 16

    issue_stage3(Ah, Bh, Al, K, 0, sb, tid);
    CPA_COMMIT();
    issue_stage3(Ah, Bh, Al, K, 32, sb + STAGE, tid);
    CPA_COMMIT();

    for (int k = 0; k < nch; k++) {
        if (k == nch - 1) { CPA_WAIT0(); } else { CPA_WAIT1(); }
        __syncthreads();

        if (k + 2 < nch) {
            issue_stage3(Ah, Bh, Al, K, (k + 2) << 5,
                         sb + ((k + 2) % 3) * STAGE, tid);
            CPA_COMMIT();
        }

        uint32_t stb = sb + (k % 3) * STAGE;
#pragma unroll
        for (int s = 0; s < 2; s++) {
            uint32_t so = s * 32;
            uint32_t ah[2][4], al[2][4], bh[4][4];
#pragma unroll
            for (int i = 0; i < 2; i++) {
                ldm4(ah[i], stb + 0 * TILE2_B + offA[i] + so);
                ldm4(al[i], stb + 2 * TILE2_B + offA[i] + so);
            }
#pragma unroll
            for (int j = 0; j < 4; j++)
                ldm4(bh[j], stb + 1 * TILE2_B + offB[j] + so);
#pragma unroll
            for (int i = 0; i < 2; i++) {
#pragma unroll
                for (int nf = 0; nf < 8; nf++) {
                    const uint32_t* bph = &bh[nf >> 1][(nf & 1) * 2];
                    mma16816(acc[i][nf], ah[i], bph);
                    mma16816(acc[i][nf], al[i], bph);
                }
            }
        }
    }

    float* Co = kh ? CoB : CoA;
#pragma unroll
    for (int i = 0; i < 2; i++) {
        int r0 = bm + wm + i * 16 + (lane >> 2);
#pragma unroll
        for (int nf = 0; nf < 8; nf++) {
            int c = bn + wn + nf * 8 + (lane & 3) * 2;
            float b0 = kh ? 0.f : bias[c];
            float b1 = kh ? 0.f : bias[c + 1];
            if (r0 < NROI) {
                Co[(size_t)r0 * FDIM + c]     = acc[i][nf][0] + b0;
                Co[(size_t)r0 * FDIM + c + 1] = acc[i][nf][1] + b1;
            }
            if (r0 + 8 < NROI) {
                Co[(size_t)(r0 + 8) * FDIM + c]     = acc[i][nf][2] + b0;
                Co[(size_t)(r0 + 8) * FDIM + c + 1] = acc[i][nf][3] + b1;
            }
        }
    }
}
#define GSMEM2 (3 * 3 * TILE2_B)    // 92160

// ---------------- BN stats ----------------
// phase 0: x1 + x1b; phase 1: x2 + x2b.
__global__ __launch_bounds__(256) void bn_partial_kernel(int phase)
{
    int f  = blockIdx.x * 256 + threadIdx.x;
    int rc = blockIdx.y;
    int b  = blockIdx.z;
    size_t base = ((size_t)b * 1000 + rc * 125) * FDIM + f;

    const float* pa = (phase == 0 ? g_x1 : g_x2) + base;
    const float* pb = (phase == 0 ? g_x1b : g_x2b) + base;

    float s = 0.f, q = 0.f;
#pragma unroll 5
    for (int n = 0; n < 125; n++) {
        float v = pa[(size_t)n * FDIM] + pb[(size_t)n * FDIM];
        s += v; q += v * v;
    }
    int idx = (b * 8 + rc) * FDIM + f;
    g_psum[idx] = s;
    g_psq[idx]  = q;
}

__global__ __launch_bounds__(256) void bn_final_kernel(int phase)
{
    float* mu   = (phase == 0) ? g_mu1   : g_mu2;
    float* rstd = (phase == 0) ? g_rstd1 : g_rstd2;
    int f = blockIdx.y * 256 + threadIdx.x;
    int b = blockIdx.x;

    float s = 0.f, q = 0.f;
#pragma unroll
    for (int rc = 0; rc < 8; rc++) {
        int idx = (b * 8 + rc) * FDIM + f;
        s += g_psum[idx];
        q += g_psq[idx];
    }
    float m   = s * (1.0f / 1000.0f);
    float var = q * (1.0f / 1000.0f) - m * m;
    mu[b * FDIM + f]   = m;
    rstd[b * FDIM + f] = rsqrtf(var + 1e-5f);
}

// ---------------- BN1+relu apply (x1 + x1b) -> fp16 hi/lo for GEMM2 --------
__global__ __launch_bounds__(256) void bn_apply_kernel(
    const float* __restrict__ gam, const float* __restrict__ bet)
{
    int i = blockIdx.x * 256 + threadIdx.x;
    if (i >= NROI * FDIM / 4) return;
    int e   = i * 4;
    int row = e >> 10;
    int b   = (row >= 1000);
    int kg  = e & 1023;

    float4 va  = *(const float4*)(g_x1 + e);
    float4 vb  = *(const float4*)(g_x1b + e);
    float4 g4  = *(const float4*)(gam + kg);
    float4 b4  = *(const float4*)(bet + kg);
    float4 mu4 = *(const float4*)(g_mu1 + b * FDIM + kg);
    float4 rs4 = *(const float4*)(g_rstd1 + b * FDIM + kg);
    float v0 = va.x + vb.x, v1 = va.y + vb.y, v2 = va.z + vb.z, v3 = va.w + vb.w;
    float o0 = fmaxf(g4.x * (v0 - mu4.x) * rs4.x + b4.x, 0.f);
    float o1 = fmaxf(g4.y * (v1 - mu4.y) * rs4.y + b4.y, 0.f);
    float o2 = fmaxf(g4.z * (v2 - mu4.z) * rs4.z + b4.z, 0.f);
    float o3 = fmaxf(g4.w * (v3 - mu4.w) * rs4.w + b4.w, 0.f);

    __half h0 = __float2half_rn(o0), h1 = __float2half_rn(o1);
    __half h2 = __float2half_rn(o2), h3 = __float2half_rn(o3);
    __half2* H = (__half2*)g_A2hi;
    __half2* L = (__half2*)g_A2lo;
    H[i*2]   = __half2(h0, h1);
    H[i*2+1] = __half2(h2, h3);
    L[i*2]   = __half2(__float2half_rn(o0 - __half2float(h0)),
                       __float2half_rn(o1 - __half2float(h1)));
    L[i*2+1] = __half2(__float2half_rn(o2 - __half2float(h2)),
                       __float2half_rn(o3 - __half2float(h3)));
}

// ---------------- head ----------------
#define RPB 8
__global__ __launch_bounds__(256) void head_kernel(
    const float* __restrict__ g2, const float* __restrict__ b2,
    const float* __restrict__ Wl, const float* __restrict__ bl,
    const float* __restrict__ Wb, const float* __restrict__ bb,
    float* __restrict__ out)
{
    __shared__ float sh[RPB][FDIM];
    __shared__ float lg[RPB][NCLS];

    int m0  = blockIdx.x * RPB;
    int tid = threadIdx.x;

    for (int r = 0; r < RPB; r++) {
        int m = m0 + r;
        int b = m / 1000;
        for (int k = tid; k < FDIM; k += 256) {
            float v = g_x2[(size_t)m * FDIM + k] + g_x2b[(size_t)m * FDIM + k];
            v = g2[k] * (v - g_mu2[b * FDIM + k]) * g_rstd2[b * FDIM + k] + b2[k];
            sh[r][k] = fmaxf(v, 0.f);
        }
    }
    __syncthreads();

    for (int o = tid; o < NOUT; o += 256) {
        const float* W; float bias;
        if (o < NCLS) { W = Wl + (size_t)o * FDIM;          bias = bl[o]; }
        else          { W = Wb + (size_t)(o - NCLS) * FDIM; bias = bb[o - NCLS]; }

        float acc[RPB];
#pragma unroll
        for (int r = 0; r < RPB; r++) acc[r] = 0.f;

        for (int k = 0; k < FDIM; k += 4) {
            float4 wv = *(const float4*)(W + k);
#pragma unroll
            for (int r = 0; r < RPB; r++) {
                float4 sv = *(const float4*)&sh[r][k];
                acc[r] += sv.x * wv.x + sv.y * wv.y + sv.z * wv.z + sv.w * wv.w;
            }
        }
#pragma unroll
        for (int r = 0; r < RPB; r++) {
            int m = m0 + r;
            float v = acc[r] + bias;
            if (o < NCLS) {
                lg[r][o] = v;
                out[(size_t)m * NCLS + o] = v;
            } else {
                out[324000 + (size_t)m * NBOX + (o - NCLS)] = v;
            }
        }
    }
    __syncthreads();

    int wid = tid >> 5, lane = tid & 31;
    if (wid < RPB) {
        int m = m0 + wid;
        float mx = -1e30f;
        for (int i = lane; i < NCLS; i += 32) mx = fmaxf(mx, lg[wid][i]);
#pragma unroll
        for (int off = 16; off; off >>= 1) mx = fmaxf(mx, __shfl_xor_sync(0xffffffffu, mx, off));
        float sum = 0.f;
        for (int i = lane; i < NCLS; i += 32) sum += expf(lg[wid][i] - mx);
#pragma unroll
        for (int off = 16; off; off >>= 1) sum += __shfl_xor_sync(0xffffffffu, sum, off);
        float inv = 1.0f / sum;
        for (int i = lane; i < NCLS; i += 32)
            out[162000 + (size_t)m * NCLS + i] = expf(lg[wid][i] - mx) * inv;
    }
}

// ---------------- launch ----------------
extern "C" void kernel_launch(void* const* d_in, const int* in_sizes, int n_in,
                              void* d_out, int out_size)
{
    const float* rois    = (const float*)d_in[0];
    const float* p2      = (const float*)d_in[1];
    const float* p3      = (const float*)d_in[2];
    const float* p4      = (const float*)d_in[3];
    const float* p5      = (const float*)d_in[4];
    const float* conv1_w = (const float*)d_in[5];
    const float* conv1_b = (const float*)d_in[6];
    const float* bn1_g   = (const float*)d_in[7];
    const float* bn1_b   = (const float*)d_in[8];
    const float* conv2_w = (const float*)d_in[9];
    const float* conv2_b = (const float*)d_in[10];
    const float* bn2_g   = (const float*)d_in[11];
    const float* bn2_b   = (const float*)d_in[12];
    const float* logitsW = (const float*)d_in[13];
    const float* logitsB = (const float*)d_in[14];
    const float* bboxW   = (const float*)d_in[15];
    const float* bboxB   = (const float*)d_in[16];
    float* out = (float*)d_out;

    cudaFuncSetAttribute(hmma_gemm1, cudaFuncAttributeMaxDynamicSharedMemorySize, GSMEM1);
    cudaFuncSetAttribute(hmma_gemm2, cudaFuncAttributeMaxDynamicSharedMemorySize, GSMEM2);

    __half *a1h, *b1h, *a2h, *a2l, *b2h, *b2l;
    float *x1, *x1b, *x2, *x2b;
    cudaGetSymbolAddress((void**)&a1h, g_A1hi);
    cudaGetSymbolAddress((void**)&b1h, g_B1hi);
    cudaGetSymbolAddress((void**)&a2h, g_A2hi); cudaGetSymbolAddress((void**)&a2l, g_A2lo);
    cudaGetSymbolAddress((void**)&b2h, g_B2hi); cudaGetSymbolAddress((void**)&b2l, g_B2lo);
    cudaGetSymbolAddress((void**)&x1, g_x1);    cudaGetSymbolAddress((void**)&x1b, g_x1b);
    cudaGetSymbolAddress((void**)&x2, g_x2);    cudaGetSymbolAddress((void**)&x2b, g_x2b);

    const int n4_1 = FDIM * KDIM / 4;
    const int n4_2 = FDIM * FDIM / 4;

    // launches 1-3
    cvt_hi_kernel<<<(n4_1 + 255) / 256, 256>>>(conv1_w, b1h, 0, n4_1);
    cvt_kernel<<<(n4_2 + 255) / 256, 256>>>(conv2_w, b2h, b2l, 0, n4_2);
    roi_align_kernel<<<1000, 256>>>(rois, 0, p2, p3, p4, p5);

    // launch 4: roi batch 1 — ncu capture slot
    roi_align_kernel<<<1000, 256>>>(rois, 1, p2, p3, p4, p5);

    // GEMM1 (split-K x2, single-pass, 2 CTAs/SM)
    hmma_gemm1<<<dim3(FDIM / 128, MPAD / 128, 2), 256, GSMEM1>>>(
        a1h, b1h, conv1_b, x1, x1b);

    // BN1 (sums split-K partials)
    bn_partial_kernel<<<dim3(4, 8, 2), 256>>>(0);
    bn_final_kernel<<<dim3(2, 4), 256>>>(0);
    bn_apply_kernel<<<(NROI * FDIM / 4 + 255) / 256, 256>>>(bn1_g, bn1_b);

    // GEMM2 (split-K x2, 2-pass, BK=32, 2 CTAs/SM)
    hmma_gemm2<<<dim3(FDIM / 128, MPAD / 128, 2), 256, GSMEM2>>>(
        a2h, a2l, b2h, conv2_b, x2, x2b);

    // BN2 (sums split-K partials)
    bn_partial_kernel<<<dim3(4, 8, 2), 256>>>(1);
    bn_final_kernel<<<dim3(2, 4), 256>>>(1);

    // head (sums split-K partials)
    head_kernel<<<NROI / RPB, 256>>>(bn2_g, bn2_b, logitsW, logitsB, bboxW, bboxB, out);
}

// round 11
// speedup vs baseline: 4.9515x; 1.4077x over previous
#include <cuda_runtime.h>
#include <cuda_fp16.h>
#include <cstdint>
#include <math.h>

#define NROI   2000
#define MPAD   2048
#define C_IN   256
#define KDIM   12544      // 256*7*7
#define KHALF  6272
#define FDIM   1024
#define NCLS   81
#define NBOX   324
#define NOUT   405

// ---------------- scratch ----------------
__device__ __half g_A1hi[(size_t)MPAD * KDIM];
__device__ __half g_B1hi[(size_t)FDIM * KDIM];
__device__ __half g_A2hi[(size_t)MPAD * FDIM];
__device__ __half g_A2lo[(size_t)MPAD * FDIM];
__device__ __half g_B2hi[(size_t)FDIM * FDIM];
__device__ __half g_B2lo[(size_t)FDIM * FDIM];
__device__ float g_x1[NROI * FDIM];
__device__ float g_x1b[NROI * FDIM];
__device__ float g_x2[NROI * FDIM];
__device__ float g_x2b[NROI * FDIM];
__device__ float g_mu1[2 * FDIM];
__device__ float g_rstd1[2 * FDIM];
__device__ float g_mu2[2 * FDIM];
__device__ float g_rstd2[2 * FDIM];
__device__ float g_psum[16 * FDIM];
__device__ float g_psq[16 * FDIM];

// ---------------- helpers ----------------
__device__ __forceinline__ uint32_t smem_u32(const void* p) {
    uint32_t a;
    asm("{ .reg .u64 t; cvta.to.shared.u64 t, %1; cvt.u32.u64 %0, t; }" : "=r"(a) : "l"(p));
    return a;
}
#define CPA(dst, src) \
    asm volatile("cp.async.cg.shared.global [%0], [%1], 16;" :: "r"(dst), "l"(src))
#define CPA_COMMIT() asm volatile("cp.async.commit_group;" ::: "memory")
#define CPA_WAIT1()  asm volatile("cp.async.wait_group 1;" ::: "memory")
#define CPA_WAIT0()  asm volatile("cp.async.wait_group 0;" ::: "memory")

__device__ __forceinline__ void ldm4(uint32_t* r, uint32_t addr) {
    asm volatile("ldmatrix.sync.aligned.m8n8.x4.shared.b16 {%0,%1,%2,%3}, [%4];"
        : "=r"(r[0]), "=r"(r[1]), "=r"(r[2]), "=r"(r[3]) : "r"(addr));
}
__device__ __forceinline__ void mma16816(float* d, const uint32_t* a, const uint32_t* b) {
    asm volatile("mma.sync.aligned.m16n8k16.row.col.f32.f16.f16.f32 "
        "{%0,%1,%2,%3},{%4,%5,%6,%7},{%8,%9},{%0,%1,%2,%3};"
        : "+f"(d[0]), "+f"(d[1]), "+f"(d[2]), "+f"(d[3])
        : "r"(a[0]), "r"(a[1]), "r"(a[2]), "r"(a[3]), "r"(b[0]), "r"(b[1]));
}

// ---------------- kernel 1: pyramid ROI align -> fp16 (hi only) ------------
// Block per ROI (grid 2000), 8 warps x 32 channels.
// Per channel: stage 14 bilinear rows into padded SMEM, then ALL 32 lanes
// compute one (py,px) output each (49 outputs in 2 rounds).
__global__ __launch_bounds__(256) void roi_align_kernel(
    const float* __restrict__ rois,
    const float* __restrict__ p2, const float* __restrict__ p3,
    const float* __restrict__ p4, const float* __restrict__ p5)
{
    __shared__ float sm[8][14 * 33];

    int roi  = blockIdx.x;
    int b    = roi / 1000;
    int tid  = threadIdx.x;
    int wid  = tid >> 5, lane = tid & 31;
    float* w = sm[wid];

    const float* r = rois + (size_t)roi * 4;
    float y1 = r[0], x1 = r[1], y2 = r[2], x2 = r[3];
    float hh = y2 - y1, ww = x2 - x1;

    float s   = sqrtf(fmaxf(hh * ww, 1e-12f));
    float lvl = log2f(s / 0.21875f);
    int level = 4 + (int)rintf(lvl);
    level = level < 2 ? 2 : (level > 5 ? 5 : level);

    const float* feat; int H;
    if      (level == 2) { feat = p2; H = 256; }
    else if (level == 3) { feat = p3; H = 128; }
    else if (level == 4) { feat = p4; H = 64;  }
    else                 { feat = p5; H = 32;  }
    float Hm1 = (float)(H - 1);

    float wxv[7], wyv[7];
    int xi0v[7], xi1v[7], yi0v[7], yi1v[7];
#pragma unroll
    for (int p = 0; p < 7; p++) {
        float t  = (float)p * (1.0f / 6.0f);
        float xs = (x1 + ww * t) * Hm1;
        float x0 = floorf(xs);
        wxv[p]  = xs - x0;
        int xi = (int)x0;
        xi0v[p] = min(max(xi, 0), H - 1);
        xi1v[p] = min(max(xi + 1, 0), H - 1);
        float ys = (y1 + hh * t) * Hm1;
        float y0 = floorf(ys);
        wyv[p]  = ys - y0;
        int yi = (int)y0;
        yi0v[p] = min(max(yi, 0), H - 1);
        yi1v[p] = min(max(yi + 1, 0), H - 1);
    }

    int xlo  = xi0v[0];
    int span = xi1v[6] - xlo + 1;

    // per-lane output mapping: round 0 -> idx=lane (0..31); round 1 -> idx=32+lane (<49)
    int idx1 = 32 + lane;
    bool act1 = idx1 < 49;
    int py0 = lane / 7,          px0 = lane - py0 * 7;
    int p1  = act1 ? idx1 : 48;
    int py1 = p1 / 7,            px1 = p1 - py1 * 7;

    float wy0 = wyv[py0], wx0 = wxv[px0];
    float wy1 = wyv[py1], wx1 = wxv[px1];
    // fast-path smem offsets
    int c00 = xi0v[px0] - xlo, c01 = xi1v[px0] - xlo;
    int c10 = xi0v[px1] - xlo, c11 = xi1v[px1] - xlo;
    int s0a = (2 * py0) * 33,  s0b = s0a + 33;
    int s1a = (2 * py1) * 33,  s1b = s1a + 33;
    // fallback absolute coords
    int ay00 = yi0v[py0], ay01 = yi1v[py0], ax00 = xi0v[px0], ax01 = xi1v[px0];
    int ay10 = yi0v[py1], ay11 = yi1v[py1], ax10 = xi0v[px1], ax11 = xi1v[px1];

    if (span <= 32) {
        for (int c = wid * 32; c < wid * 32 + 32; c++) {
            const float* plane = feat + (size_t)(b * C_IN + c) * H * H;
            size_t obase = (size_t)roi * KDIM + (size_t)c * 49;
#pragma unroll
            for (int py = 0; py < 7; py++) {
                float v0 = 0.f, v1 = 0.f;
                if (lane < span) {
                    v0 = plane[yi0v[py] * H + xlo + lane];
                    v1 = plane[yi1v[py] * H + xlo + lane];
                }
                w[(2 * py) * 33 + lane]     = v0;
                w[(2 * py + 1) * 33 + lane] = v1;
            }
            __syncwarp();
            {
                float v00 = w[s0a + c00], v01 = w[s0a + c01];
                float v10 = w[s0b + c00], v11 = w[s0b + c01];
                float val = v00 * (1.f - wy0) * (1.f - wx0)
                          + v01 * (1.f - wy0) * wx0
                          + v10 * wy0 * (1.f - wx0)
                          + v11 * wy0 * wx0;
                g_A1hi[obase + lane] = __float2half_rn(val);
            }
            if (act1) {
                float v00 = w[s1a + c10], v01 = w[s1a + c11];
                float v10 = w[s1b + c10], v11 = w[s1b + c11];
                float val = v00 * (1.f - wy1) * (1.f - wx1)
                          + v01 * (1.f - wy1) * wx1
                          + v10 * wy1 * (1.f - wx1)
                          + v11 * wy1 * wx1;
                g_A1hi[obase + idx1] = __float2half_rn(val);
            }
            __syncwarp();
        }
    } else {
        // rare wide-ROI path: direct gather per lane
        for (int c = wid * 32; c < wid * 32 + 32; c++) {
            const float* plane = feat + (size_t)(b * C_IN + c) * H * H;
            size_t obase = (size_t)roi * KDIM + (size_t)c * 49;
            {
                const float* r0 = plane + ay00 * H;
                const float* r1 = plane + ay01 * H;
                float v00 = r0[ax00], v01 = r0[ax01];
                float v10 = r1[ax00], v11 = r1[ax01];
                float val = v00 * (1.f - wy0) * (1.f - wx0)
                          + v01 * (1.f - wy0) * wx0
                          + v10 * wy0 * (1.f - wx0)
                          + v11 * wy0 * wx0;
                g_A1hi[obase + lane] = __float2half_rn(val);
            }
            if (act1) {
                const float* r0 = plane + ay10 * H;
                const float* r1 = plane + ay11 * H;
                float v00 = r0[ax10], v01 = r0[ax11];
                float v10 = r1[ax10], v11 = r1[ax11];
                float val = v00 * (1.f - wy1) * (1.f - wx1)
                          + v01 * (1.f - wy1) * wx1
                          + v10 * wy1 * (1.f - wx1)
                          + v11 * wy1 * wx1;
                g_A1hi[obase + idx1] = __float2half_rn(val);
            }
        }
    }
}

// ---------------- fp32 -> fp16 hi-only convert ----------------
__global__ __launch_bounds__(256) void cvt_hi_kernel(
    const float* __restrict__ in, __half* __restrict__ hi, int off4, int n4)
{
    int i = off4 + blockIdx.x * 256 + threadIdx.x;
    if (i >= n4) return;
    float4 v = ((const float4*)in)[i];
    __half2* H = (__half2*)hi;
    H[i*2]   = __half2(__float2half_rn(v.x), __float2half_rn(v.y));
    H[i*2+1] = __half2(__float2half_rn(v.z), __float2half_rn(v.w));
}

// ---------------- fp32 -> fp16 hi/lo split ----------------
__global__ __launch_bounds__(256) void cvt_kernel(
    const float* __restrict__ in, __half* __restrict__ hi,
    __half* __restrict__ lo, int off4, int n4)
{
    int i = off4 + blockIdx.x * 256 + threadIdx.x;
    if (i >= n4) return;
    float4 v = ((const float4*)in)[i];
    __half h0 = __float2half_rn(v.x), h1 = __float2half_rn(v.y);
    __half h2 = __float2half_rn(v.z), h3 = __float2half_rn(v.w);
    __half2* H = (__half2*)hi;
    __half2* L = (__half2*)lo;
    H[i*2]   = __half2(h0, h1);
    H[i*2+1] = __half2(h2, h3);
    L[i*2]   = __half2(__float2half_rn(v.x - __half2float(h0)),
                       __float2half_rn(v.y - __half2float(h1)));
    L[i*2+1] = __half2(__float2half_rn(v.z - __half2float(h2)),
                       __float2half_rn(v.w - __half2float(h3)));
}

// ---------------- GEMM1: split-K x2, single-pass fp16, 2 CTAs/SM -----------
#define ROWB    144
#define TILE_B  18432           // 128 * 144 (BK=64)

__device__ __forceinline__ void issue_stage2(
    const __half* __restrict__ Ah, const __half* __restrict__ Bh,
    int K, int k0, uint32_t sbase, int tid)
{
    const __half* gs[2] = {Ah, Bh};
#pragma unroll
    for (int t = 0; t < 2; t++) {
#pragma unroll
        for (int i = 0; i < 4; i++) {
            int u   = tid + i * 256;
            int row = u >> 3, seg = u & 7;
            const void* g = gs[t] + (size_t)row * K + k0 + seg * 8;
            uint32_t sm   = sbase + t * TILE_B + row * ROWB + seg * 16;
            CPA(sm, g);
        }
    }
}

__global__ __launch_bounds__(256, 2) void hmma_gemm1(
    const __half* __restrict__ Ahi, const __half* __restrict__ Bhi,
    const float* __restrict__ bias,
    float* __restrict__ CoA, float* __restrict__ CoB)
{
    const int K = KDIM;
    const uint32_t STAGE = 2 * TILE_B;

    extern __shared__ char smem[];
    uint32_t sb = smem_u32(smem);

    int tid  = threadIdx.x;
    int wid  = tid >> 5, lane = tid & 31;
    int wm   = (wid & 3) * 32;
    int wn   = (wid >> 2) * 64;
    int bm   = blockIdx.y * 128;
    int bn   = blockIdx.x * 128;
    int kh   = blockIdx.z;

    const __half* Ah = Ahi + (size_t)bm * K + kh * KHALF;
    const __half* Bh = Bhi + (size_t)bn * K + kh * KHALF;

    uint32_t offA[2], offB[4];
#pragma unroll
    for (int i = 0; i < 2; i++)
        offA[i] = (wm + i * 16 + (lane & 15)) * ROWB + ((lane >> 4) << 4);
#pragma unroll
    for (int j = 0; j < 4; j++)
        offB[j] = (wn + j * 16 + ((lane >> 4) << 3) + (lane & 7)) * ROWB
                + (((lane >> 3) & 1) << 4);

    float acc[2][8][4];
#pragma unroll
    for (int i = 0; i < 2; i++)
#pragma unroll
        for (int n = 0; n < 8; n++)
#pragma unroll
            for (int q = 0; q < 4; q++) acc[i][n][q] = 0.f;

    const int nch = KHALF >> 6;   // 98

    issue_stage2(Ah, Bh, K, 0, sb, tid);
    CPA_COMMIT();
    issue_stage2(Ah, Bh, K, 64, sb + STAGE, tid);
    CPA_COMMIT();

    for (int k = 0; k < nch; k++) {
        if (k == nch - 1) { CPA_WAIT0(); } else { CPA_WAIT1(); }
        __syncthreads();

        if (k + 2 < nch) {
            issue_stage2(Ah, Bh, K, (k + 2) << 6,
                         sb + ((k + 2) % 3) * STAGE, tid);
            CPA_COMMIT();
        }

        uint32_t stb = sb + (k % 3) * STAGE;
#pragma unroll
        for (int s = 0; s < 4; s++) {
            uint32_t so = s * 32;
            uint32_t ah[2][4], bh[4][4];
#pragma unroll
            for (int i = 0; i < 2; i++)
                ldm4(ah[i], stb + 0 * TILE_B + offA[i] + so);
#pragma unroll
            for (int j = 0; j < 4; j++)
                ldm4(bh[j], stb + 1 * TILE_B + offB[j] + so);
#pragma unroll
            for (int i = 0; i < 2; i++)
#pragma unroll
                for (int nf = 0; nf < 8; nf++)
                    mma16816(acc[i][nf], ah[i], &bh[nf >> 1][(nf & 1) * 2]);
        }
    }

    float* Co = kh ? CoB : CoA;
#pragma unroll
    for (int i = 0; i < 2; i++) {
        int r0 = bm + wm + i * 16 + (lane >> 2);
#pragma unroll
        for (int nf = 0; nf < 8; nf++) {
            int c = bn + wn + nf * 8 + (lane & 3) * 2;
            float b0 = kh ? 0.f : bias[c];
            float b1 = kh ? 0.f : bias[c + 1];
            if (r0 < NROI) {
                Co[(size_t)r0 * FDIM + c]     = acc[i][nf][0] + b0;
                Co[(size_t)r0 * FDIM + c + 1] = acc[i][nf][1] + b1;
            }
            if (r0 + 8 < NROI) {
                Co[(size_t)(r0 + 8) * FDIM + c]     = acc[i][nf][2] + b0;
                Co[(size_t)(r0 + 8) * FDIM + c + 1] = acc[i][nf][3] + b1;
            }
        }
    }
}
#define GSMEM1 (3 * 2 * TILE_B)    // 110592

// ---------------- GEMM2: split-K x2, 2-pass fp16 (Ah*Bh + Al*Bh), BK=32 ----
#define ROWB2   80
#define TILE2_B 10240           // 128 * 80 (BK=32)

__device__ __forceinline__ void issue_stage3(
    const __half* __restrict__ Ah, const __half* __restrict__ Bh,
    const __half* __restrict__ Al, int K, int k0, uint32_t sbase, int tid)
{
    const __half* gs[3] = {Ah, Bh, Al};
#pragma unroll
    for (int t = 0; t < 3; t++) {
#pragma unroll
        for (int i = 0; i < 2; i++) {
            int u   = tid + i * 256;
            int row = u >> 2, seg = u & 3;
            const void* g = gs[t] + (size_t)row * K + k0 + seg * 8;
            uint32_t sm   = sbase + t * TILE2_B + row * ROWB2 + seg * 16;
            CPA(sm, g);
        }
    }
}

__global__ __launch_bounds__(256, 2) void hmma_gemm2(
    const __half* __restrict__ Ahi, const __half* __restrict__ Alo,
    const __half* __restrict__ Bhi, const float* __restrict__ bias,
    float* __restrict__ CoA, float* __restrict__ CoB)
{
    const int K = FDIM;
    const uint32_t STAGE = 3 * TILE2_B;

    extern __shared__ char smem[];
    uint32_t sb = smem_u32(smem);

    int tid  = threadIdx.x;
    int wid  = tid >> 5, lane = tid & 31;
    int wm   = (wid & 3) * 32;
    int wn   = (wid >> 2) * 64;
    int bm   = blockIdx.y * 128;
    int bn   = blockIdx.x * 128;
    int kh   = blockIdx.z;

    const __half* Ah = Ahi + (size_t)bm * K + kh * (FDIM / 2);
    const __half* Al = Alo + (size_t)bm * K + kh * (FDIM / 2);
    const __half* Bh = Bhi + (size_t)bn * K + kh * (FDIM / 2);

    uint32_t offA[2], offB[4];
#pragma unroll
    for (int i = 0; i < 2; i++)
        offA[i] = (wm + i * 16 + (lane & 15)) * ROWB2 + ((lane >> 4) << 4);
#pragma unroll
    for (int j = 0; j < 4; j++)
        offB[j] = (wn + j * 16 + ((lane >> 4) << 3) + (lane & 7)) * ROWB2
                + (((lane >> 3) & 1) << 4);

    float acc[2][8][4];
#pragma unroll
    for (int i = 0; i < 2; i++)
#pragma unroll
        for (int n = 0; n < 8; n++)
#pragma unroll
            for (int q = 0; q < 4; q++) acc[i][n][q] = 0.f;

    const int nch = (FDIM / 2) >> 5;   // 16

    issue_stage3(Ah, Bh, Al, K, 0, sb, tid);
    CPA_COMMIT();
    issue_stage3(Ah, Bh, Al, K, 32, sb + STAGE, tid);
    CPA_COMMIT();

    for (int k = 0; k < nch; k++) {
        if (k == nch - 1) { CPA_WAIT0(); } else { CPA_WAIT1(); }
        __syncthreads();

        if (k + 2 < nch) {
            issue_stage3(Ah, Bh, Al, K, (k + 2) << 5,
                         sb + ((k + 2) % 3) * STAGE, tid);
            CPA_COMMIT();
        }

        uint32_t stb = sb + (k % 3) * STAGE;
#pragma unroll
        for (int s = 0; s < 2; s++) {
            uint32_t so = s * 32;
            uint32_t ah[2][4], al[2][4], bh[4][4];
#pragma unroll
            for (int i = 0; i < 2; i++) {
                ldm4(ah[i], stb + 0 * TILE2_B + offA[i] + so);
                ldm4(al[i], stb + 2 * TILE2_B + offA[i] + so);
            }
#pragma unroll
            for (int j = 0; j < 4; j++)
                ldm4(bh[j], stb + 1 * TILE2_B + offB[j] + so);
#pragma unroll
            for (int i = 0; i < 2; i++) {
#pragma unroll
                for (int nf = 0; nf < 8; nf++) {
                    const uint32_t* bph = &bh[nf >> 1][(nf & 1) * 2];
                    mma16816(acc[i][nf], ah[i], bph);
                    mma16816(acc[i][nf], al[i], bph);
                }
            }
        }
    }

    float* Co = kh ? CoB : CoA;
#pragma unroll
    for (int i = 0; i < 2; i++) {
        int r0 = bm + wm + i * 16 + (lane >> 2);
#pragma unroll
        for (int nf = 0; nf < 8; nf++) {
            int c = bn + wn + nf * 8 + (lane & 3) * 2;
            float b0 = kh ? 0.f : bias[c];
            float b1 = kh ? 0.f : bias[c + 1];
            if (r0 < NROI) {
                Co[(size_t)r0 * FDIM + c]     = acc[i][nf][0] + b0;
                Co[(size_t)r0 * FDIM + c + 1] = acc[i][nf][1] + b1;
            }
            if (r0 + 8 < NROI) {
                Co[(size_t)(r0 + 8) * FDIM + c]     = acc[i][nf][2] + b0;
                Co[(size_t)(r0 + 8) * FDIM + c + 1] = acc[i][nf][3] + b1;
            }
        }
    }
}
#define GSMEM2 (3 * 3 * TILE2_B)    // 92160

// ---------------- BN stats ----------------
__global__ __launch_bounds__(256) void bn_partial_kernel(int phase)
{
    int f  = blockIdx.x * 256 + threadIdx.x;
    int rc = blockIdx.y;
    int b  = blockIdx.z;
    size_t base = ((size_t)b * 1000 + rc * 125) * FDIM + f;

    const float* pa = (phase == 0 ? g_x1 : g_x2) + base;
    const float* pb = (phase == 0 ? g_x1b : g_x2b) + base;

    float s = 0.f, q = 0.f;
#pragma unroll 5
    for (int n = 0; n < 125; n++) {
        float v = pa[(size_t)n * FDIM] + pb[(size_t)n * FDIM];
        s += v; q += v * v;
    }
    int idx = (b * 8 + rc) * FDIM + f;
    g_psum[idx] = s;
    g_psq[idx]  = q;
}

__global__ __launch_bounds__(256) void bn_final_kernel(int phase)
{
    float* mu   = (phase == 0) ? g_mu1   : g_mu2;
    float* rstd = (phase == 0) ? g_rstd1 : g_rstd2;
    int f = blockIdx.y * 256 + threadIdx.x;
    int b = blockIdx.x;

    float s = 0.f, q = 0.f;
#pragma unroll
    for (int rc = 0; rc < 8; rc++) {
        int idx = (b * 8 + rc) * FDIM + f;
        s += g_psum[idx];
        q += g_psq[idx];
    }
    float m   = s * (1.0f / 1000.0f);
    float var = q * (1.0f / 1000.0f) - m * m;
    mu[b * FDIM + f]   = m;
    rstd[b * FDIM + f] = rsqrtf(var + 1e-5f);
}

// ---------------- BN1+relu apply (x1 + x1b) -> fp16 hi/lo for GEMM2 --------
__global__ __launch_bounds__(256) void bn_apply_kernel(
    const float* __restrict__ gam, const float* __restrict__ bet)
{
    int i = blockIdx.x * 256 + threadIdx.x;
    if (i >= NROI * FDIM / 4) return;
    int e   = i * 4;
    int row = e >> 10;
    int b   = (row >= 1000);
    int kg  = e & 1023;

    float4 va  = *(const float4*)(g_x1 + e);
    float4 vb  = *(const float4*)(g_x1b + e);
    float4 g4  = *(const float4*)(gam + kg);
    float4 b4  = *(const float4*)(bet + kg);
    float4 mu4 = *(const float4*)(g_mu1 + b * FDIM + kg);
    float4 rs4 = *(const float4*)(g_rstd1 + b * FDIM + kg);
    float v0 = va.x + vb.x, v1 = va.y + vb.y, v2 = va.z + vb.z, v3 = va.w + vb.w;
    float o0 = fmaxf(g4.x * (v0 - mu4.x) * rs4.x + b4.x, 0.f);
    float o1 = fmaxf(g4.y * (v1 - mu4.y) * rs4.y + b4.y, 0.f);
    float o2 = fmaxf(g4.z * (v2 - mu4.z) * rs4.z + b4.z, 0.f);
    float o3 = fmaxf(g4.w * (v3 - mu4.w) * rs4.w + b4.w, 0.f);

    __half h0 = __float2half_rn(o0), h1 = __float2half_rn(o1);
    __half h2 = __float2half_rn(o2), h3 = __float2half_rn(o3);
    __half2* H = (__half2*)g_A2hi;
    __half2* L = (__half2*)g_A2lo;
    H[i*2]   = __half2(h0, h1);
    H[i*2+1] = __half2(h2, h3);
    L[i*2]   = __half2(__float2half_rn(o0 - __half2float(h0)),
                       __float2half_rn(o1 - __half2float(h1)));
    L[i*2+1] = __half2(__float2half_rn(o2 - __half2float(h2)),
                       __float2half_rn(o3 - __half2float(h3)));
}

// ---------------- head ----------------
#define RPB 8
__global__ __launch_bounds__(256) void head_kernel(
    const float* __restrict__ g2, const float* __restrict__ b2,
    const float* __restrict__ Wl, const float* __restrict__ bl,
    const float* __restrict__ Wb, const float* __restrict__ bb,
    float* __restrict__ out)
{
    __shared__ float sh[RPB][FDIM];
    __shared__ float lg[RPB][NCLS];

    int m0  = blockIdx.x * RPB;
    int tid = threadIdx.x;

    for (int r = 0; r < RPB; r++) {
        int m = m0 + r;
        int b = m / 1000;
        for (int k = tid; k < FDIM; k += 256) {
            float v = g_x2[(size_t)m * FDIM + k] + g_x2b[(size_t)m * FDIM + k];
            v = g2[k] * (v - g_mu2[b * FDIM + k]) * g_rstd2[b * FDIM + k] + b2[k];
            sh[r][k] = fmaxf(v, 0.f);
        }
    }
    __syncthreads();

    for (int o = tid; o < NOUT; o += 256) {
        const float* W; float bias;
        if (o < NCLS) { W = Wl + (size_t)o * FDIM;          bias = bl[o]; }
        else          { W = Wb + (size_t)(o - NCLS) * FDIM; bias = bb[o - NCLS]; }

        float acc[RPB];
#pragma unroll
        for (int r = 0; r < RPB; r++) acc[r] = 0.f;

        for (int k = 0; k < FDIM; k += 4) {
            float4 wv = *(const float4*)(W + k);
#pragma unroll
            for (int r = 0; r < RPB; r++) {
                float4 sv = *(const float4*)&sh[r][k];
                acc[r] += sv.x * wv.x + sv.y * wv.y + sv.z * wv.z + sv.w * wv.w;
            }
        }
#pragma unroll
        for (int r = 0; r < RPB; r++) {
            int m = m0 + r;
            float v = acc[r] + bias;
            if (o < NCLS) {
                lg[r][o] = v;
                out[(size_t)m * NCLS + o] = v;
            } else {
                out[324000 + (size_t)m * NBOX + (o - NCLS)] = v;
            }
        }
    }
    __syncthreads();

    int wid = tid >> 5, lane = tid & 31;
    if (wid < RPB) {
        int m = m0 + wid;
        float mx = -1e30f;
        for (int i = lane; i < NCLS; i += 32) mx = fmaxf(mx, lg[wid][i]);
#pragma unroll
        for (int off = 16; off; off >>= 1) mx = fmaxf(mx, __shfl_xor_sync(0xffffffffu, mx, off));
        float sum = 0.f;
        for (int i = lane; i < NCLS; i += 32) sum += expf(lg[wid][i] - mx);
#pragma unroll
        for (int off = 16; off; off >>= 1) sum += __shfl_xor_sync(0xffffffffu, sum, off);
        float inv = 1.0f / sum;
        for (int i = lane; i < NCLS; i += 32)
            out[162000 + (size_t)m * NCLS + i] = expf(lg[wid][i] - mx) * inv;
    }
}

// ---------------- launch ----------------
extern "C" void kernel_launch(void* const* d_in, const int* in_sizes, int n_in,
                              void* d_out, int out_size)
{
    const float* rois    = (const float*)d_in[0];
    const float* p2      = (const float*)d_in[1];
    const float* p3      = (const float*)d_in[2];
    const float* p4      = (const float*)d_in[3];
    const float* p5      = (const float*)d_in[4];
    const float* conv1_w = (const float*)d_in[5];
    const float* conv1_b = (const float*)d_in[6];
    const float* bn1_g   = (const float*)d_in[7];
    const float* bn1_b   = (const float*)d_in[8];
    const float* conv2_w = (const float*)d_in[9];
    const float* conv2_b = (const float*)d_in[10];
    const float* bn2_g   = (const float*)d_in[11];
    const float* bn2_b   = (const float*)d_in[12];
    const float* logitsW = (const float*)d_in[13];
    const float* logitsB = (const float*)d_in[14];
    const float* bboxW   = (const float*)d_in[15];
    const float* bboxB   = (const float*)d_in[16];
    float* out = (float*)d_out;

    cudaFuncSetAttribute(hmma_gemm1, cudaFuncAttributeMaxDynamicSharedMemorySize, GSMEM1);
    cudaFuncSetAttribute(hmma_gemm2, cudaFuncAttributeMaxDynamicSharedMemorySize, GSMEM2);

    __half *a1h, *b1h, *a2h, *a2l, *b2h, *b2l;
    float *x1, *x1b, *x2, *x2b;
    cudaGetSymbolAddress((void**)&a1h, g_A1hi);
    cudaGetSymbolAddress((void**)&b1h, g_B1hi);
    cudaGetSymbolAddress((void**)&a2h, g_A2hi); cudaGetSymbolAddress((void**)&a2l, g_A2lo);
    cudaGetSymbolAddress((void**)&b2h, g_B2hi); cudaGetSymbolAddress((void**)&b2l, g_B2lo);
    cudaGetSymbolAddress((void**)&x1, g_x1);    cudaGetSymbolAddress((void**)&x1b, g_x1b);
    cudaGetSymbolAddress((void**)&x2, g_x2);    cudaGetSymbolAddress((void**)&x2b, g_x2b);

    const int n4_1 = FDIM * KDIM / 4;
    const int n4_2 = FDIM * FDIM / 4;

    // launches 1-3
    cvt_hi_kernel<<<(n4_1 / 2 + 255) / 256, 256>>>(conv1_w, b1h, 0, n4_1 / 2);
    cvt_hi_kernel<<<(n4_1 - n4_1 / 2 + 255) / 256, 256>>>(conv1_w, b1h, n4_1 / 2, n4_1);
    cvt_kernel<<<(n4_2 + 255) / 256, 256>>>(conv2_w, b2h, b2l, 0, n4_2);

    // launch 4: ROI align (merged, 2000 blocks) — ncu capture slot
    roi_align_kernel<<<NROI, 256>>>(rois, p2, p3, p4, p5);

    // GEMM1 (split-K x2, single-pass, 2 CTAs/SM)
    hmma_gemm1<<<dim3(FDIM / 128, MPAD / 128, 2), 256, GSMEM1>>>(
        a1h, b1h, conv1_b, x1, x1b);

    // BN1 (sums split-K partials)
    bn_partial_kernel<<<dim3(4, 8, 2), 256>>>(0);
    bn_final_kernel<<<dim3(2, 4), 256>>>(0);
    bn_apply_kernel<<<(NROI * FDIM / 4 + 255) / 256, 256>>>(bn1_g, bn1_b);

    // GEMM2 (split-K x2, 2-pass, BK=32, 2 CTAs/SM)
    hmma_gemm2<<<dim3(FDIM / 128, MPAD / 128, 2), 256, GSMEM2>>>(
        a2h, a2l, b2h, conv2_b, x2, x2b);

    // BN2 (sums split-K partials)
    bn_partial_kernel<<<dim3(4, 8, 2), 256>>>(1);
    bn_final_kernel<<<dim3(2, 4), 256>>>(1);

    // head (sums split-K partials)
    head_kernel<<<NROI / RPB, 256>>>(bn2_g, bn2_b, logitsW, logitsB, bboxW, bboxB, out);
}